// round 4
// baseline (speedup 1.0000x reference)
#include <cuda_runtime.h>
#include <math.h>
#include <stdint.h>

// ---------------- problem constants ----------------
#define BB    64
#define NN    128
#define FIN_  768
#define NFEAT 1024
#define NHID  512
#define NHEADS 8
#define NCLASS 512
#define ALPHA_ 0.2f
#define NEG_E_ (-9e15f)
#define NEG_S_ (-9e10f)

// input identity indices
enum { I_X=0, I_TAG, I_OFFS, I_AMASK, I_ADJ, I_WGW, I_WGB, I_HWW, I_HWB,
       I_HAW, I_HAB, I_OWW, I_OWB, I_OAW, I_OAB, I_FINW, I_FINB };

__device__ const void* g_inp[17];
#define IN_F(i) ((const float*)g_inp[i])

// ---------------- static device scratch ----------------
__device__ float g_xoff[BB * NN * FIN_];
__device__ float g_xw  [BB * NN * NFEAT];
__device__ float g_h   [NHEADS * BB * NN * NHID];    // (H,B,N,O)
__device__ float g_el  [NHEADS * BB * NN];
__device__ float g_er  [NHEADS * BB * NN];
__device__ float g_att [NHEADS * BB * NN * NN];      // (H,B,N,N)
__device__ float g_x1  [BB * NN * NHEADS * NHID];    // (B,N,H*O)
__device__ float g_h2  [BB * NN * NCLASS];
__device__ float g_el2 [BB * NN];
__device__ float g_er2 [BB * NN];
__device__ float g_att2[BB * NN * NN];
__device__ float g_x2  [BB * NN * NCLASS];
__device__ float g_logits[BB * NN];
__device__ int   g_ig  [BB * NN * 2];
__device__ int   g_fix [BB * NN * 2];

// ---------------- input classification ----------------
struct InPack { const void* p[17]; int s[17]; int n; };

__global__ void classify_kernel(InPack pk) {
    int lane = threadIdx.x;                       // 32 threads
    __shared__ int   bin_idx[4];
    __shared__ float bin_sum[4];
    __shared__ int   n_bin;
    if (lane == 0) n_bin = 0;
    __syncwarp();

    for (int i = 0; i < pk.n && i < 17; i++) {
        int sz = pk.s[i];
        const float* f = (const float*)pk.p[i];
        int target = -1;
        if      (sz == BB*NN*FIN_)            target = I_X;
        else if (sz == BB*NN*2)               target = I_OFFS;
        else if (sz == BB*NN*NN)              target = I_ADJ;
        else if (sz == FIN_*NFEAT)            target = I_WGW;
        else if (sz == NHEADS*NFEAT*NHID)     target = I_HWW;
        else if (sz == NHEADS*NHID*NCLASS)    target = I_OWW;
        else if (sz == NHEADS*NHID)           target = I_HWB;
        else if (sz == NHEADS)                target = I_HAB;
        else if (sz == NFEAT) {               // Wg_b (zeros) or oa_w
            bool nz = false;
            for (int k = lane; k < sz; k += 32) nz |= (f[k] != 0.f);
            target = __any_sync(0xffffffffu, nz) ? I_OAW : I_WGB;
        } else if (sz == NCLASS) {            // oW_b (zeros) or fin_w
            bool nz = false;
            for (int k = lane; k < sz; k += 32) nz |= (f[k] != 0.f);
            target = __any_sync(0xffffffffu, nz) ? I_FINW : I_OWB;
        } else if (sz == 1) {
            if (lane == 0) { g_inp[I_OAB] = pk.p[i]; g_inp[I_FINB] = pk.p[i]; }
        } else if (sz == BB*NN) {             // tag / amask / ha_w
            bool frac = false; float sum = 0.f;
            for (int k = lane; k < sz; k += 32) {
                float v = f[k];
                frac |= (v != 0.f && v != 1.f);
                sum += v;
            }
            frac = __any_sync(0xffffffffu, frac);
#pragma unroll
            for (int o = 16; o; o >>= 1) sum += __shfl_xor_sync(0xffffffffu, sum, o);
            if (frac) target = I_HAW;
            else if (lane == 0) { bin_idx[n_bin] = i; bin_sum[n_bin] = sum; n_bin++; }
        }
        if (target >= 0 && lane == 0) g_inp[target] = pk.p[i];
        __syncwarp();
    }
    if (lane == 0) {
        if (n_bin >= 2) {
            int a = bin_idx[0], b = bin_idx[1];
            if (bin_sum[0] >= bin_sum[1]) { g_inp[I_AMASK] = pk.p[a]; g_inp[I_TAG] = pk.p[b]; }
            else                          { g_inp[I_AMASK] = pk.p[b]; g_inp[I_TAG] = pk.p[a]; }
        } else if (n_bin == 1) {
            g_inp[I_AMASK] = pk.p[bin_idx[0]]; g_inp[I_TAG] = pk.p[bin_idx[0]];
        }
    }
}

// ---------------- reduction helpers ----------------
__device__ __forceinline__ float warpSum(float v) {
#pragma unroll
    for (int o = 16; o; o >>= 1) v += __shfl_xor_sync(0xffffffffu, v, o);
    return v;
}
__device__ __forceinline__ float warpMax(float v) {
#pragma unroll
    for (int o = 16; o; o >>= 1) v = fmaxf(v, __shfl_xor_sync(0xffffffffu, v, o));
    return v;
}
__device__ __forceinline__ float blockSum128(float v) {
    __shared__ float s[4];
    float w = warpSum(v);
    if ((threadIdx.x & 31) == 0) s[threadIdx.x >> 5] = w;
    __syncthreads();
    float r = s[0] + s[1] + s[2] + s[3];
    __syncthreads();
    return r;
}
__device__ __forceinline__ float blockMax128(float v) {
    __shared__ float s[4];
    float w = warpMax(v);
    if ((threadIdx.x & 31) == 0) s[threadIdx.x >> 5] = w;
    __syncthreads();
    float r = fmaxf(fmaxf(s[0], s[1]), fmaxf(s[2], s[3]));
    __syncthreads();
    return r;
}

// ---------------- group pool ----------------
__global__ void group_pool_kernel() {
    const float* x  = IN_F(I_X);
    const int* offs = (const int*)g_inp[I_OFFS];
    int b = blockIdx.x;
    __shared__ int seg[NN];
    __shared__ int cnt[NN + 1];
    __shared__ int G_s;

    if (threadIdx.x == 0) {
        const int* ob = offs + b * NN * 2;
        int fz = 0; bool found = false;
        for (int n = 0; n < NN; n++)
            if (ob[2 * n] == 0 && ob[2 * n + 1] == 0) { fz = n; found = true; break; }
        if (!found) fz = 0;
        int cs = 0;
        for (int g = 0; g <= NN; g++) cnt[g] = 0;
        int ends_local[NN];
        for (int g = 0; g < NN; g++) ends_local[g] = 0;
        for (int n = 0; n < NN; n++) {
            int nxt = (n < NN - 1) ? ob[2 * (n + 1)] : 0;
            int bi = (n < fz && ob[2 * n + 1] == nxt - 1) ? 1 : 0;
            cs += bi;
            int s = cs - bi;
            seg[n] = s;
            cnt[s]++;
            if (bi && s < NN) ends_local[s] = n + 1;
        }
        G_s = cs;
        int* igb = g_ig + b * NN * 2;
        int prev_end = 0;
        for (int g = 0; g < NN; g++) {
            if (g < cs) {
                igb[2 * g] = prev_end;
                igb[2 * g + 1] = ends_local[g];
                prev_end = ends_local[g];
            } else {
                igb[2 * g] = 0; igb[2 * g + 1] = 0;
            }
        }
    }
    __syncthreads();
    int G = G_s;
    float* xo = g_xoff + (long)b * NN * FIN_;
    const float* xb = x + (long)b * NN * FIN_;
    for (int f = threadIdx.x; f < FIN_; f += blockDim.x) {
        for (int g = 0; g < NN; g++) xo[g * FIN_ + f] = 0.f;
        float acc = 0.f;
        int cur = seg[0];
        for (int n = 0; n < NN; n++) {
            int s = seg[n];
            if (s != cur) {
                if (cur < G) xo[cur * FIN_ + f] = acc / (float)max(cnt[cur], 1);
                acc = 0.f; cur = s;
            }
            acc += xb[n * FIN_ + f];
        }
        if (cur < G) xo[cur * FIN_ + f] = acc / (float)max(cnt[cur], 1);
    }
}

// ---------------- generic tiled SGEMM ----------------
__global__ void sgemm_kernel(const float* Ap, int Ai, long sAz, int lda,
                             const float* Bp, int Bi, long sBz, int ldb,
                             float* C, long sCz1, long sCz2, int zdiv, int ldc,
                             const float* biasp, int biasi, int sBiasz,
                             int M, int Ncol, int K, int act) {
    const float* A  = (Ai   >= 0) ? IN_F(Ai)   : Ap;
    const float* Bm = (Bi   >= 0) ? IN_F(Bi)   : Bp;
    const float* bp = (biasi >= 0) ? IN_F(biasi) : biasp;

    __shared__ float As[16][65];
    __shared__ float Bs[16][64];
    int z = blockIdx.z;
    A  += (long)z * sAz;
    Bm += (long)z * sBz;
    C  += (long)(z % zdiv) * sCz1 + (long)(z / zdiv) * sCz2;
    if (bp) bp += (long)z * sBiasz;

    int row0 = blockIdx.y << 6;
    int col0 = blockIdx.x << 6;
    int tid = threadIdx.x;
    int tx = tid & 15, ty = tid >> 4;
    float acc[4][4] = {};

    for (int k0 = 0; k0 < K; k0 += 16) {
#pragma unroll
        for (int it = 0; it < 4; it++) {
            int i = tid + it * 256;
            int m = i >> 4, kk = i & 15;
            int gm = row0 + m;
            As[kk][m] = (gm < M) ? A[(long)gm * lda + (k0 + kk)] : 0.f;
            int kb = i >> 6, nb = i & 63;
            int gn = col0 + nb;
            Bs[kb][nb] = (gn < Ncol) ? Bm[(long)(k0 + kb) * ldb + gn] : 0.f;
        }
        __syncthreads();
#pragma unroll
        for (int kk = 0; kk < 16; kk++) {
            float a[4], bv[4];
#pragma unroll
            for (int i2 = 0; i2 < 4; i2++) a[i2] = As[kk][(ty << 2) + i2];
#pragma unroll
            for (int j2 = 0; j2 < 4; j2++) bv[j2] = Bs[kk][(tx << 2) + j2];
#pragma unroll
            for (int i2 = 0; i2 < 4; i2++)
#pragma unroll
                for (int j2 = 0; j2 < 4; j2++)
                    acc[i2][j2] = fmaf(a[i2], bv[j2], acc[i2][j2]);
        }
        __syncthreads();
    }
#pragma unroll
    for (int i2 = 0; i2 < 4; i2++) {
        int gm = row0 + (ty << 2) + i2;
        if (gm >= M) continue;
#pragma unroll
        for (int j2 = 0; j2 < 4; j2++) {
            int gn = col0 + (tx << 2) + j2;
            if (gn >= Ncol) continue;
            float v = acc[i2][j2];
            if (bp) v += bp[gn];
            if (act == 1) v = v > 0.f ? v : expm1f(v);
            C[(long)gm * ldc + gn] = v;
        }
    }
}

// ---------------- attention left/right dots ----------------
__global__ void dots_kernel(const float* __restrict__ rows, int wIdx,
                            float* __restrict__ el, float* __restrict__ er,
                            int nrows, int rows_per_head, int width) {
    const float* w = IN_F(wIdx);
    int gw = (blockIdx.x * blockDim.x + threadIdx.x) >> 5;
    if (gw >= nrows) return;
    int lane = threadIdx.x & 31;
    int hh = gw / rows_per_head;
    const float* row = rows + (long)gw * width;
    const float* wl = w + (long)hh * 2 * width;
    const float* wr = wl + width;
    float a = 0.f, c = 0.f;
    for (int k = lane; k < width; k += 32) {
        float v = row[k];
        a = fmaf(v, wl[k], a);
        c = fmaf(v, wr[k], c);
    }
    a = warpSum(a); c = warpSum(c);
    if (lane == 0) { el[gw] = a; er[gw] = c; }
}

// ---------------- masked softmax attention rows ----------------
__global__ void att_kernel(const float* __restrict__ el, const float* __restrict__ er,
                           int biasIdx, int bias_per_head,
                           float* __restrict__ att) {
    const float* adj = IN_F(I_ADJ);
    const float* bias_arr = IN_F(biasIdx);
    int i = blockIdx.x;
    int z = blockIdx.y;
    int j = threadIdx.x;
    int b = z % BB;
    int hh = z / BB;
    float bb = bias_arr[bias_per_head ? hh : 0];
    float e = el[z * NN + i] + er[z * NN + j] + bb;
    e = (e >= 0.f) ? e : ALPHA_ * e;
    float adjv = adj[((long)b * NN + i) * NN + j];
    float val = (adjv > 0.f) ? e : NEG_E_;
    float mx = blockMax128(val);
    float ex = expf(val - mx);
    float sm = blockSum128(ex);
    att[((long)z * NN + i) * NN + j] = ex / sm;
}

// ---------------- final logits ----------------
__global__ void logits_kernel() {
    const float* fin_w = IN_F(I_FINW);
    const float* fin_b = IN_F(I_FINB);
    int gw = (blockIdx.x * blockDim.x + threadIdx.x) >> 5;
    if (gw >= BB * NN) return;
    int lane = threadIdx.x & 31;
    const float* row = g_x2 + (long)gw * NCLASS;
    float a = 0.f;
    for (int k = lane; k < NCLASS; k += 32) a = fmaf(row[k], fin_w[k], a);
    a = warpSum(a);
    if (lane == 0) g_logits[gw] = a + fin_b[0];
}

// ---------------- scores + stable rank + scatter fix ----------------
__global__ void score_fix_kernel() {
    const float* tag   = IN_F(I_TAG);
    const float* amask = IN_F(I_AMASK);
    int b = blockIdx.x;
    int j = threadIdx.x;
    float m = (tag[b * NN + j] > 0.f) ? amask[b * NN + j] : 0.f;
    float lg = g_logits[b * NN + j];

    float v1 = (m > 0.f) ? lg * m : NEG_S_;
    float mx1 = blockMax128(v1);
    float e1 = expf(v1 - mx1);
    float d1 = blockSum128(e1);
    float s1 = e1 / d1;

    float summary = blockSum128(m);

    float v2 = (m > 0.f) ? ((float)(NN - j)) / summary * m : NEG_S_;
    float mx2 = blockMax128(v2);
    float e2 = expf(v2 - mx2);
    float d2 = blockSum128(e2);
    float s2 = e2 / d2;

    __shared__ float sc[NN];
    sc[j] = s1 + s2;
    __syncthreads();

    float me = sc[j];
    int rank = 0;
    for (int k = 0; k < NN; k++) {
        float o = sc[k];
        rank += (o > me) || (o == me && k < j);
    }
    g_fix[(b * NN + j) * 2 + 0] = g_ig[(b * NN + rank) * 2 + 0];
    g_fix[(b * NN + j) * 2 + 1] = g_ig[(b * NN + rank) * 2 + 1];
}

// ---------------- expand rows (FLOAT32 output) ----------------
__global__ void expand_kernel(float* __restrict__ out) {
    int b = blockIdx.x;
    int l = threadIdx.x;
    __shared__ int f0[NN], f1[NN], csum[NN];
    __shared__ int fzs, total;
    f0[l] = g_fix[(b * NN + l) * 2 + 0];
    f1[l] = g_fix[(b * NN + l) * 2 + 1];
    __syncthreads();
    if (l == 0) {
        int fz = 0; bool found = false;
        for (int n = 0; n < NN; n++)
            if (f0[n] == 0 && f1[n] == 0) { fz = n; found = true; break; }
        if (!found) fz = 0;
        int cs = 0;
        for (int n = 0; n < NN; n++) {
            int len = (n < fz) ? (f1[n] - f0[n]) : 0;
            cs += len;
            csum[n] = cs;
        }
        fzs = fz; total = cs;
    }
    __syncthreads();
    int k = 0;
    for (int n = 0; n < NN; n++) k += (csum[n] <= l);
    if (k > NN - 1) k = NN - 1;
    int lenk = (k < fzs) ? (f1[k] - f0[k]) : 0;
    int excl = csum[k] - lenk;
    int val = f0[k] + (l - excl);
    out[b * NN + l] = (float)((l < total) ? val : l);
}

// ---------------- host launcher ----------------
extern "C" void kernel_launch(void* const* d_in, const int* in_sizes, int n_in,
                              void* d_out, int /*out_size*/) {
    float* out = (float*)d_out;

    InPack pk;
    int nn = n_in < 17 ? n_in : 17;
    for (int i = 0; i < 17; i++) {
        pk.p[i] = (i < nn) ? d_in[i] : nullptr;
        pk.s[i] = (i < nn) ? in_sizes[i] : 0;
    }
    pk.n = nn;
    classify_kernel<<<1, 32>>>(pk);

    float *p_xoff, *p_xw, *p_h, *p_el, *p_er, *p_att, *p_x1, *p_h2;
    float *p_el2, *p_er2, *p_att2, *p_x2;
    cudaGetSymbolAddress((void**)&p_xoff,  g_xoff);
    cudaGetSymbolAddress((void**)&p_xw,    g_xw);
    cudaGetSymbolAddress((void**)&p_h,     g_h);
    cudaGetSymbolAddress((void**)&p_el,    g_el);
    cudaGetSymbolAddress((void**)&p_er,    g_er);
    cudaGetSymbolAddress((void**)&p_att,   g_att);
    cudaGetSymbolAddress((void**)&p_x1,    g_x1);
    cudaGetSymbolAddress((void**)&p_h2,    g_h2);
    cudaGetSymbolAddress((void**)&p_el2,   g_el2);
    cudaGetSymbolAddress((void**)&p_er2,   g_er2);
    cudaGetSymbolAddress((void**)&p_att2,  g_att2);
    cudaGetSymbolAddress((void**)&p_x2,    g_x2);

    const int M = BB * NN;

    group_pool_kernel<<<BB, 256>>>();

    sgemm_kernel<<<dim3(NFEAT / 64, M / 64, 1), 256>>>(
        p_xoff, -1, 0, FIN_, nullptr, I_WGW, 0, NFEAT,
        p_xw, 0, 0, 1, NFEAT, nullptr, I_WGB, 0, M, NFEAT, FIN_, 0);

    sgemm_kernel<<<dim3(NHID / 64, M / 64, NHEADS), 256>>>(
        p_xw, -1, 0, NFEAT, nullptr, I_HWW, (long)NFEAT * NHID, NHID,
        p_h, (long)M * NHID, 0, NHEADS, NHID, nullptr, I_HWB, NHID, M, NHID, NFEAT, 0);

    {
        int nrows = NHEADS * M;
        int nthreads = nrows * 32;
        dots_kernel<<<(nthreads + 255) / 256, 256>>>(p_h, I_HAW, p_el, p_er, nrows, M, NHID);
    }

    att_kernel<<<dim3(NN, NHEADS * BB), 128>>>(p_el, p_er, I_HAB, 1, p_att);

    sgemm_kernel<<<dim3(NHID / 64, NN / 64, NHEADS * BB), 256>>>(
        p_att, -1, (long)NN * NN, NN, p_h, -1, (long)NN * NHID, NHID,
        p_x1, (long)NN * NHEADS * NHID, NHID, BB, NHEADS * NHID,
        nullptr, -1, 0, NN, NHID, NN, 1);

    sgemm_kernel<<<dim3(NCLASS / 64, M / 64, 1), 256>>>(
        p_x1, -1, 0, NHEADS * NHID, nullptr, I_OWW, 0, NCLASS,
        p_h2, 0, 0, 1, NCLASS, nullptr, I_OWB, 0, M, NCLASS, NHEADS * NHID, 0);

    {
        int nthreads = M * 32;
        dots_kernel<<<(nthreads + 255) / 256, 256>>>(p_h2, I_OAW, p_el2, p_er2, M, M, NCLASS);
    }

    att_kernel<<<dim3(NN, BB), 128>>>(p_el2, p_er2, I_OAB, 0, p_att2);

    sgemm_kernel<<<dim3(NCLASS / 64, NN / 64, BB), 256>>>(
        p_att2, -1, (long)NN * NN, NN, p_h2, -1, (long)NN * NCLASS, NCLASS,
        p_x2, (long)NN * NCLASS, 0, BB, NCLASS, nullptr, -1, 0, NN, NCLASS, NN, 1);

    logits_kernel<<<(M * 32 + 255) / 256, 256>>>();

    score_fix_kernel<<<BB, 128>>>();

    expand_kernel<<<BB, 128>>>(out);
}

// round 5
// speedup vs baseline: 1.3335x; 1.3335x over previous
#include <cuda_runtime.h>
#include <math.h>
#include <stdint.h>

// ---------------- problem constants ----------------
#define BB    64
#define NN    128
#define FIN_  768
#define NFEAT 1024
#define NHID  512
#define NHEADS 8
#define NCLASS 512
#define ALPHA_ 0.2f
#define NEG_E_ (-9e15f)
#define NEG_S_ (-9e10f)

// input identity indices
enum { I_X=0, I_TAG, I_OFFS, I_AMASK, I_ADJ, I_WGW, I_WGB, I_HWW, I_HWB,
       I_HAW, I_HAB, I_OWW, I_OWB, I_OAW, I_OAB, I_FINW, I_FINB };

__device__ const void* g_inp[17];
#define IN_F(i) ((const float*)g_inp[i])

// ---------------- static device scratch ----------------
__device__ float g_xoff[BB * NN * FIN_];
__device__ float g_xw  [BB * NN * NFEAT];
__device__ float g_h   [NHEADS * BB * NN * NHID];    // (H,B,N,O)
__device__ float g_el  [NHEADS * BB * NN];
__device__ float g_er  [NHEADS * BB * NN];
__device__ float g_att [NHEADS * BB * NN * NN];      // (H,B,N,N)
__device__ float g_x1  [BB * NN * NHEADS * NHID];    // (B,N,H*O)
__device__ float g_h2  [BB * NN * NCLASS];
__device__ float g_el2 [BB * NN];
__device__ float g_er2 [BB * NN];
__device__ float g_att2[BB * NN * NN];
__device__ float g_x2  [BB * NN * NCLASS];
__device__ float g_logits[BB * NN];
__device__ int   g_ig  [BB * NN * 2];
__device__ int   g_fix [BB * NN * 2];

// ---------------- input classification ----------------
struct InPack { const void* p[17]; int s[17]; int n; };

__global__ void classify_kernel(InPack pk) {
    int lane = threadIdx.x;
    __shared__ int   bin_idx[4];
    __shared__ float bin_sum[4];
    __shared__ int   n_bin;
    if (lane == 0) n_bin = 0;
    __syncwarp();

    for (int i = 0; i < pk.n && i < 17; i++) {
        int sz = pk.s[i];
        const float* f = (const float*)pk.p[i];
        int target = -1;
        if      (sz == BB*NN*FIN_)            target = I_X;
        else if (sz == BB*NN*2)               target = I_OFFS;
        else if (sz == BB*NN*NN)              target = I_ADJ;
        else if (sz == FIN_*NFEAT)            target = I_WGW;
        else if (sz == NHEADS*NFEAT*NHID)     target = I_HWW;
        else if (sz == NHEADS*NHID*NCLASS)    target = I_OWW;
        else if (sz == NHEADS*NHID)           target = I_HWB;
        else if (sz == NHEADS)                target = I_HAB;
        else if (sz == NFEAT) {
            bool nz = false;
            for (int k = lane; k < sz; k += 32) nz |= (f[k] != 0.f);
            target = __any_sync(0xffffffffu, nz) ? I_OAW : I_WGB;
        } else if (sz == NCLASS) {
            bool nz = false;
            for (int k = lane; k < sz; k += 32) nz |= (f[k] != 0.f);
            target = __any_sync(0xffffffffu, nz) ? I_FINW : I_OWB;
        } else if (sz == 1) {
            if (lane == 0) { g_inp[I_OAB] = pk.p[i]; g_inp[I_FINB] = pk.p[i]; }
        } else if (sz == BB*NN) {
            bool frac = false; float sum = 0.f;
            for (int k = lane; k < sz; k += 32) {
                float v = f[k];
                frac |= (v != 0.f && v != 1.f);
                sum += v;
            }
            frac = __any_sync(0xffffffffu, frac);
#pragma unroll
            for (int o = 16; o; o >>= 1) sum += __shfl_xor_sync(0xffffffffu, sum, o);
            if (frac) target = I_HAW;
            else if (lane == 0) { bin_idx[n_bin] = i; bin_sum[n_bin] = sum; n_bin++; }
        }
        if (target >= 0 && lane == 0) g_inp[target] = pk.p[i];
        __syncwarp();
    }
    if (lane == 0) {
        if (n_bin >= 2) {
            int a = bin_idx[0], b = bin_idx[1];
            if (bin_sum[0] >= bin_sum[1]) { g_inp[I_AMASK] = pk.p[a]; g_inp[I_TAG] = pk.p[b]; }
            else                          { g_inp[I_AMASK] = pk.p[b]; g_inp[I_TAG] = pk.p[a]; }
        } else if (n_bin == 1) {
            g_inp[I_AMASK] = pk.p[bin_idx[0]]; g_inp[I_TAG] = pk.p[bin_idx[0]];
        }
    }
}

// ---------------- reduction helpers ----------------
__device__ __forceinline__ float warpSum(float v) {
#pragma unroll
    for (int o = 16; o; o >>= 1) v += __shfl_xor_sync(0xffffffffu, v, o);
    return v;
}
__device__ __forceinline__ float warpMax(float v) {
#pragma unroll
    for (int o = 16; o; o >>= 1) v = fmaxf(v, __shfl_xor_sync(0xffffffffu, v, o));
    return v;
}
__device__ __forceinline__ float blockSum128(float v) {
    __shared__ float s[4];
    float w = warpSum(v);
    if ((threadIdx.x & 31) == 0) s[threadIdx.x >> 5] = w;
    __syncthreads();
    float r = s[0] + s[1] + s[2] + s[3];
    __syncthreads();
    return r;
}
__device__ __forceinline__ float blockMax128(float v) {
    __shared__ float s[4];
    float w = warpMax(v);
    if ((threadIdx.x & 31) == 0) s[threadIdx.x >> 5] = w;
    __syncthreads();
    float r = fmaxf(fmaxf(s[0], s[1]), fmaxf(s[2], s[3]));
    __syncthreads();
    return r;
}

// ---------------- group pool ----------------
__global__ void group_pool_kernel() {
    const float* x  = IN_F(I_X);
    const int* offs = (const int*)g_inp[I_OFFS];
    int b = blockIdx.x;
    __shared__ int seg[NN];
    __shared__ int cnt[NN + 1];
    __shared__ int G_s;

    if (threadIdx.x == 0) {
        const int* ob = offs + b * NN * 2;
        int fz = 0; bool found = false;
        for (int n = 0; n < NN; n++)
            if (ob[2 * n] == 0 && ob[2 * n + 1] == 0) { fz = n; found = true; break; }
        if (!found) fz = 0;
        int cs = 0;
        for (int g = 0; g <= NN; g++) cnt[g] = 0;
        int ends_local[NN];
        for (int g = 0; g < NN; g++) ends_local[g] = 0;
        for (int n = 0; n < NN; n++) {
            int nxt = (n < NN - 1) ? ob[2 * (n + 1)] : 0;
            int bi = (n < fz && ob[2 * n + 1] == nxt - 1) ? 1 : 0;
            cs += bi;
            int s = cs - bi;
            seg[n] = s;
            cnt[s]++;
            if (bi && s < NN) ends_local[s] = n + 1;
        }
        G_s = cs;
        int* igb = g_ig + b * NN * 2;
        int prev_end = 0;
        for (int g = 0; g < NN; g++) {
            if (g < cs) {
                igb[2 * g] = prev_end;
                igb[2 * g + 1] = ends_local[g];
                prev_end = ends_local[g];
            } else {
                igb[2 * g] = 0; igb[2 * g + 1] = 0;
            }
        }
    }
    __syncthreads();
    int G = G_s;
    float* xo = g_xoff + (long)b * NN * FIN_;
    const float* xb = x + (long)b * NN * FIN_;
    for (int f = threadIdx.x; f < FIN_; f += blockDim.x) {
        for (int g = 0; g < NN; g++) xo[g * FIN_ + f] = 0.f;
        float acc = 0.f;
        int cur = seg[0];
        for (int n = 0; n < NN; n++) {
            int s = seg[n];
            if (s != cur) {
                if (cur < G) xo[cur * FIN_ + f] = acc / (float)max(cnt[cur], 1);
                acc = 0.f; cur = s;
            }
            acc += xb[n * FIN_ + f];
        }
        if (cur < G) xo[cur * FIN_ + f] = acc / (float)max(cnt[cur], 1);
    }
}

// ---------------- 128x128x8 SGEMM, 8x8 microtile, double-buffered ----------------
// Requires: M%128==0, Ncol%128==0, K%8==0, lda/ldb/ldc %4==0. (All call sites satisfy.)
__global__ void __launch_bounds__(256, 2)
sgemm128_kernel(const float* Ap, int Ai, long sAz, int lda,
                const float* Bp, int Bi, long sBz, int ldb,
                float* C, long sCz1, long sCz2, int zdiv, int ldc,
                const float* biasp, int biasi, int sBiasz,
                int K, int act) {
    const float* A  = (Ai    >= 0) ? IN_F(Ai)    : Ap;
    const float* Bm = (Bi    >= 0) ? IN_F(Bi)    : Bp;
    const float* bp = (biasi >= 0) ? IN_F(biasi) : biasp;

    int z = blockIdx.z;
    A  += (long)z * sAz;
    Bm += (long)z * sBz;
    C  += (long)(z % zdiv) * sCz1 + (long)(z / zdiv) * sCz2;
    if (bp) bp += (long)z * sBiasz;

    __shared__ float As[2][8][128];
    __shared__ float Bs[2][8][128];

    int tid = threadIdx.x;
    int tx = tid & 15, ty = tid >> 4;
    int row0 = blockIdx.y << 7, col0 = blockIdx.x << 7;

    // A tile loader: 128 rows x 8 k; thread -> row am, k-offset ak (conflict-free STS)
    int am = tid & 127, ak = (tid >> 7) << 2;
    // B tile loader: 8 k-rows x 128 cols; coalesced 128B per k-row
    int bk = tid >> 5, bn = (tid & 31) << 2;

    const float* Aptr = A + (long)(row0 + am) * lda + ak;
    const float* Bptr = Bm + (long)bk * ldb + col0 + bn;

    float4 av = *(const float4*)Aptr;
    float4 bv = *(const float4*)Bptr;

    float acc[8][8] = {};
    int nt = K >> 3;
    int stage = 0;
    As[0][ak + 0][am] = av.x; As[0][ak + 1][am] = av.y;
    As[0][ak + 2][am] = av.z; As[0][ak + 3][am] = av.w;
    *(float4*)&Bs[0][bk][bn] = bv;
    __syncthreads();

    for (int t = 0; t < nt; t++) {
        if (t + 1 < nt) {
            av = *(const float4*)(Aptr + (t + 1) * 8);
            bv = *(const float4*)(Bptr + (long)(t + 1) * 8 * ldb);
        }
#pragma unroll
        for (int k = 0; k < 8; k++) {
            float4 a0 = *(const float4*)&As[stage][k][ty << 2];
            float4 a1 = *(const float4*)&As[stage][k][(ty << 2) + 64];
            float4 b0 = *(const float4*)&Bs[stage][k][tx << 2];
            float4 b1 = *(const float4*)&Bs[stage][k][(tx << 2) + 64];
            float a[8] = {a0.x, a0.y, a0.z, a0.w, a1.x, a1.y, a1.z, a1.w};
            float b[8] = {b0.x, b0.y, b0.z, b0.w, b1.x, b1.y, b1.z, b1.w};
#pragma unroll
            for (int i = 0; i < 8; i++)
#pragma unroll
                for (int j = 0; j < 8; j++)
                    acc[i][j] = fmaf(a[i], b[j], acc[i][j]);
        }
        if (t + 1 < nt) {
            int ns = stage ^ 1;
            As[ns][ak + 0][am] = av.x; As[ns][ak + 1][am] = av.y;
            As[ns][ak + 2][am] = av.z; As[ns][ak + 3][am] = av.w;
            *(float4*)&Bs[ns][bk][bn] = bv;
            __syncthreads();
            stage = ns;
        }
    }

    // epilogue: 8 rows x 2 float4 each
#pragma unroll
    for (int i = 0; i < 8; i++) {
        int gm = row0 + (ty << 2) + (i & 3) + ((i >> 2) << 6);
        float* Crow = C + (long)gm * ldc + col0;
#pragma unroll
        for (int jh = 0; jh < 2; jh++) {
            int gn = (tx << 2) + (jh << 6);
            float4 v;
            v.x = acc[i][jh * 4 + 0]; v.y = acc[i][jh * 4 + 1];
            v.z = acc[i][jh * 4 + 2]; v.w = acc[i][jh * 4 + 3];
            if (bp) {
                v.x += bp[col0 + gn + 0]; v.y += bp[col0 + gn + 1];
                v.z += bp[col0 + gn + 2]; v.w += bp[col0 + gn + 3];
            }
            if (act == 1) {
                v.x = v.x > 0.f ? v.x : expm1f(v.x);
                v.y = v.y > 0.f ? v.y : expm1f(v.y);
                v.z = v.z > 0.f ? v.z : expm1f(v.z);
                v.w = v.w > 0.f ? v.w : expm1f(v.w);
            }
            *(float4*)(Crow + gn) = v;
        }
    }
}

// ---------------- attention left/right dots ----------------
__global__ void dots_kernel(const float* __restrict__ rows, int wIdx,
                            float* __restrict__ el, float* __restrict__ er,
                            int nrows, int rows_per_head, int width) {
    const float* w = IN_F(wIdx);
    int gw = (blockIdx.x * blockDim.x + threadIdx.x) >> 5;
    if (gw >= nrows) return;
    int lane = threadIdx.x & 31;
    int hh = gw / rows_per_head;
    const float* row = rows + (long)gw * width;
    const float* wl = w + (long)hh * 2 * width;
    const float* wr = wl + width;
    float a = 0.f, c = 0.f;
    for (int k = lane; k < width; k += 32) {
        float v = row[k];
        a = fmaf(v, wl[k], a);
        c = fmaf(v, wr[k], c);
    }
    a = warpSum(a); c = warpSum(c);
    if (lane == 0) { el[gw] = a; er[gw] = c; }
}

// ---------------- masked softmax attention rows ----------------
__global__ void att_kernel(const float* __restrict__ el, const float* __restrict__ er,
                           int biasIdx, int bias_per_head,
                           float* __restrict__ att) {
    const float* adj = IN_F(I_ADJ);
    const float* bias_arr = IN_F(biasIdx);
    int i = blockIdx.x;
    int z = blockIdx.y;
    int j = threadIdx.x;
    int b = z % BB;
    int hh = z / BB;
    float bb = bias_arr[bias_per_head ? hh : 0];
    float e = el[z * NN + i] + er[z * NN + j] + bb;
    e = (e >= 0.f) ? e : ALPHA_ * e;
    float adjv = adj[((long)b * NN + i) * NN + j];
    float val = (adjv > 0.f) ? e : NEG_E_;
    float mx = blockMax128(val);
    float ex = expf(val - mx);
    float sm = blockSum128(ex);
    att[((long)z * NN + i) * NN + j] = ex / sm;
}

// ---------------- final logits ----------------
__global__ void logits_kernel() {
    const float* fin_w = IN_F(I_FINW);
    const float* fin_b = IN_F(I_FINB);
    int gw = (blockIdx.x * blockDim.x + threadIdx.x) >> 5;
    if (gw >= BB * NN) return;
    int lane = threadIdx.x & 31;
    const float* row = g_x2 + (long)gw * NCLASS;
    float a = 0.f;
    for (int k = lane; k < NCLASS; k += 32) a = fmaf(row[k], fin_w[k], a);
    a = warpSum(a);
    if (lane == 0) g_logits[gw] = a + fin_b[0];
}

// ---------------- scores + stable rank + scatter fix ----------------
__global__ void score_fix_kernel() {
    const float* tag   = IN_F(I_TAG);
    const float* amask = IN_F(I_AMASK);
    int b = blockIdx.x;
    int j = threadIdx.x;
    float m = (tag[b * NN + j] > 0.f) ? amask[b * NN + j] : 0.f;
    float lg = g_logits[b * NN + j];

    float v1 = (m > 0.f) ? lg * m : NEG_S_;
    float mx1 = blockMax128(v1);
    float e1 = expf(v1 - mx1);
    float d1 = blockSum128(e1);
    float s1 = e1 / d1;

    float summary = blockSum128(m);

    float v2 = (m > 0.f) ? ((float)(NN - j)) / summary * m : NEG_S_;
    float mx2 = blockMax128(v2);
    float e2 = expf(v2 - mx2);
    float d2 = blockSum128(e2);
    float s2 = e2 / d2;

    __shared__ float sc[NN];
    sc[j] = s1 + s2;
    __syncthreads();

    float me = sc[j];
    int rank = 0;
    for (int k = 0; k < NN; k++) {
        float o = sc[k];
        rank += (o > me) || (o == me && k < j);
    }
    g_fix[(b * NN + j) * 2 + 0] = g_ig[(b * NN + rank) * 2 + 0];
    g_fix[(b * NN + j) * 2 + 1] = g_ig[(b * NN + rank) * 2 + 1];
}

// ---------------- expand rows (float32 output) ----------------
__global__ void expand_kernel(float* __restrict__ out) {
    int b = blockIdx.x;
    int l = threadIdx.x;
    __shared__ int f0[NN], f1[NN], csum[NN];
    __shared__ int fzs, total;
    f0[l] = g_fix[(b * NN + l) * 2 + 0];
    f1[l] = g_fix[(b * NN + l) * 2 + 1];
    __syncthreads();
    if (l == 0) {
        int fz = 0; bool found = false;
        for (int n = 0; n < NN; n++)
            if (f0[n] == 0 && f1[n] == 0) { fz = n; found = true; break; }
        if (!found) fz = 0;
        int cs = 0;
        for (int n = 0; n < NN; n++) {
            int len = (n < fz) ? (f1[n] - f0[n]) : 0;
            cs += len;
            csum[n] = cs;
        }
        fzs = fz; total = cs;
    }
    __syncthreads();
    int k = 0;
    for (int n = 0; n < NN; n++) k += (csum[n] <= l);
    if (k > NN - 1) k = NN - 1;
    int lenk = (k < fzs) ? (f1[k] - f0[k]) : 0;
    int excl = csum[k] - lenk;
    int val = f0[k] + (l - excl);
    out[b * NN + l] = (float)((l < total) ? val : l);
}

// ---------------- host launcher ----------------
extern "C" void kernel_launch(void* const* d_in, const int* in_sizes, int n_in,
                              void* d_out, int /*out_size*/) {
    float* out = (float*)d_out;

    InPack pk;
    int nn = n_in < 17 ? n_in : 17;
    for (int i = 0; i < 17; i++) {
        pk.p[i] = (i < nn) ? d_in[i] : nullptr;
        pk.s[i] = (i < nn) ? in_sizes[i] : 0;
    }
    pk.n = nn;
    classify_kernel<<<1, 32>>>(pk);

    float *p_xoff, *p_xw, *p_h, *p_el, *p_er, *p_att, *p_x1, *p_h2;
    float *p_el2, *p_er2, *p_att2, *p_x2;
    cudaGetSymbolAddress((void**)&p_xoff,  g_xoff);
    cudaGetSymbolAddress((void**)&p_xw,    g_xw);
    cudaGetSymbolAddress((void**)&p_h,     g_h);
    cudaGetSymbolAddress((void**)&p_el,    g_el);
    cudaGetSymbolAddress((void**)&p_er,    g_er);
    cudaGetSymbolAddress((void**)&p_att,   g_att);
    cudaGetSymbolAddress((void**)&p_x1,    g_x1);
    cudaGetSymbolAddress((void**)&p_h2,    g_h2);
    cudaGetSymbolAddress((void**)&p_el2,   g_el2);
    cudaGetSymbolAddress((void**)&p_er2,   g_er2);
    cudaGetSymbolAddress((void**)&p_att2,  g_att2);
    cudaGetSymbolAddress((void**)&p_x2,    g_x2);

    const int M = BB * NN;

    // 1. group pooling + index_group
    group_pool_kernel<<<BB, 256>>>();

    // 2. xw = x_off @ Wg_w + Wg_b      (8192 x 1024 x 768)
    sgemm128_kernel<<<dim3(NFEAT / 128, M / 128, 1), 256>>>(
        p_xoff, -1, 0, FIN_, nullptr, I_WGW, 0, NFEAT,
        p_xw, 0, 0, 1, NFEAT, nullptr, I_WGB, 0, FIN_, 0);

    // 3. h[hh] = xw @ hW_w[hh] + hW_b[hh]   (8 x 8192 x 512 x 1024)
    sgemm128_kernel<<<dim3(NHID / 128, M / 128, NHEADS), 256>>>(
        p_xw, -1, 0, NFEAT, nullptr, I_HWW, (long)NFEAT * NHID, NHID,
        p_h, (long)M * NHID, 0, NHEADS, NHID, nullptr, I_HWB, NHID, NFEAT, 0);

    // 4. el / er dots
    {
        int nrows = NHEADS * M;
        int nthreads = nrows * 32;
        dots_kernel<<<(nthreads + 255) / 256, 256>>>(p_h, I_HAW, p_el, p_er, nrows, M, NHID);
    }

    // 5. att = softmax(lrelu(el_i + er_j + b), adj-masked)
    att_kernel<<<dim3(NN, NHEADS * BB), 128>>>(p_el, p_er, I_HAB, 1, p_att);

    // 6. x1 = elu(att @ h) scattered into (B,N,H*NHID)   (512 x 128 x 512 x 128)
    sgemm128_kernel<<<dim3(NHID / 128, NN / 128, NHEADS * BB), 256>>>(
        p_att, -1, (long)NN * NN, NN, p_h, -1, (long)NN * NHID, NHID,
        p_x1, (long)NN * NHEADS * NHID, NHID, BB, NHEADS * NHID,
        nullptr, -1, 0, NN, 1);

    // 7. h2 = x1 @ oW_w + oW_b        (8192 x 512 x 4096)
    sgemm128_kernel<<<dim3(NCLASS / 128, M / 128, 1), 256>>>(
        p_x1, -1, 0, NHEADS * NHID, nullptr, I_OWW, 0, NCLASS,
        p_h2, 0, 0, 1, NCLASS, nullptr, I_OWB, 0, NHEADS * NHID, 0);

    // 8. el2 / er2 dots
    {
        int nthreads = M * 32;
        dots_kernel<<<(nthreads + 255) / 256, 256>>>(p_h2, I_OAW, p_el2, p_er2, M, M, NCLASS);
    }

    // 9. att2
    att_kernel<<<dim3(NN, BB), 128>>>(p_el2, p_er2, I_OAB, 0, p_att2);

    // 10. x2 = elu(att2 @ h2)   (64 x 128 x 512 x 128)
    sgemm128_kernel<<<dim3(NCLASS / 128, NN / 128, BB), 256>>>(
        p_att2, -1, (long)NN * NN, NN, p_h2, -1, (long)NN * NCLASS, NCLASS,
        p_x2, (long)NN * NCLASS, 0, BB, NCLASS, nullptr, -1, 0, NN, 1);

    // 11. logits
    logits_kernel<<<(M * 32 + 255) / 256, 256>>>();

    // 12. scores + stable rank + scatter
    score_fix_kernel<<<BB, 128>>>();

    // 13. expand -> output
    expand_kernel<<<BB, 128>>>(out);
}

// round 6
// speedup vs baseline: 2.2266x; 1.6698x over previous
#include <cuda_runtime.h>
#include <math.h>
#include <stdint.h>

// ---------------- problem constants ----------------
#define BB    64
#define NN    128
#define FIN_  768
#define NFEAT 1024
#define NHID  512
#define NHEADS 8
#define NCLASS 512
#define ALPHA_ 0.2f
#define NEG_E_ (-9e15f)
#define NEG_S_ (-9e10f)

// input identity indices
enum { I_X=0, I_TAG, I_OFFS, I_AMASK, I_ADJ, I_WGW, I_WGB, I_HWW, I_HWB,
       I_HAW, I_HAB, I_OWW, I_OWB, I_OAW, I_OAB, I_FINW, I_FINB };

__device__ const void* g_inp[17];
#define IN_F(i) ((const float*)g_inp[i])

// ---------------- static device scratch ----------------
__device__ float g_xoff[BB * NN * FIN_];
__device__ float g_xw  [BB * NN * NFEAT];
__device__ float g_h   [NHEADS * BB * NN * NHID];    // (H,B,N,O)
__device__ float g_el  [NHEADS * BB * NN];
__device__ float g_er  [NHEADS * BB * NN];
__device__ float g_att [NHEADS * BB * NN * NN];      // (H,B,N,N)
__device__ float g_x1  [BB * NN * NHEADS * NHID];    // (B,N,H*O)
__device__ float g_h2  [BB * NN * NCLASS];
__device__ float g_el2 [BB * NN];
__device__ float g_er2 [BB * NN];
__device__ float g_att2[BB * NN * NN];
__device__ float g_x2  [BB * NN * NCLASS];
__device__ float g_logits[BB * NN];
__device__ int   g_ig  [BB * NN * 2];
__device__ int   g_fix [BB * NN * 2];

// ---------------- input classification ----------------
struct InPack { const void* p[17]; int s[17]; int n; };

__global__ void classify_kernel(InPack pk) {
    int lane = threadIdx.x;
    __shared__ int   bin_idx[4];
    __shared__ float bin_sum[4];
    __shared__ int   n_bin;
    if (lane == 0) n_bin = 0;
    __syncwarp();

    for (int i = 0; i < pk.n && i < 17; i++) {
        int sz = pk.s[i];
        const float* f = (const float*)pk.p[i];
        int target = -1;
        if      (sz == BB*NN*FIN_)            target = I_X;
        else if (sz == BB*NN*2)               target = I_OFFS;
        else if (sz == BB*NN*NN)              target = I_ADJ;
        else if (sz == FIN_*NFEAT)            target = I_WGW;
        else if (sz == NHEADS*NFEAT*NHID)     target = I_HWW;
        else if (sz == NHEADS*NHID*NCLASS)    target = I_OWW;
        else if (sz == NHEADS*NHID)           target = I_HWB;
        else if (sz == NHEADS)                target = I_HAB;
        else if (sz == NFEAT) {
            bool nz = false;
            for (int k = lane; k < sz; k += 32) nz |= (f[k] != 0.f);
            target = __any_sync(0xffffffffu, nz) ? I_OAW : I_WGB;
        } else if (sz == NCLASS) {
            bool nz = false;
            for (int k = lane; k < sz; k += 32) nz |= (f[k] != 0.f);
            target = __any_sync(0xffffffffu, nz) ? I_FINW : I_OWB;
        } else if (sz == 1) {
            if (lane == 0) { g_inp[I_OAB] = pk.p[i]; g_inp[I_FINB] = pk.p[i]; }
        } else if (sz == BB*NN) {
            bool frac = false; float sum = 0.f;
            for (int k = lane; k < sz; k += 32) {
                float v = f[k];
                frac |= (v != 0.f && v != 1.f);
                sum += v;
            }
            frac = __any_sync(0xffffffffu, frac);
#pragma unroll
            for (int o = 16; o; o >>= 1) sum += __shfl_xor_sync(0xffffffffu, sum, o);
            if (frac) target = I_HAW;
            else if (lane == 0) { bin_idx[n_bin] = i; bin_sum[n_bin] = sum; n_bin++; }
        }
        if (target >= 0 && lane == 0) g_inp[target] = pk.p[i];
        __syncwarp();
    }
    if (lane == 0) {
        if (n_bin >= 2) {
            int a = bin_idx[0], b = bin_idx[1];
            if (bin_sum[0] >= bin_sum[1]) { g_inp[I_AMASK] = pk.p[a]; g_inp[I_TAG] = pk.p[b]; }
            else                          { g_inp[I_AMASK] = pk.p[b]; g_inp[I_TAG] = pk.p[a]; }
        } else if (n_bin == 1) {
            g_inp[I_AMASK] = pk.p[bin_idx[0]]; g_inp[I_TAG] = pk.p[bin_idx[0]];
        }
    }
}

// ---------------- reduction helpers ----------------
__device__ __forceinline__ float warpSum(float v) {
#pragma unroll
    for (int o = 16; o; o >>= 1) v += __shfl_xor_sync(0xffffffffu, v, o);
    return v;
}
__device__ __forceinline__ float warpMax(float v) {
#pragma unroll
    for (int o = 16; o; o >>= 1) v = fmaxf(v, __shfl_xor_sync(0xffffffffu, v, o));
    return v;
}
__device__ __forceinline__ float blockSum128(float v) {
    __shared__ float s[4];
    float w = warpSum(v);
    if ((threadIdx.x & 31) == 0) s[threadIdx.x >> 5] = w;
    __syncthreads();
    float r = s[0] + s[1] + s[2] + s[3];
    __syncthreads();
    return r;
}
__device__ __forceinline__ float blockMax128(float v) {
    __shared__ float s[4];
    float w = warpMax(v);
    if ((threadIdx.x & 31) == 0) s[threadIdx.x >> 5] = w;
    __syncthreads();
    float r = fmaxf(fmaxf(s[0], s[1]), fmaxf(s[2], s[3]));
    __syncthreads();
    return r;
}

// ---------------- group pool ----------------
__global__ void group_pool_kernel() {
    const float* x  = IN_F(I_X);
    const int* offs = (const int*)g_inp[I_OFFS];
    int b = blockIdx.x;
    __shared__ int seg[NN];
    __shared__ int cnt[NN + 1];
    __shared__ int G_s;

    if (threadIdx.x == 0) {
        const int* ob = offs + b * NN * 2;
        int fz = 0; bool found = false;
        for (int n = 0; n < NN; n++)
            if (ob[2 * n] == 0 && ob[2 * n + 1] == 0) { fz = n; found = true; break; }
        if (!found) fz = 0;
        int cs = 0;
        for (int g = 0; g <= NN; g++) cnt[g] = 0;
        int ends_local[NN];
        for (int g = 0; g < NN; g++) ends_local[g] = 0;
        for (int n = 0; n < NN; n++) {
            int nxt = (n < NN - 1) ? ob[2 * (n + 1)] : 0;
            int bi = (n < fz && ob[2 * n + 1] == nxt - 1) ? 1 : 0;
            cs += bi;
            int s = cs - bi;
            seg[n] = s;
            cnt[s]++;
            if (bi && s < NN) ends_local[s] = n + 1;
        }
        G_s = cs;
        int* igb = g_ig + b * NN * 2;
        int prev_end = 0;
        for (int g = 0; g < NN; g++) {
            if (g < cs) {
                igb[2 * g] = prev_end;
                igb[2 * g + 1] = ends_local[g];
                prev_end = ends_local[g];
            } else {
                igb[2 * g] = 0; igb[2 * g + 1] = 0;
            }
        }
    }
    __syncthreads();
    int G = G_s;
    float* xo = g_xoff + (long)b * NN * FIN_;
    const float* xb = x + (long)b * NN * FIN_;
    for (int f = threadIdx.x; f < FIN_; f += blockDim.x) {
        for (int g = 0; g < NN; g++) xo[g * FIN_ + f] = 0.f;
        float acc = 0.f;
        int cur = seg[0];
        for (int n = 0; n < NN; n++) {
            int s = seg[n];
            if (s != cur) {
                if (cur < G) xo[cur * FIN_ + f] = acc / (float)max(cnt[cur], 1);
                acc = 0.f; cur = s;
            }
            acc += xb[n * FIN_ + f];
        }
        if (cur < G) xo[cur * FIN_ + f] = acc / (float)max(cnt[cur], 1);
    }
}

// ---------------- tf32 helpers ----------------
__device__ __forceinline__ uint32_t f2tf32(float x) {
    uint32_t r;
    asm("cvt.rna.tf32.f32 %0, %1;" : "=r"(r) : "f"(x));
    return r;
}
__device__ __forceinline__ void mma_tf32(float* d, const uint32_t* a, const uint32_t* b) {
    asm volatile(
        "mma.sync.aligned.m16n8k8.row.col.f32.tf32.tf32.f32 "
        "{%0,%1,%2,%3}, {%4,%5,%6,%7}, {%8,%9}, {%0,%1,%2,%3};\n"
        : "+f"(d[0]), "+f"(d[1]), "+f"(d[2]), "+f"(d[3])
        : "r"(a[0]), "r"(a[1]), "r"(a[2]), "r"(a[3]), "r"(b[0]), "r"(b[1]));
}

// ---------------- tf32 tensor-core GEMM: 128x128 tile, BK=16 ----------------
// Requires: M%128==0, Ncol%128==0, K%16==0, lda/ldb/ldc %4==0.
#define ASTRIDE 20
#define BSTRIDE 132
__global__ void __launch_bounds__(256, 2)
tgemm_kernel(const float* Ap, int Ai, long sAz, int lda,
             const float* Bp, int Bi, long sBz, int ldb,
             float* C, long sCz1, long sCz2, int zdiv, int ldc,
             const float* biasp, int biasi, int sBiasz,
             int K, int act) {
    const float* A  = (Ai    >= 0) ? IN_F(Ai)    : Ap;
    const float* Bm = (Bi    >= 0) ? IN_F(Bi)    : Bp;
    const float* bp = (biasi >= 0) ? IN_F(biasi) : biasp;

    int z = blockIdx.z;
    A  += (long)z * sAz;
    Bm += (long)z * sBz;
    C  += (long)(z % zdiv) * sCz1 + (long)(z / zdiv) * sCz2;
    if (bp) bp += (long)z * sBiasz;

    __shared__ uint32_t As[2][128 * ASTRIDE];   // [m][k], tf32 bits
    __shared__ uint32_t Bs[2][16 * BSTRIDE];    // [k][n], tf32 bits

    int tid  = threadIdx.x;
    int wid  = tid >> 5;
    int lane = tid & 31;
    int gr = lane >> 2, gc = lane & 3;          // groupID / threadID_in_group
    int wm = (wid & 1) << 6;                     // warp m offset (0/64)
    int wn = (wid >> 1) << 5;                    // warp n offset (0/32/64/96)
    int row0 = blockIdx.y << 7, col0 = blockIdx.x << 7;

    // loaders: A tile 128x16, B tile 16x128; 8 floats (2 float4) per thread each
    int ar = tid & 127, ac = (tid >> 7) << 3;    // A: row ar, cols ac..ac+7
    int bkr = tid >> 4, bnc = (tid & 15) << 3;   // B: k-row bkr, cols bnc..bnc+7

    const float* Aptr = A + (long)(row0 + ar) * lda + ac;
    const float* Bptr = Bm + (long)bkr * ldb + col0 + bnc;

    float acc[4][4][4];
#pragma unroll
    for (int i = 0; i < 4; i++)
#pragma unroll
        for (int j = 0; j < 4; j++)
#pragma unroll
            for (int q = 0; q < 4; q++) acc[i][j][q] = 0.f;

    int nt = K >> 4;
    float4 av0 = *(const float4*)Aptr;
    float4 av1 = *(const float4*)(Aptr + 4);
    float4 bv0 = *(const float4*)Bptr;
    float4 bv1 = *(const float4*)(Bptr + 4);

    int stage = 0;
    {
        uint32_t* as = &As[0][ar * ASTRIDE + ac];
        as[0] = f2tf32(av0.x); as[1] = f2tf32(av0.y); as[2] = f2tf32(av0.z); as[3] = f2tf32(av0.w);
        as[4] = f2tf32(av1.x); as[5] = f2tf32(av1.y); as[6] = f2tf32(av1.z); as[7] = f2tf32(av1.w);
        uint32_t* bs = &Bs[0][bkr * BSTRIDE + bnc];
        bs[0] = f2tf32(bv0.x); bs[1] = f2tf32(bv0.y); bs[2] = f2tf32(bv0.z); bs[3] = f2tf32(bv0.w);
        bs[4] = f2tf32(bv1.x); bs[5] = f2tf32(bv1.y); bs[6] = f2tf32(bv1.z); bs[7] = f2tf32(bv1.w);
    }
    __syncthreads();

    for (int t = 0; t < nt; t++) {
        if (t + 1 < nt) {
            const float* An = Aptr + (t + 1) * 16;
            const float* Bn = Bptr + (long)(t + 1) * 16 * ldb;
            av0 = *(const float4*)An;       av1 = *(const float4*)(An + 4);
            bv0 = *(const float4*)Bn;       bv1 = *(const float4*)(Bn + 4);
        }
        const uint32_t* as = As[stage];
        const uint32_t* bs = Bs[stage];
#pragma unroll
        for (int kk = 0; kk < 16; kk += 8) {
            uint32_t afr[4][4], bfr[4][2];
#pragma unroll
            for (int ti = 0; ti < 4; ti++) {
                int rb = (wm + (ti << 4) + gr) * ASTRIDE + kk + gc;
                afr[ti][0] = as[rb];
                afr[ti][1] = as[rb + 8 * ASTRIDE];
                afr[ti][2] = as[rb + 4];
                afr[ti][3] = as[rb + 8 * ASTRIDE + 4];
            }
#pragma unroll
            for (int tj = 0; tj < 4; tj++) {
                int cb = (kk + gc) * BSTRIDE + wn + (tj << 3) + gr;
                bfr[tj][0] = bs[cb];
                bfr[tj][1] = bs[cb + 4 * BSTRIDE];
            }
#pragma unroll
            for (int ti = 0; ti < 4; ti++)
#pragma unroll
                for (int tj = 0; tj < 4; tj++)
                    mma_tf32(acc[ti][tj], afr[ti], bfr[tj]);
        }
        if (t + 1 < nt) {
            int ns = stage ^ 1;
            uint32_t* asw = &As[ns][ar * ASTRIDE + ac];
            asw[0] = f2tf32(av0.x); asw[1] = f2tf32(av0.y); asw[2] = f2tf32(av0.z); asw[3] = f2tf32(av0.w);
            asw[4] = f2tf32(av1.x); asw[5] = f2tf32(av1.y); asw[6] = f2tf32(av1.z); asw[7] = f2tf32(av1.w);
            uint32_t* bsw = &Bs[ns][bkr * BSTRIDE + bnc];
            bsw[0] = f2tf32(bv0.x); bsw[1] = f2tf32(bv0.y); bsw[2] = f2tf32(bv0.z); bsw[3] = f2tf32(bv0.w);
            bsw[4] = f2tf32(bv1.x); bsw[5] = f2tf32(bv1.y); bsw[6] = f2tf32(bv1.z); bsw[7] = f2tf32(bv1.w);
            __syncthreads();
            stage = ns;
        }
    }

    // epilogue
#pragma unroll
    for (int ti = 0; ti < 4; ti++) {
        int rg0 = row0 + wm + (ti << 4) + gr;
#pragma unroll
        for (int tj = 0; tj < 4; tj++) {
            int cg = col0 + wn + (tj << 3) + (gc << 1);
            float d0 = acc[ti][tj][0], d1 = acc[ti][tj][1];
            float d2 = acc[ti][tj][2], d3 = acc[ti][tj][3];
            if (bp) {
                float b0 = bp[cg], b1 = bp[cg + 1];
                d0 += b0; d1 += b1; d2 += b0; d3 += b1;
            }
            if (act == 1) {
                d0 = d0 > 0.f ? d0 : expm1f(d0);
                d1 = d1 > 0.f ? d1 : expm1f(d1);
                d2 = d2 > 0.f ? d2 : expm1f(d2);
                d3 = d3 > 0.f ? d3 : expm1f(d3);
            }
            float2 v0 = {d0, d1}, v1 = {d2, d3};
            *(float2*)(C + (long)rg0 * ldc + cg) = v0;
            *(float2*)(C + (long)(rg0 + 8) * ldc + cg) = v1;
        }
    }
}

// ---------------- attention left/right dots ----------------
__global__ void dots_kernel(const float* __restrict__ rows, int wIdx,
                            float* __restrict__ el, float* __restrict__ er,
                            int nrows, int rows_per_head, int width) {
    const float* w = IN_F(wIdx);
    int gw = (blockIdx.x * blockDim.x + threadIdx.x) >> 5;
    if (gw >= nrows) return;
    int lane = threadIdx.x & 31;
    int hh = gw / rows_per_head;
    const float* row = rows + (long)gw * width;
    const float* wl = w + (long)hh * 2 * width;
    const float* wr = wl + width;
    float a = 0.f, c = 0.f;
    for (int k = lane; k < width; k += 32) {
        float v = row[k];
        a = fmaf(v, wl[k], a);
        c = fmaf(v, wr[k], c);
    }
    a = warpSum(a); c = warpSum(c);
    if (lane == 0) { el[gw] = a; er[gw] = c; }
}

// ---------------- masked softmax attention rows ----------------
__global__ void att_kernel(const float* __restrict__ el, const float* __restrict__ er,
                           int biasIdx, int bias_per_head,
                           float* __restrict__ att) {
    const float* adj = IN_F(I_ADJ);
    const float* bias_arr = IN_F(biasIdx);
    int i = blockIdx.x;
    int z = blockIdx.y;
    int j = threadIdx.x;
    int b = z % BB;
    int hh = z / BB;
    float bb = bias_arr[bias_per_head ? hh : 0];
    float e = el[z * NN + i] + er[z * NN + j] + bb;
    e = (e >= 0.f) ? e : ALPHA_ * e;
    float adjv = adj[((long)b * NN + i) * NN + j];
    float val = (adjv > 0.f) ? e : NEG_E_;
    float mx = blockMax128(val);
    float ex = expf(val - mx);
    float sm = blockSum128(ex);
    att[((long)z * NN + i) * NN + j] = ex / sm;
}

// ---------------- final logits ----------------
__global__ void logits_kernel() {
    const float* fin_w = IN_F(I_FINW);
    const float* fin_b = IN_F(I_FINB);
    int gw = (blockIdx.x * blockDim.x + threadIdx.x) >> 5;
    if (gw >= BB * NN) return;
    int lane = threadIdx.x & 31;
    const float* row = g_x2 + (long)gw * NCLASS;
    float a = 0.f;
    for (int k = lane; k < NCLASS; k += 32) a = fmaf(row[k], fin_w[k], a);
    a = warpSum(a);
    if (lane == 0) g_logits[gw] = a + fin_b[0];
}

// ---------------- scores + stable rank + scatter fix ----------------
__global__ void score_fix_kernel() {
    const float* tag   = IN_F(I_TAG);
    const float* amask = IN_F(I_AMASK);
    int b = blockIdx.x;
    int j = threadIdx.x;
    float m = (tag[b * NN + j] > 0.f) ? amask[b * NN + j] : 0.f;
    float lg = g_logits[b * NN + j];

    float v1 = (m > 0.f) ? lg * m : NEG_S_;
    float mx1 = blockMax128(v1);
    float e1 = expf(v1 - mx1);
    float d1 = blockSum128(e1);
    float s1 = e1 / d1;

    float summary = blockSum128(m);

    float v2 = (m > 0.f) ? ((float)(NN - j)) / summary * m : NEG_S_;
    float mx2 = blockMax128(v2);
    float e2 = expf(v2 - mx2);
    float d2 = blockSum128(e2);
    float s2 = e2 / d2;

    __shared__ float sc[NN];
    sc[j] = s1 + s2;
    __syncthreads();

    float me = sc[j];
    int rank = 0;
    for (int k = 0; k < NN; k++) {
        float o = sc[k];
        rank += (o > me) || (o == me && k < j);
    }
    g_fix[(b * NN + j) * 2 + 0] = g_ig[(b * NN + rank) * 2 + 0];
    g_fix[(b * NN + j) * 2 + 1] = g_ig[(b * NN + rank) * 2 + 1];
}

// ---------------- expand rows (float32 output) ----------------
__global__ void expand_kernel(float* __restrict__ out) {
    int b = blockIdx.x;
    int l = threadIdx.x;
    __shared__ int f0[NN], f1[NN], csum[NN];
    __shared__ int fzs, total;
    f0[l] = g_fix[(b * NN + l) * 2 + 0];
    f1[l] = g_fix[(b * NN + l) * 2 + 1];
    __syncthreads();
    if (l == 0) {
        int fz = 0; bool found = false;
        for (int n = 0; n < NN; n++)
            if (f0[n] == 0 && f1[n] == 0) { fz = n; found = true; break; }
        if (!found) fz = 0;
        int cs = 0;
        for (int n = 0; n < NN; n++) {
            int len = (n < fz) ? (f1[n] - f0[n]) : 0;
            cs += len;
            csum[n] = cs;
        }
        fzs = fz; total = cs;
    }
    __syncthreads();
    int k = 0;
    for (int n = 0; n < NN; n++) k += (csum[n] <= l);
    if (k > NN - 1) k = NN - 1;
    int lenk = (k < fzs) ? (f1[k] - f0[k]) : 0;
    int excl = csum[k] - lenk;
    int val = f0[k] + (l - excl);
    out[b * NN + l] = (float)((l < total) ? val : l);
}

// ---------------- host launcher ----------------
extern "C" void kernel_launch(void* const* d_in, const int* in_sizes, int n_in,
                              void* d_out, int /*out_size*/) {
    float* out = (float*)d_out;

    InPack pk;
    int nn = n_in < 17 ? n_in : 17;
    for (int i = 0; i < 17; i++) {
        pk.p[i] = (i < nn) ? d_in[i] : nullptr;
        pk.s[i] = (i < nn) ? in_sizes[i] : 0;
    }
    pk.n = nn;
    classify_kernel<<<1, 32>>>(pk);

    float *p_xoff, *p_xw, *p_h, *p_el, *p_er, *p_att, *p_x1, *p_h2;
    float *p_el2, *p_er2, *p_att2, *p_x2;
    cudaGetSymbolAddress((void**)&p_xoff,  g_xoff);
    cudaGetSymbolAddress((void**)&p_xw,    g_xw);
    cudaGetSymbolAddress((void**)&p_h,     g_h);
    cudaGetSymbolAddress((void**)&p_el,    g_el);
    cudaGetSymbolAddress((void**)&p_er,    g_er);
    cudaGetSymbolAddress((void**)&p_att,   g_att);
    cudaGetSymbolAddress((void**)&p_x1,    g_x1);
    cudaGetSymbolAddress((void**)&p_h2,    g_h2);
    cudaGetSymbolAddress((void**)&p_el2,   g_el2);
    cudaGetSymbolAddress((void**)&p_er2,   g_er2);
    cudaGetSymbolAddress((void**)&p_att2,  g_att2);
    cudaGetSymbolAddress((void**)&p_x2,    g_x2);

    const int M = BB * NN;

    // 1. group pooling + index_group
    group_pool_kernel<<<BB, 256>>>();

    // 2. xw = x_off @ Wg_w + Wg_b      (8192 x 1024 x 768)
    tgemm_kernel<<<dim3(NFEAT / 128, M / 128, 1), 256>>>(
        p_xoff, -1, 0, FIN_, nullptr, I_WGW, 0, NFEAT,
        p_xw, 0, 0, 1, NFEAT, nullptr, I_WGB, 0, FIN_, 0);

    // 3. h[hh] = xw @ hW_w[hh] + hW_b[hh]   (8 x 8192 x 512 x 1024)
    tgemm_kernel<<<dim3(NHID / 128, M / 128, NHEADS), 256>>>(
        p_xw, -1, 0, NFEAT, nullptr, I_HWW, (long)NFEAT * NHID, NHID,
        p_h, (long)M * NHID, 0, NHEADS, NHID, nullptr, I_HWB, NHID, NFEAT, 0);

    // 4. el / er dots
    {
        int nrows = NHEADS * M;
        int nthreads = nrows * 32;
        dots_kernel<<<(nthreads + 255) / 256, 256>>>(p_h, I_HAW, p_el, p_er, nrows, M, NHID);
    }

    // 5. att = softmax(lrelu(el_i + er_j + b), adj-masked)
    att_kernel<<<dim3(NN, NHEADS * BB), 128>>>(p_el, p_er, I_HAB, 1, p_att);

    // 6. x1 = elu(att @ h) scattered into (B,N,H*NHID)   (512 x 128 x 512 x 128)
    tgemm_kernel<<<dim3(NHID / 128, NN / 128, NHEADS * BB), 256>>>(
        p_att, -1, (long)NN * NN, NN, p_h, -1, (long)NN * NHID, NHID,
        p_x1, (long)NN * NHEADS * NHID, NHID, BB, NHEADS * NHID,
        nullptr, -1, 0, NN, 1);

    // 7. h2 = x1 @ oW_w + oW_b        (8192 x 512 x 4096)
    tgemm_kernel<<<dim3(NCLASS / 128, M / 128, 1), 256>>>(
        p_x1, -1, 0, NHEADS * NHID, nullptr, I_OWW, 0, NCLASS,
        p_h2, 0, 0, 1, NCLASS, nullptr, I_OWB, 0, NHEADS * NHID, 0);

    // 8. el2 / er2 dots
    {
        int nthreads = M * 32;
        dots_kernel<<<(nthreads + 255) / 256, 256>>>(p_h2, I_OAW, p_el2, p_er2, M, M, NCLASS);
    }

    // 9. att2
    att_kernel<<<dim3(NN, BB), 128>>>(p_el2, p_er2, I_OAB, 0, p_att2);

    // 10. x2 = elu(att2 @ h2)   (64 x 128 x 512 x 128)
    tgemm_kernel<<<dim3(NCLASS / 128, NN / 128, BB), 256>>>(
        p_att2, -1, (long)NN * NN, NN, p_h2, -1, (long)NN * NCLASS, NCLASS,
        p_x2, (long)NN * NCLASS, 0, BB, NCLASS, nullptr, -1, 0, NN, 1);

    // 11. logits
    logits_kernel<<<(M * 32 + 255) / 256, 256>>>();

    // 12. scores + stable rank + scatter
    score_fix_kernel<<<BB, 128>>>();

    // 13. expand -> output
    expand_kernel<<<BB, 128>>>(out);
}

// round 7
// speedup vs baseline: 2.6997x; 1.2125x over previous
#include <cuda_runtime.h>
#include <math.h>
#include <stdint.h>

// ---------------- problem constants ----------------
#define BB    64
#define NN    128
#define FIN_  768
#define NFEAT 1024
#define NHID  512
#define NHEADS 8
#define NCLASS 512
#define ALPHA_ 0.2f
#define NEG_E_ (-9e15f)
#define NEG_S_ (-9e10f)

// input identity indices
enum { I_X=0, I_TAG, I_OFFS, I_AMASK, I_ADJ, I_WGW, I_WGB, I_HWW, I_HWB,
       I_HAW, I_HAB, I_OWW, I_OWB, I_OAW, I_OAB, I_FINW, I_FINB };

__device__ const void* g_inp[17];
#define IN_F(i) ((const float*)g_inp[i])

// ---------------- static device scratch ----------------
__device__ float g_xoff[BB * NN * FIN_];
__device__ float g_xw  [BB * NN * NFEAT];
__device__ float g_h   [NHEADS * BB * NN * NHID];    // (H,B,N,O)
__device__ float g_el  [NHEADS * BB * NN];
__device__ float g_er  [NHEADS * BB * NN];
__device__ float g_att [NHEADS * BB * NN * NN];      // (H,B,N,N)
__device__ float g_x1  [BB * NN * NHEADS * NHID];    // (B,N,H*O)
__device__ float g_h2  [BB * NN * NCLASS];
__device__ float g_el2 [BB * NN];
__device__ float g_er2 [BB * NN];
__device__ float g_att2[BB * NN * NN];
__device__ float g_x2  [BB * NN * NCLASS];
__device__ float g_logits[BB * NN];
__device__ int   g_ig  [BB * NN * 2];
__device__ int   g_fix [BB * NN * 2];

// ---------------- input classification ----------------
struct InPack { const void* p[17]; int s[17]; int n; };

__global__ void classify_kernel(InPack pk) {
    int lane = threadIdx.x;
    __shared__ int   bin_idx[4];
    __shared__ float bin_sum[4];
    __shared__ int   n_bin;
    if (lane == 0) n_bin = 0;
    __syncwarp();

    for (int i = 0; i < pk.n && i < 17; i++) {
        int sz = pk.s[i];
        const float* f = (const float*)pk.p[i];
        int target = -1;
        if      (sz == BB*NN*FIN_)            target = I_X;
        else if (sz == BB*NN*2)               target = I_OFFS;
        else if (sz == BB*NN*NN)              target = I_ADJ;
        else if (sz == FIN_*NFEAT)            target = I_WGW;
        else if (sz == NHEADS*NFEAT*NHID)     target = I_HWW;
        else if (sz == NHEADS*NHID*NCLASS)    target = I_OWW;
        else if (sz == NHEADS*NHID)           target = I_HWB;
        else if (sz == NHEADS)                target = I_HAB;
        else if (sz == NFEAT) {
            bool nz = false;
            for (int k = lane; k < sz; k += 32) nz |= (f[k] != 0.f);
            target = __any_sync(0xffffffffu, nz) ? I_OAW : I_WGB;
        } else if (sz == NCLASS) {
            bool nz = false;
            for (int k = lane; k < sz; k += 32) nz |= (f[k] != 0.f);
            target = __any_sync(0xffffffffu, nz) ? I_FINW : I_OWB;
        } else if (sz == 1) {
            if (lane == 0) { g_inp[I_OAB] = pk.p[i]; g_inp[I_FINB] = pk.p[i]; }
        } else if (sz == BB*NN) {
            bool frac = false; float sum = 0.f;
            for (int k = lane; k < sz; k += 32) {
                float v = f[k];
                frac |= (v != 0.f && v != 1.f);
                sum += v;
            }
            frac = __any_sync(0xffffffffu, frac);
#pragma unroll
            for (int o = 16; o; o >>= 1) sum += __shfl_xor_sync(0xffffffffu, sum, o);
            if (frac) target = I_HAW;
            else if (lane == 0) { bin_idx[n_bin] = i; bin_sum[n_bin] = sum; n_bin++; }
        }
        if (target >= 0 && lane == 0) g_inp[target] = pk.p[i];
        __syncwarp();
    }
    if (lane == 0) {
        if (n_bin >= 2) {
            int a = bin_idx[0], b = bin_idx[1];
            if (bin_sum[0] >= bin_sum[1]) { g_inp[I_AMASK] = pk.p[a]; g_inp[I_TAG] = pk.p[b]; }
            else                          { g_inp[I_AMASK] = pk.p[b]; g_inp[I_TAG] = pk.p[a]; }
        } else if (n_bin == 1) {
            g_inp[I_AMASK] = pk.p[bin_idx[0]]; g_inp[I_TAG] = pk.p[bin_idx[0]];
        }
    }
}

// ---------------- reduction helpers ----------------
__device__ __forceinline__ float warpSum(float v) {
#pragma unroll
    for (int o = 16; o; o >>= 1) v += __shfl_xor_sync(0xffffffffu, v, o);
    return v;
}
__device__ __forceinline__ float warpMax(float v) {
#pragma unroll
    for (int o = 16; o; o >>= 1) v = fmaxf(v, __shfl_xor_sync(0xffffffffu, v, o));
    return v;
}
__device__ __forceinline__ float blockSum128(float v) {
    __shared__ float s[4];
    float w = warpSum(v);
    if ((threadIdx.x & 31) == 0) s[threadIdx.x >> 5] = w;
    __syncthreads();
    float r = s[0] + s[1] + s[2] + s[3];
    __syncthreads();
    return r;
}
__device__ __forceinline__ float blockMax128(float v) {
    __shared__ float s[4];
    float w = warpMax(v);
    if ((threadIdx.x & 31) == 0) s[threadIdx.x >> 5] = w;
    __syncthreads();
    float r = fmaxf(fmaxf(s[0], s[1]), fmaxf(s[2], s[3]));
    __syncthreads();
    return r;
}

// ---------------- group pool ----------------
__global__ void group_pool_kernel() {
    const float* x  = IN_F(I_X);
    const int* offs = (const int*)g_inp[I_OFFS];
    int b = blockIdx.x;
    __shared__ int seg[NN];
    __shared__ int cnt[NN + 1];
    __shared__ int G_s;

    if (threadIdx.x == 0) {
        const int* ob = offs + b * NN * 2;
        int fz = 0; bool found = false;
        for (int n = 0; n < NN; n++)
            if (ob[2 * n] == 0 && ob[2 * n + 1] == 0) { fz = n; found = true; break; }
        if (!found) fz = 0;
        int cs = 0;
        for (int g = 0; g <= NN; g++) cnt[g] = 0;
        int ends_local[NN];
        for (int g = 0; g < NN; g++) ends_local[g] = 0;
        for (int n = 0; n < NN; n++) {
            int nxt = (n < NN - 1) ? ob[2 * (n + 1)] : 0;
            int bi = (n < fz && ob[2 * n + 1] == nxt - 1) ? 1 : 0;
            cs += bi;
            int s = cs - bi;
            seg[n] = s;
            cnt[s]++;
            if (bi && s < NN) ends_local[s] = n + 1;
        }
        G_s = cs;
        int* igb = g_ig + b * NN * 2;
        int prev_end = 0;
        for (int g = 0; g < NN; g++) {
            if (g < cs) {
                igb[2 * g] = prev_end;
                igb[2 * g + 1] = ends_local[g];
                prev_end = ends_local[g];
            } else {
                igb[2 * g] = 0; igb[2 * g + 1] = 0;
            }
        }
    }
    __syncthreads();
    int G = G_s;
    float* xo = g_xoff + (long)b * NN * FIN_;
    const float* xb = x + (long)b * NN * FIN_;
    for (int f = threadIdx.x; f < FIN_; f += blockDim.x) {
        for (int g = 0; g < NN; g++) xo[g * FIN_ + f] = 0.f;
        float acc = 0.f;
        int cur = seg[0];
        for (int n = 0; n < NN; n++) {
            int s = seg[n];
            if (s != cur) {
                if (cur < G) xo[cur * FIN_ + f] = acc / (float)max(cnt[cur], 1);
                acc = 0.f; cur = s;
            }
            acc += xb[n * FIN_ + f];
        }
        if (cur < G) xo[cur * FIN_ + f] = acc / (float)max(cnt[cur], 1);
    }
}

// ---------------- async-copy / ldmatrix / mma primitives ----------------
__device__ __forceinline__ void cp_async16(uint32_t dst, const void* src) {
    asm volatile("cp.async.cg.shared.global [%0], [%1], 16;\n" :: "r"(dst), "l"(src));
}
__device__ __forceinline__ void cp_commit() { asm volatile("cp.async.commit_group;\n"); }
template<int N> __device__ __forceinline__ void cp_wait() {
    asm volatile("cp.async.wait_group %0;\n" :: "n"(N));
}
__device__ __forceinline__ void ldsm_x4(uint32_t* r, uint32_t saddr) {
    asm volatile("ldmatrix.sync.aligned.m8n8.x4.shared.b16 {%0,%1,%2,%3}, [%4];\n"
                 : "=r"(r[0]), "=r"(r[1]), "=r"(r[2]), "=r"(r[3]) : "r"(saddr));
}
__device__ __forceinline__ void mma_tf32(float* d, const uint32_t* a, const uint32_t* b) {
    asm volatile(
        "mma.sync.aligned.m16n8k8.row.col.f32.tf32.tf32.f32 "
        "{%0,%1,%2,%3}, {%4,%5,%6,%7}, {%8,%9}, {%0,%1,%2,%3};\n"
        : "+f"(d[0]), "+f"(d[1]), "+f"(d[2]), "+f"(d[3])
        : "r"(a[0]), "r"(a[1]), "r"(a[2]), "r"(a[3]), "r"(b[0]), "r"(b[1]));
}

// ---------------- tf32 tensor-core GEMM: 128x128 tile, BK=16, cp.async x3 stages ----------------
// Requires: M%128==0, Ncol%128==0, K%16==0, lda/ldb/ldc %4==0.
#define ASTR 20
#define BSTR 132
#define STAGES 3
#define A_U32 (128 * ASTR)
#define B_U32 (16 * BSTR)
#define STAGE_U32 (A_U32 + B_U32)
#define TGEMM_SMEM (STAGES * STAGE_U32 * 4)

extern __shared__ uint32_t sm_dyn[];

__global__ void __launch_bounds__(256, 2)
tgemm_kernel(const float* Ap, int Ai, long sAz, int lda,
             const float* Bp, int Bi, long sBz, int ldb,
             float* C, long sCz1, long sCz2, int zdiv, int ldc,
             const float* biasp, int biasi, int sBiasz,
             int K, int act) {
    const float* A  = (Ai    >= 0) ? IN_F(Ai)    : Ap;
    const float* Bm = (Bi    >= 0) ? IN_F(Bi)    : Bp;
    const float* bp = (biasi >= 0) ? IN_F(biasi) : biasp;

    int z = blockIdx.z;
    A  += (long)z * sAz;
    Bm += (long)z * sBz;
    C  += (long)(z % zdiv) * sCz1 + (long)(z / zdiv) * sCz2;
    if (bp) bp += (long)z * sBiasz;

    int tid  = threadIdx.x;
    int wid  = tid >> 5;
    int lane = tid & 31;
    int gr = lane >> 2, gc = lane & 3;
    int wm = (wid & 1) << 6;
    int wn = (wid >> 1) << 5;
    int row0 = blockIdx.y << 7, col0 = blockIdx.x << 7;

    uint32_t smem_base = (uint32_t)__cvta_generic_to_shared(sm_dyn);

    // loader mapping
    int ar = tid & 127;                 // A row
    int ac0 = (tid >> 7) << 2;          // A k-chunk base (floats): {0,4} ; +8 for second
    int br = tid >> 4;                  // B k-row
    int bc0 = (tid & 15) << 2;          // B n-chunk (floats); +64 for second
    const char* Abase = (const char*)(A + (long)(row0 + ar) * lda);
    const char* Bbase = (const char*)(Bm + (long)br * ldb + col0);

    // ldmatrix per-thread address offsets (A frag)
    int lrow = lane & 15;               // row within 16-row tile
    int lcol = (lane >> 4) << 2;        // k offset 0 or 4

    float acc[4][4][4];
#pragma unroll
    for (int i = 0; i < 4; i++)
#pragma unroll
        for (int j = 0; j < 4; j++)
#pragma unroll
            for (int q = 0; q < 4; q++) acc[i][j][q] = 0.f;

    int nt = K >> 4;

    // ---- async load of tile t into stage s ----
    auto load_tile = [&](int t, int s) {
        uint32_t abuf = smem_base + (s * STAGE_U32) * 4;
        uint32_t bbuf = abuf + A_U32 * 4;
        const char* ag = Abase + (size_t)t * 64;                    // t*16 floats
        cp_async16(abuf + (ar * ASTR + ac0) * 4,        ag + ac0 * 4);
        cp_async16(abuf + (ar * ASTR + ac0 + 8) * 4,    ag + (ac0 + 8) * 4);
        const char* bg = Bbase + (size_t)t * 16 * ldb * 4;
        cp_async16(bbuf + (br * BSTR + bc0) * 4,        bg + bc0 * 4);
        cp_async16(bbuf + (br * BSTR + bc0 + 64) * 4,   bg + (bc0 + 64) * 4);
    };

    load_tile(0, 0); cp_commit();
    if (nt > 1) load_tile(1, 1);
    cp_commit();

    for (int t = 0; t < nt; t++) {
        cp_wait<1>();
        __syncthreads();
        if (t + 2 < nt) load_tile(t + 2, (t + 2) % STAGES);
        cp_commit();

        int s = t % STAGES;
        uint32_t abuf = smem_base + (s * STAGE_U32) * 4;
        const uint32_t* bs = sm_dyn + s * STAGE_U32 + A_U32;

#pragma unroll
        for (int kk = 0; kk < 16; kk += 8) {
            uint32_t afr[4][4], bfr[4][2];
#pragma unroll
            for (int ti = 0; ti < 4; ti++) {
                uint32_t addr = abuf + (((wm + (ti << 4) + lrow) * ASTR) + kk + lcol) * 4;
                ldsm_x4(afr[ti], addr);
            }
#pragma unroll
            for (int tj = 0; tj < 4; tj++) {
                int cb = (kk + gc) * BSTR + wn + (tj << 3) + gr;
                bfr[tj][0] = bs[cb];
                bfr[tj][1] = bs[cb + 4 * BSTR];
            }
#pragma unroll
            for (int ti = 0; ti < 4; ti++)
#pragma unroll
                for (int tj = 0; tj < 4; tj++)
                    mma_tf32(acc[ti][tj], afr[ti], bfr[tj]);
        }
    }

    // epilogue
#pragma unroll
    for (int ti = 0; ti < 4; ti++) {
        int rg0 = row0 + wm + (ti << 4) + gr;
#pragma unroll
        for (int tj = 0; tj < 4; tj++) {
            int cg = col0 + wn + (tj << 3) + (gc << 1);
            float d0 = acc[ti][tj][0], d1 = acc[ti][tj][1];
            float d2 = acc[ti][tj][2], d3 = acc[ti][tj][3];
            if (bp) {
                float b0 = bp[cg], b1 = bp[cg + 1];
                d0 += b0; d1 += b1; d2 += b0; d3 += b1;
            }
            if (act == 1) {
                d0 = d0 > 0.f ? d0 : expm1f(d0);
                d1 = d1 > 0.f ? d1 : expm1f(d1);
                d2 = d2 > 0.f ? d2 : expm1f(d2);
                d3 = d3 > 0.f ? d3 : expm1f(d3);
            }
            float2 v0 = {d0, d1}, v1 = {d2, d3};
            *(float2*)(C + (long)rg0 * ldc + cg) = v0;
            *(float2*)(C + (long)(rg0 + 8) * ldc + cg) = v1;
        }
    }
}

// ---------------- attention left/right dots ----------------
__global__ void dots_kernel(const float* __restrict__ rows, int wIdx,
                            float* __restrict__ el, float* __restrict__ er,
                            int nrows, int rows_per_head, int width) {
    const float* w = IN_F(wIdx);
    int gw = (blockIdx.x * blockDim.x + threadIdx.x) >> 5;
    if (gw >= nrows) return;
    int lane = threadIdx.x & 31;
    int hh = gw / rows_per_head;
    const float* row = rows + (long)gw * width;
    const float* wl = w + (long)hh * 2 * width;
    const float* wr = wl + width;
    float a = 0.f, c = 0.f;
    for (int k = lane; k < width; k += 32) {
        float v = row[k];
        a = fmaf(v, wl[k], a);
        c = fmaf(v, wr[k], c);
    }
    a = warpSum(a); c = warpSum(c);
    if (lane == 0) { el[gw] = a; er[gw] = c; }
}

// ---------------- masked softmax attention rows (warp-per-row) ----------------
__global__ void att_kernel(const float* __restrict__ el, const float* __restrict__ er,
                           int biasIdx, int bias_per_head,
                           float* __restrict__ att, int Z) {
    int gw = (blockIdx.x * blockDim.x + threadIdx.x) >> 5;
    if (gw >= Z * NN) return;
    int lane = threadIdx.x & 31;
    int z = gw >> 7, i = gw & 127;
    int b = z % BB;
    int hh = z / BB;
    float bb = IN_F(biasIdx)[bias_per_head ? hh : 0];
    float eli = el[z * NN + i];
    const float* adjrow = IN_F(I_ADJ) + ((long)b * NN + i) * NN;
    const float* err = er + z * NN;

    float v[4];
    float mx = -INFINITY;
#pragma unroll
    for (int q = 0; q < 4; q++) {
        int j = lane + (q << 5);
        float e = eli + err[j] + bb;
        e = (e >= 0.f) ? e : ALPHA_ * e;
        v[q] = (adjrow[j] > 0.f) ? e : NEG_E_;
        mx = fmaxf(mx, v[q]);
    }
    mx = warpMax(mx);
    float sum = 0.f;
#pragma unroll
    for (int q = 0; q < 4; q++) { v[q] = expf(v[q] - mx); sum += v[q]; }
    sum = warpSum(sum);
    float inv = 1.f / sum;
    float* arow = att + ((long)z * NN + i) * NN;
#pragma unroll
    for (int q = 0; q < 4; q++) arow[lane + (q << 5)] = v[q] * inv;
}

// ---------------- final logits ----------------
__global__ void logits_kernel() {
    const float* fin_w = IN_F(I_FINW);
    const float* fin_b = IN_F(I_FINB);
    int gw = (blockIdx.x * blockDim.x + threadIdx.x) >> 5;
    if (gw >= BB * NN) return;
    int lane = threadIdx.x & 31;
    const float* row = g_x2 + (long)gw * NCLASS;
    float a = 0.f;
    for (int k = lane; k < NCLASS; k += 32) a = fmaf(row[k], fin_w[k], a);
    a = warpSum(a);
    if (lane == 0) g_logits[gw] = a + fin_b[0];
}

// ---------------- scores + stable rank + scatter fix ----------------
__global__ void score_fix_kernel() {
    const float* tag   = IN_F(I_TAG);
    const float* amask = IN_F(I_AMASK);
    int b = blockIdx.x;
    int j = threadIdx.x;
    float m = (tag[b * NN + j] > 0.f) ? amask[b * NN + j] : 0.f;
    float lg = g_logits[b * NN + j];

    float v1 = (m > 0.f) ? lg * m : NEG_S_;
    float mx1 = blockMax128(v1);
    float e1 = expf(v1 - mx1);
    float d1 = blockSum128(e1);
    float s1 = e1 / d1;

    float summary = blockSum128(m);

    float v2 = (m > 0.f) ? ((float)(NN - j)) / summary * m : NEG_S_;
    float mx2 = blockMax128(v2);
    float e2 = expf(v2 - mx2);
    float d2 = blockSum128(e2);
    float s2 = e2 / d2;

    __shared__ float sc[NN];
    sc[j] = s1 + s2;
    __syncthreads();

    float me = sc[j];
    int rank = 0;
    for (int k = 0; k < NN; k++) {
        float o = sc[k];
        rank += (o > me) || (o == me && k < j);
    }
    g_fix[(b * NN + j) * 2 + 0] = g_ig[(b * NN + rank) * 2 + 0];
    g_fix[(b * NN + j) * 2 + 1] = g_ig[(b * NN + rank) * 2 + 1];
}

// ---------------- expand rows (float32 output) ----------------
__global__ void expand_kernel(float* __restrict__ out) {
    int b = blockIdx.x;
    int l = threadIdx.x;
    __shared__ int f0[NN], f1[NN], csum[NN];
    __shared__ int fzs, total;
    f0[l] = g_fix[(b * NN + l) * 2 + 0];
    f1[l] = g_fix[(b * NN + l) * 2 + 1];
    __syncthreads();
    if (l == 0) {
        int fz = 0; bool found = false;
        for (int n = 0; n < NN; n++)
            if (f0[n] == 0 && f1[n] == 0) { fz = n; found = true; break; }
        if (!found) fz = 0;
        int cs = 0;
        for (int n = 0; n < NN; n++) {
            int len = (n < fz) ? (f1[n] - f0[n]) : 0;
            cs += len;
            csum[n] = cs;
        }
        fzs = fz; total = cs;
    }
    __syncthreads();
    int k = 0;
    for (int n = 0; n < NN; n++) k += (csum[n] <= l);
    if (k > NN - 1) k = NN - 1;
    int lenk = (k < fzs) ? (f1[k] - f0[k]) : 0;
    int excl = csum[k] - lenk;
    int val = f0[k] + (l - excl);
    out[b * NN + l] = (float)((l < total) ? val : l);
}

// ---------------- host launcher ----------------
extern "C" void kernel_launch(void* const* d_in, const int* in_sizes, int n_in,
                              void* d_out, int /*out_size*/) {
    float* out = (float*)d_out;

    InPack pk;
    int nn = n_in < 17 ? n_in : 17;
    for (int i = 0; i < 17; i++) {
        pk.p[i] = (i < nn) ? d_in[i] : nullptr;
        pk.s[i] = (i < nn) ? in_sizes[i] : 0;
    }
    pk.n = nn;
    classify_kernel<<<1, 32>>>(pk);

    float *p_xoff, *p_xw, *p_h, *p_el, *p_er, *p_att, *p_x1, *p_h2;
    float *p_el2, *p_er2, *p_att2, *p_x2;
    cudaGetSymbolAddress((void**)&p_xoff,  g_xoff);
    cudaGetSymbolAddress((void**)&p_xw,    g_xw);
    cudaGetSymbolAddress((void**)&p_h,     g_h);
    cudaGetSymbolAddress((void**)&p_el,    g_el);
    cudaGetSymbolAddress((void**)&p_er,    g_er);
    cudaGetSymbolAddress((void**)&p_att,   g_att);
    cudaGetSymbolAddress((void**)&p_x1,    g_x1);
    cudaGetSymbolAddress((void**)&p_h2,    g_h2);
    cudaGetSymbolAddress((void**)&p_el2,   g_el2);
    cudaGetSymbolAddress((void**)&p_er2,   g_er2);
    cudaGetSymbolAddress((void**)&p_att2,  g_att2);
    cudaGetSymbolAddress((void**)&p_x2,    g_x2);

    static bool attr_set = false;
    if (!attr_set) {
        cudaFuncSetAttribute(tgemm_kernel, cudaFuncAttributeMaxDynamicSharedMemorySize, TGEMM_SMEM);
        attr_set = true;
    }

    const int M = BB * NN;

    // 1. group pooling + index_group
    group_pool_kernel<<<BB, 256>>>();

    // 2. xw = x_off @ Wg_w + Wg_b      (8192 x 1024 x 768)
    tgemm_kernel<<<dim3(NFEAT / 128, M / 128, 1), 256, TGEMM_SMEM>>>(
        p_xoff, -1, 0, FIN_, nullptr, I_WGW, 0, NFEAT,
        p_xw, 0, 0, 1, NFEAT, nullptr, I_WGB, 0, FIN_, 0);

    // 3. h[hh] = xw @ hW_w[hh] + hW_b[hh]   (8 x 8192 x 512 x 1024)
    tgemm_kernel<<<dim3(NHID / 128, M / 128, NHEADS), 256, TGEMM_SMEM>>>(
        p_xw, -1, 0, NFEAT, nullptr, I_HWW, (long)NFEAT * NHID, NHID,
        p_h, (long)M * NHID, 0, NHEADS, NHID, nullptr, I_HWB, NHID, NFEAT, 0);

    // 4. el / er dots
    {
        int nrows = NHEADS * M;
        int nthreads = nrows * 32;
        dots_kernel<<<(nthreads + 255) / 256, 256>>>(p_h, I_HAW, p_el, p_er, nrows, M, NHID);
    }

    // 5. att = softmax(lrelu(el_i + er_j + b), adj-masked)
    {
        int Z = NHEADS * BB;
        att_kernel<<<(Z * NN * 32 + 255) / 256, 256>>>(p_el, p_er, I_HAB, 1, p_att, Z);
    }

    // 6. x1 = elu(att @ h) scattered into (B,N,H*NHID)   (512 x 128 x 512 x 128)
    tgemm_kernel<<<dim3(NHID / 128, NN / 128, NHEADS * BB), 256, TGEMM_SMEM>>>(
        p_att, -1, (long)NN * NN, NN, p_h, -1, (long)NN * NHID, NHID,
        p_x1, (long)NN * NHEADS * NHID, NHID, BB, NHEADS * NHID,
        nullptr, -1, 0, NN, 1);

    // 7. h2 = x1 @ oW_w + oW_b        (8192 x 512 x 4096)
    tgemm_kernel<<<dim3(NCLASS / 128, M / 128, 1), 256, TGEMM_SMEM>>>(
        p_x1, -1, 0, NHEADS * NHID, nullptr, I_OWW, 0, NCLASS,
        p_h2, 0, 0, 1, NCLASS, nullptr, I_OWB, 0, NHEADS * NHID, 0);

    // 8. el2 / er2 dots
    {
        int nthreads = M * 32;
        dots_kernel<<<(nthreads + 255) / 256, 256>>>(p_h2, I_OAW, p_el2, p_er2, M, M, NCLASS);
    }

    // 9. att2
    att_kernel<<<(BB * NN * 32 + 255) / 256, 256>>>(p_el2, p_er2, I_OAB, 0, p_att2, BB);

    // 10. x2 = elu(att2 @ h2)   (64 x 128 x 512 x 128)
    tgemm_kernel<<<dim3(NCLASS / 128, NN / 128, BB), 256, TGEMM_SMEM>>>(
        p_att2, -1, (long)NN * NN, NN, p_h2, -1, (long)NN * NCLASS, NCLASS,
        p_x2, (long)NN * NCLASS, 0, BB, NCLASS, nullptr, -1, 0, NN, 1);

    // 11. logits
    logits_kernel<<<(M * 32 + 255) / 256, 256>>>();

    // 12. scores + stable rank + scatter
    score_fix_kernel<<<BB, 128>>>();

    // 13. expand -> output
    expand_kernel<<<BB, 128>>>(out);
}

// round 8
// speedup vs baseline: 2.7011x; 1.0005x over previous
#include <cuda_runtime.h>
#include <math.h>
#include <stdint.h>

// ---------------- problem constants ----------------
#define BB    64
#define NN    128
#define FIN_  768
#define NFEAT 1024
#define NHID  512
#define NHEADS 8
#define NCLASS 512
#define ALPHA_ 0.2f
#define NEG_E_ (-9e15f)
#define NEG_S_ (-9e10f)

// input identity indices
enum { I_X=0, I_TAG, I_OFFS, I_AMASK, I_ADJ, I_WGW, I_WGB, I_HWW, I_HWB,
       I_HAW, I_HAB, I_OWW, I_OWB, I_OAW, I_OAB, I_FINW, I_FINB };

__device__ const void* g_inp[17];
#define IN_F(i) ((const float*)g_inp[i])

// ---------------- static device scratch ----------------
__device__ float g_xoff[BB * NN * FIN_];
__device__ float g_xw  [BB * NN * NFEAT];
__device__ float g_h   [NHEADS * BB * NN * NHID];    // (H,B,N,O)
__device__ float g_el  [NHEADS * BB * NN];
__device__ float g_er  [NHEADS * BB * NN];
__device__ float g_att [NHEADS * BB * NN * NN];      // (H,B,N,N)
__device__ float g_x1  [BB * NN * NHEADS * NHID];    // (B,N,H*O)
__device__ float g_h2  [BB * NN * NCLASS];
__device__ float g_el2 [BB * NN];
__device__ float g_er2 [BB * NN];
__device__ float g_att2[BB * NN * NN];
__device__ float g_x2  [BB * NN * NCLASS];
__device__ float g_logits[BB * NN];
__device__ int   g_ig  [BB * NN * 2];
__device__ int   g_fix [BB * NN * 2];

// ---------------- input classification ----------------
struct InPack { const void* p[17]; int s[17]; int n; };

__global__ void classify_kernel(InPack pk) {
    int lane = threadIdx.x;
    __shared__ int   bin_idx[4];
    __shared__ float bin_sum[4];
    __shared__ int   n_bin;
    if (lane == 0) n_bin = 0;
    __syncwarp();

    for (int i = 0; i < pk.n && i < 17; i++) {
        int sz = pk.s[i];
        const float* f = (const float*)pk.p[i];
        int target = -1;
        if      (sz == BB*NN*FIN_)            target = I_X;
        else if (sz == BB*NN*2)               target = I_OFFS;
        else if (sz == BB*NN*NN)              target = I_ADJ;
        else if (sz == FIN_*NFEAT)            target = I_WGW;
        else if (sz == NHEADS*NFEAT*NHID)     target = I_HWW;
        else if (sz == NHEADS*NHID*NCLASS)    target = I_OWW;
        else if (sz == NHEADS*NHID)           target = I_HWB;
        else if (sz == NHEADS)                target = I_HAB;
        else if (sz == NFEAT) {
            bool nz = false;
            for (int k = lane; k < sz; k += 32) nz |= (f[k] != 0.f);
            target = __any_sync(0xffffffffu, nz) ? I_OAW : I_WGB;
        } else if (sz == NCLASS) {
            bool nz = false;
            for (int k = lane; k < sz; k += 32) nz |= (f[k] != 0.f);
            target = __any_sync(0xffffffffu, nz) ? I_FINW : I_OWB;
        } else if (sz == 1) {
            if (lane == 0) { g_inp[I_OAB] = pk.p[i]; g_inp[I_FINB] = pk.p[i]; }
        } else if (sz == BB*NN) {
            bool frac = false; float sum = 0.f;
            for (int k = lane; k < sz; k += 32) {
                float v = f[k];
                frac |= (v != 0.f && v != 1.f);
                sum += v;
            }
            frac = __any_sync(0xffffffffu, frac);
#pragma unroll
            for (int o = 16; o; o >>= 1) sum += __shfl_xor_sync(0xffffffffu, sum, o);
            if (frac) target = I_HAW;
            else if (lane == 0) { bin_idx[n_bin] = i; bin_sum[n_bin] = sum; n_bin++; }
        }
        if (target >= 0 && lane == 0) g_inp[target] = pk.p[i];
        __syncwarp();
    }
    if (lane == 0) {
        if (n_bin >= 2) {
            int a = bin_idx[0], b = bin_idx[1];
            if (bin_sum[0] >= bin_sum[1]) { g_inp[I_AMASK] = pk.p[a]; g_inp[I_TAG] = pk.p[b]; }
            else                          { g_inp[I_AMASK] = pk.p[b]; g_inp[I_TAG] = pk.p[a]; }
        } else if (n_bin == 1) {
            g_inp[I_AMASK] = pk.p[bin_idx[0]]; g_inp[I_TAG] = pk.p[bin_idx[0]];
        }
    }
}

// ---------------- reduction helpers ----------------
__device__ __forceinline__ float warpSum(float v) {
#pragma unroll
    for (int o = 16; o; o >>= 1) v += __shfl_xor_sync(0xffffffffu, v, o);
    return v;
}
__device__ __forceinline__ float warpMax(float v) {
#pragma unroll
    for (int o = 16; o; o >>= 1) v = fmaxf(v, __shfl_xor_sync(0xffffffffu, v, o));
    return v;
}
__device__ __forceinline__ float blockSum128(float v) {
    __shared__ float s[4];
    float w = warpSum(v);
    if ((threadIdx.x & 31) == 0) s[threadIdx.x >> 5] = w;
    __syncthreads();
    float r = s[0] + s[1] + s[2] + s[3];
    __syncthreads();
    return r;
}
__device__ __forceinline__ float blockMax128(float v) {
    __shared__ float s[4];
    float w = warpMax(v);
    if ((threadIdx.x & 31) == 0) s[threadIdx.x >> 5] = w;
    __syncthreads();
    float r = fmaxf(fmaxf(s[0], s[1]), fmaxf(s[2], s[3]));
    __syncthreads();
    return r;
}

// ---------------- group pool ----------------
__global__ void group_pool_kernel() {
    const float* x  = IN_F(I_X);
    const int* offs = (const int*)g_inp[I_OFFS];
    int b = blockIdx.x;
    __shared__ int seg[NN];
    __shared__ int cnt[NN + 1];
    __shared__ int G_s;

    if (threadIdx.x == 0) {
        const int* ob = offs + b * NN * 2;
        int fz = 0; bool found = false;
        for (int n = 0; n < NN; n++)
            if (ob[2 * n] == 0 && ob[2 * n + 1] == 0) { fz = n; found = true; break; }
        if (!found) fz = 0;
        int cs = 0;
        for (int g = 0; g <= NN; g++) cnt[g] = 0;
        int ends_local[NN];
        for (int g = 0; g < NN; g++) ends_local[g] = 0;
        for (int n = 0; n < NN; n++) {
            int nxt = (n < NN - 1) ? ob[2 * (n + 1)] : 0;
            int bi = (n < fz && ob[2 * n + 1] == nxt - 1) ? 1 : 0;
            cs += bi;
            int s = cs - bi;
            seg[n] = s;
            cnt[s]++;
            if (bi && s < NN) ends_local[s] = n + 1;
        }
        G_s = cs;
        int* igb = g_ig + b * NN * 2;
        int prev_end = 0;
        for (int g = 0; g < NN; g++) {
            if (g < cs) {
                igb[2 * g] = prev_end;
                igb[2 * g + 1] = ends_local[g];
                prev_end = ends_local[g];
            } else {
                igb[2 * g] = 0; igb[2 * g + 1] = 0;
            }
        }
    }
    __syncthreads();
    int G = G_s;
    float* xo = g_xoff + (long)b * NN * FIN_;
    const float* xb = x + (long)b * NN * FIN_;
    for (int f = threadIdx.x; f < FIN_; f += blockDim.x) {
        for (int g = 0; g < NN; g++) xo[g * FIN_ + f] = 0.f;
        float acc = 0.f;
        int cur = seg[0];
        for (int n = 0; n < NN; n++) {
            int s = seg[n];
            if (s != cur) {
                if (cur < G) xo[cur * FIN_ + f] = acc / (float)max(cnt[cur], 1);
                acc = 0.f; cur = s;
            }
            acc += xb[n * FIN_ + f];
        }
        if (cur < G) xo[cur * FIN_ + f] = acc / (float)max(cnt[cur], 1);
    }
}

// ---------------- async-copy / ldmatrix / mma primitives ----------------
__device__ __forceinline__ void cp_async16(uint32_t dst, const void* src) {
    asm volatile("cp.async.cg.shared.global [%0], [%1], 16;\n" :: "r"(dst), "l"(src));
}
__device__ __forceinline__ void cp_commit() { asm volatile("cp.async.commit_group;\n"); }
template<int N> __device__ __forceinline__ void cp_wait() {
    asm volatile("cp.async.wait_group %0;\n" :: "n"(N));
}
__device__ __forceinline__ void ldsm_x4(uint32_t* r, uint32_t saddr) {
    asm volatile("ldmatrix.sync.aligned.m8n8.x4.shared.b16 {%0,%1,%2,%3}, [%4];\n"
                 : "=r"(r[0]), "=r"(r[1]), "=r"(r[2]), "=r"(r[3]) : "r"(saddr));
}
__device__ __forceinline__ void mma_tf32(float* d, const uint32_t* a, const uint32_t* b) {
    asm volatile(
        "mma.sync.aligned.m16n8k8.row.col.f32.tf32.tf32.f32 "
        "{%0,%1,%2,%3}, {%4,%5,%6,%7}, {%8,%9}, {%0,%1,%2,%3};\n"
        : "+f"(d[0]), "+f"(d[1]), "+f"(d[2]), "+f"(d[3])
        : "r"(a[0]), "r"(a[1]), "r"(a[2]), "r"(a[3]), "r"(b[0]), "r"(b[1]));
}

// ---------------- tf32 tensor-core GEMM: 128x128 tile, BK=16, cp.async x3 stages ----------------
// Requires: M%128==0, Ncol%128==0, K%16==0, lda/ldb/ldc %4==0.
#define ASTR 20
#define BSTR 132
#define STAGES 3
#define A_U32 (128 * ASTR)
#define B_U32 (16 * BSTR)
#define STAGE_U32 (A_U32 + B_U32)
#define TGEMM_SMEM (STAGES * STAGE_U32 * 4)

extern __shared__ uint32_t sm_dyn[];

__global__ void __launch_bounds__(256, 2)
tgemm_kernel(const float* Ap, int Ai, long sAz, int lda,
             const float* Bp, int Bi, long sBz, int ldb,
             float* C, long sCz1, long sCz2, int zdiv, int ldc,
             const float* biasp, int biasi, int sBiasz,
             int K, int act) {
    const float* A  = (Ai    >= 0) ? IN_F(Ai)    : Ap;
    const float* Bm = (Bi    >= 0) ? IN_F(Bi)    : Bp;
    const float* bp = (biasi >= 0) ? IN_F(biasi) : biasp;

    int z = blockIdx.z;
    A  += (long)z * sAz;
    Bm += (long)z * sBz;
    C  += (long)(z % zdiv) * sCz1 + (long)(z / zdiv) * sCz2;
    if (bp) bp += (long)z * sBiasz;

    int tid  = threadIdx.x;
    int wid  = tid >> 5;
    int lane = tid & 31;
    int gr = lane >> 2, gc = lane & 3;
    int wm = (wid & 1) << 6;
    int wn = (wid >> 1) << 5;
    int row0 = blockIdx.y << 7, col0 = blockIdx.x << 7;

    uint32_t smem_base = (uint32_t)__cvta_generic_to_shared(sm_dyn);

    // loader mapping
    int ar = tid & 127;                 // A row
    int ac0 = (tid >> 7) << 2;          // A k-chunk base (floats): {0,4} ; +8 for second
    int br = tid >> 4;                  // B k-row
    int bc0 = (tid & 15) << 2;          // B n-chunk (floats); +64 for second
    const char* Abase = (const char*)(A + (long)(row0 + ar) * lda);
    const char* Bbase = (const char*)(Bm + (long)br * ldb + col0);

    // ldmatrix per-thread address offsets (A frag)
    int lrow = lane & 15;               // row within 16-row tile
    int lcol = (lane >> 4) << 2;        // k offset 0 or 4

    float acc[4][4][4];
#pragma unroll
    for (int i = 0; i < 4; i++)
#pragma unroll
        for (int j = 0; j < 4; j++)
#pragma unroll
            for (int q = 0; q < 4; q++) acc[i][j][q] = 0.f;

    int nt = K >> 4;

    // ---- async load of tile t into stage s ----
    auto load_tile = [&](int t, int s) {
        uint32_t abuf = smem_base + (s * STAGE_U32) * 4;
        uint32_t bbuf = abuf + A_U32 * 4;
        const char* ag = Abase + (size_t)t * 64;                    // t*16 floats
        cp_async16(abuf + (ar * ASTR + ac0) * 4,        ag + ac0 * 4);
        cp_async16(abuf + (ar * ASTR + ac0 + 8) * 4,    ag + (ac0 + 8) * 4);
        const char* bg = Bbase + (size_t)t * 16 * ldb * 4;
        cp_async16(bbuf + (br * BSTR + bc0) * 4,        bg + bc0 * 4);
        cp_async16(bbuf + (br * BSTR + bc0 + 64) * 4,   bg + (bc0 + 64) * 4);
    };

    load_tile(0, 0); cp_commit();
    if (nt > 1) load_tile(1, 1);
    cp_commit();

    for (int t = 0; t < nt; t++) {
        cp_wait<1>();
        __syncthreads();
        if (t + 2 < nt) load_tile(t + 2, (t + 2) % STAGES);
        cp_commit();

        int s = t % STAGES;
        uint32_t abuf = smem_base + (s * STAGE_U32) * 4;
        const uint32_t* bs = sm_dyn + s * STAGE_U32 + A_U32;

#pragma unroll
        for (int kk = 0; kk < 16; kk += 8) {
            uint32_t afr[4][4], bfr[4][2];
#pragma unroll
            for (int ti = 0; ti < 4; ti++) {
                uint32_t addr = abuf + (((wm + (ti << 4) + lrow) * ASTR) + kk + lcol) * 4;
                ldsm_x4(afr[ti], addr);
            }
#pragma unroll
            for (int tj = 0; tj < 4; tj++) {
                int cb = (kk + gc) * BSTR + wn + (tj << 3) + gr;
                bfr[tj][0] = bs[cb];
                bfr[tj][1] = bs[cb + 4 * BSTR];
            }
#pragma unroll
            for (int ti = 0; ti < 4; ti++)
#pragma unroll
                for (int tj = 0; tj < 4; tj++)
                    mma_tf32(acc[ti][tj], afr[ti], bfr[tj]);
        }
    }

    // epilogue
#pragma unroll
    for (int ti = 0; ti < 4; ti++) {
        int rg0 = row0 + wm + (ti << 4) + gr;
#pragma unroll
        for (int tj = 0; tj < 4; tj++) {
            int cg = col0 + wn + (tj << 3) + (gc << 1);
            float d0 = acc[ti][tj][0], d1 = acc[ti][tj][1];
            float d2 = acc[ti][tj][2], d3 = acc[ti][tj][3];
            if (bp) {
                float b0 = bp[cg], b1 = bp[cg + 1];
                d0 += b0; d1 += b1; d2 += b0; d3 += b1;
            }
            if (act == 1) {
                d0 = d0 > 0.f ? d0 : expm1f(d0);
                d1 = d1 > 0.f ? d1 : expm1f(d1);
                d2 = d2 > 0.f ? d2 : expm1f(d2);
                d3 = d3 > 0.f ? d3 : expm1f(d3);
            }
            float2 v0 = {d0, d1}, v1 = {d2, d3};
            *(float2*)(C + (long)rg0 * ldc + cg) = v0;
            *(float2*)(C + (long)(rg0 + 8) * ldc + cg) = v1;
        }
    }
}

// ---------------- attention left/right dots ----------------
__global__ void dots_kernel(const float* __restrict__ rows, int wIdx,
                            float* __restrict__ el, float* __restrict__ er,
                            int nrows, int rows_per_head, int width) {
    const float* w = IN_F(wIdx);
    int gw = (blockIdx.x * blockDim.x + threadIdx.x) >> 5;
    if (gw >= nrows) return;
    int lane = threadIdx.x & 31;
    int hh = gw / rows_per_head;
    const float* row = rows + (long)gw * width;
    const float* wl = w + (long)hh * 2 * width;
    const float* wr = wl + width;
    float a = 0.f, c = 0.f;
    for (int k = lane; k < width; k += 32) {
        float v = row[k];
        a = fmaf(v, wl[k], a);
        c = fmaf(v, wr[k], c);
    }
    a = warpSum(a); c = warpSum(c);
    if (lane == 0) { el[gw] = a; er[gw] = c; }
}

// ---------------- masked softmax attention rows (warp-per-row) ----------------
__global__ void att_kernel(const float* __restrict__ el, const float* __restrict__ er,
                           int biasIdx, int bias_per_head,
                           float* __restrict__ att, int Z) {
    int gw = (blockIdx.x * blockDim.x + threadIdx.x) >> 5;
    if (gw >= Z * NN) return;
    int lane = threadIdx.x & 31;
    int z = gw >> 7, i = gw & 127;
    int b = z % BB;
    int hh = z / BB;
    float bb = IN_F(biasIdx)[bias_per_head ? hh : 0];
    float eli = el[z * NN + i];
    const float* adjrow = IN_F(I_ADJ) + ((long)b * NN + i) * NN;
    const float* err = er + z * NN;

    float v[4];
    float mx = -INFINITY;
#pragma unroll
    for (int q = 0; q < 4; q++) {
        int j = lane + (q << 5);
        float e = eli + err[j] + bb;
        e = (e >= 0.f) ? e : ALPHA_ * e;
        v[q] = (adjrow[j] > 0.f) ? e : NEG_E_;
        mx = fmaxf(mx, v[q]);
    }
    mx = warpMax(mx);
    float sum = 0.f;
#pragma unroll
    for (int q = 0; q < 4; q++) { v[q] = expf(v[q] - mx); sum += v[q]; }
    sum = warpSum(sum);
    float inv = 1.f / sum;
    float* arow = att + ((long)z * NN + i) * NN;
#pragma unroll
    for (int q = 0; q < 4; q++) arow[lane + (q << 5)] = v[q] * inv;
}

// ---------------- final logits ----------------
__global__ void logits_kernel() {
    const float* fin_w = IN_F(I_FINW);
    const float* fin_b = IN_F(I_FINB);
    int gw = (blockIdx.x * blockDim.x + threadIdx.x) >> 5;
    if (gw >= BB * NN) return;
    int lane = threadIdx.x & 31;
    const float* row = g_x2 + (long)gw * NCLASS;
    float a = 0.f;
    for (int k = lane; k < NCLASS; k += 32) a = fmaf(row[k], fin_w[k], a);
    a = warpSum(a);
    if (lane == 0) g_logits[gw] = a + fin_b[0];
}

// ---------------- scores + stable rank + scatter fix ----------------
__global__ void score_fix_kernel() {
    const float* tag   = IN_F(I_TAG);
    const float* amask = IN_F(I_AMASK);
    int b = blockIdx.x;
    int j = threadIdx.x;
    float m = (tag[b * NN + j] > 0.f) ? amask[b * NN + j] : 0.f;
    float lg = g_logits[b * NN + j];

    float v1 = (m > 0.f) ? lg * m : NEG_S_;
    float mx1 = blockMax128(v1);
    float e1 = expf(v1 - mx1);
    float d1 = blockSum128(e1);
    float s1 = e1 / d1;

    float summary = blockSum128(m);

    float v2 = (m > 0.f) ? ((float)(NN - j)) / summary * m : NEG_S_;
    float mx2 = blockMax128(v2);
    float e2 = expf(v2 - mx2);
    float d2 = blockSum128(e2);
    float s2 = e2 / d2;

    __shared__ float sc[NN];
    sc[j] = s1 + s2;
    __syncthreads();

    float me = sc[j];
    int rank = 0;
    for (int k = 0; k < NN; k++) {
        float o = sc[k];
        rank += (o > me) || (o == me && k < j);
    }
    g_fix[(b * NN + j) * 2 + 0] = g_ig[(b * NN + rank) * 2 + 0];
    g_fix[(b * NN + j) * 2 + 1] = g_ig[(b * NN + rank) * 2 + 1];
}

// ---------------- expand rows (float32 output) ----------------
__global__ void expand_kernel(float* __restrict__ out) {
    int b = blockIdx.x;
    int l = threadIdx.x;
    __shared__ int f0[NN], f1[NN], csum[NN];
    __shared__ int fzs, total;
    f0[l] = g_fix[(b * NN + l) * 2 + 0];
    f1[l] = g_fix[(b * NN + l) * 2 + 1];
    __syncthreads();
    if (l == 0) {
        int fz = 0; bool found = false;
        for (int n = 0; n < NN; n++)
            if (f0[n] == 0 && f1[n] == 0) { fz = n; found = true; break; }
        if (!found) fz = 0;
        int cs = 0;
        for (int n = 0; n < NN; n++) {
            int len = (n < fz) ? (f1[n] - f0[n]) : 0;
            cs += len;
            csum[n] = cs;
        }
        fzs = fz; total = cs;
    }
    __syncthreads();
    int k = 0;
    for (int n = 0; n < NN; n++) k += (csum[n] <= l);
    if (k > NN - 1) k = NN - 1;
    int lenk = (k < fzs) ? (f1[k] - f0[k]) : 0;
    int excl = csum[k] - lenk;
    int val = f0[k] + (l - excl);
    out[b * NN + l] = (float)((l < total) ? val : l);
}

// ---------------- host launcher ----------------
extern "C" void kernel_launch(void* const* d_in, const int* in_sizes, int n_in,
                              void* d_out, int /*out_size*/) {
    float* out = (float*)d_out;

    InPack pk;
    int nn = n_in < 17 ? n_in : 17;
    for (int i = 0; i < 17; i++) {
        pk.p[i] = (i < nn) ? d_in[i] : nullptr;
        pk.s[i] = (i < nn) ? in_sizes[i] : 0;
    }
    pk.n = nn;
    classify_kernel<<<1, 32>>>(pk);

    float *p_xoff, *p_xw, *p_h, *p_el, *p_er, *p_att, *p_x1, *p_h2;
    float *p_el2, *p_er2, *p_att2, *p_x2;
    cudaGetSymbolAddress((void**)&p_xoff,  g_xoff);
    cudaGetSymbolAddress((void**)&p_xw,    g_xw);
    cudaGetSymbolAddress((void**)&p_h,     g_h);
    cudaGetSymbolAddress((void**)&p_el,    g_el);
    cudaGetSymbolAddress((void**)&p_er,    g_er);
    cudaGetSymbolAddress((void**)&p_att,   g_att);
    cudaGetSymbolAddress((void**)&p_x1,    g_x1);
    cudaGetSymbolAddress((void**)&p_h2,    g_h2);
    cudaGetSymbolAddress((void**)&p_el2,   g_el2);
    cudaGetSymbolAddress((void**)&p_er2,   g_er2);
    cudaGetSymbolAddress((void**)&p_att2,  g_att2);
    cudaGetSymbolAddress((void**)&p_x2,    g_x2);

    static bool attr_set = false;
    if (!attr_set) {
        cudaFuncSetAttribute(tgemm_kernel, cudaFuncAttributeMaxDynamicSharedMemorySize, TGEMM_SMEM);
        attr_set = true;
    }

    const int M = BB * NN;

    // 1. group pooling + index_group
    group_pool_kernel<<<BB, 256>>>();

    // 2. xw = x_off @ Wg_w + Wg_b      (8192 x 1024 x 768)
    tgemm_kernel<<<dim3(NFEAT / 128, M / 128, 1), 256, TGEMM_SMEM>>>(
        p_xoff, -1, 0, FIN_, nullptr, I_WGW, 0, NFEAT,
        p_xw, 0, 0, 1, NFEAT, nullptr, I_WGB, 0, FIN_, 0);

    // 3. h[hh] = xw @ hW_w[hh] + hW_b[hh]   (8 x 8192 x 512 x 1024)
    tgemm_kernel<<<dim3(NHID / 128, M / 128, NHEADS), 256, TGEMM_SMEM>>>(
        p_xw, -1, 0, NFEAT, nullptr, I_HWW, (long)NFEAT * NHID, NHID,
        p_h, (long)M * NHID, 0, NHEADS, NHID, nullptr, I_HWB, NHID, NFEAT, 0);

    // 4. el / er dots
    {
        int nrows = NHEADS * M;
        int nthreads = nrows * 32;
        dots_kernel<<<(nthreads + 255) / 256, 256>>>(p_h, I_HAW, p_el, p_er, nrows, M, NHID);
    }

    // 5. att = softmax(lrelu(el_i + er_j + b), adj-masked)
    {
        int Z = NHEADS * BB;
        att_kernel<<<(Z * NN * 32 + 255) / 256, 256>>>(p_el, p_er, I_HAB, 1, p_att, Z);
    }

    // 6. x1 = elu(att @ h) scattered into (B,N,H*NHID)   (512 x 128 x 512 x 128)
    tgemm_kernel<<<dim3(NHID / 128, NN / 128, NHEADS * BB), 256, TGEMM_SMEM>>>(
        p_att, -1, (long)NN * NN, NN, p_h, -1, (long)NN * NHID, NHID,
        p_x1, (long)NN * NHEADS * NHID, NHID, BB, NHEADS * NHID,
        nullptr, -1, 0, NN, 1);

    // 7. h2 = x1 @ oW_w + oW_b        (8192 x 512 x 4096)
    tgemm_kernel<<<dim3(NCLASS / 128, M / 128, 1), 256, TGEMM_SMEM>>>(
        p_x1, -1, 0, NHEADS * NHID, nullptr, I_OWW, 0, NCLASS,
        p_h2, 0, 0, 1, NCLASS, nullptr, I_OWB, 0, NHEADS * NHID, 0);

    // 8. el2 / er2 dots
    {
        int nthreads = M * 32;
        dots_kernel<<<(nthreads + 255) / 256, 256>>>(p_h2, I_OAW, p_el2, p_er2, M, M, NCLASS);
    }

    // 9. att2
    att_kernel<<<(BB * NN * 32 + 255) / 256, 256>>>(p_el2, p_er2, I_OAB, 0, p_att2, BB);

    // 10. x2 = elu(att2 @ h2)   (64 x 128 x 512 x 128)
    tgemm_kernel<<<dim3(NCLASS / 128, NN / 128, BB), 256, TGEMM_SMEM>>>(
        p_att2, -1, (long)NN * NN, NN, p_h2, -1, (long)NN * NCLASS, NCLASS,
        p_x2, (long)NN * NCLASS, 0, BB, NCLASS, nullptr, -1, 0, NN, 1);

    // 11. logits
    logits_kernel<<<(M * 32 + 255) / 256, 256>>>();

    // 12. scores + stable rank + scatter
    score_fix_kernel<<<BB, 128>>>();

    // 13. expand -> output
    expand_kernel<<<BB, 128>>>(out);
}

// round 10
// speedup vs baseline: 2.9851x; 1.1052x over previous
#include <cuda_runtime.h>
#include <math.h>
#include <stdint.h>

#define BB 64
#define NN 128
#define FIN_ 768
#define NFEAT 1024
#define NHID 512
#define NHEADS 8
#define NCLASS 512
#define ALPHA_ 0.2f
#define NEG_E_ (-9e15f)
#define NEG_S_ (-9e10f)

enum { I_X=0, I_TAG, I_OFFS, I_AMASK, I_ADJ, I_WGW, I_WGB, I_HWW, I_HWB,
       I_HAW, I_HAB, I_OWW, I_OWB, I_OAW, I_OAB, I_FINW, I_FINB };
__device__ const void* g_inp[17];
#define IN_F(i) ((const float*)g_inp[i])

__device__ float g_xoff[BB*NN*FIN_];
__device__ float g_h   [NHEADS*BB*NN*NHID];
__device__ float g_el  [NHEADS*BB*NN];
__device__ float g_er  [NHEADS*BB*NN];
__device__ float g_att [NHEADS*BB*NN*NN];
__device__ float g_x1  [BB*NN*NHEADS*NHID];
__device__ float g_h2  [BB*NN*NCLASS];
__device__ float g_el2 [BB*NN];
__device__ float g_er2 [BB*NN];
__device__ float g_att2[BB*NN*NN];
__device__ float g_x2  [BB*NN*NCLASS];
__device__ float g_logits[BB*NN];
__device__ int   g_ig  [BB*NN*2];
__device__ int   g_fix [BB*NN*2];
__device__ float g_Wc  [NHEADS*FIN_*NHID];   // combined Wg@hW per head
__device__ float g_cb  [NHEADS*NHID];        // combined bias

struct InPack { const void* p[17]; int s[17]; int n; };

__global__ void classify_kernel(InPack pk) {
    int lane = threadIdx.x;
    __shared__ int bin_idx[4]; __shared__ float bin_sum[4]; __shared__ int n_bin;
    if (lane == 0) n_bin = 0;
    __syncwarp();
    for (int i = 0; i < pk.n && i < 17; i++) {
        int sz = pk.s[i];
        const float* f = (const float*)pk.p[i];
        int target = -1;
        if      (sz == BB*NN*FIN_)         target = I_X;
        else if (sz == BB*NN*2)            target = I_OFFS;
        else if (sz == BB*NN*NN)           target = I_ADJ;
        else if (sz == FIN_*NFEAT)         target = I_WGW;
        else if (sz == NHEADS*NFEAT*NHID)  target = I_HWW;
        else if (sz == NHEADS*NHID*NCLASS) target = I_OWW;
        else if (sz == NHEADS*NHID)        target = I_HWB;
        else if (sz == NHEADS)             target = I_HAB;
        else if (sz == NFEAT) {
            bool nz = false;
            for (int k = lane; k < sz; k += 32) nz |= (f[k] != 0.f);
            target = __any_sync(0xffffffffu, nz) ? I_OAW : I_WGB;
        } else if (sz == NCLASS) {
            bool nz = false;
            for (int k = lane; k < sz; k += 32) nz |= (f[k] != 0.f);
            target = __any_sync(0xffffffffu, nz) ? I_FINW : I_OWB;
        } else if (sz == 1) {
            if (lane == 0) { g_inp[I_OAB] = pk.p[i]; g_inp[I_FINB] = pk.p[i]; }
        } else if (sz == BB*NN) {
            bool frac = false; float sum = 0.f;
            for (int k = lane; k < sz; k += 32) {
                float v = f[k]; frac |= (v != 0.f && v != 1.f); sum += v;
            }
            frac = __any_sync(0xffffffffu, frac);
#pragma unroll
            for (int o = 16; o; o >>= 1) sum += __shfl_xor_sync(0xffffffffu, sum, o);
            if (frac) target = I_HAW;
            else if (lane == 0) { bin_idx[n_bin] = i; bin_sum[n_bin] = sum; n_bin++; }
        }
        if (target >= 0 && lane == 0) g_inp[target] = pk.p[i];
        __syncwarp();
    }
    if (lane == 0) {
        if (n_bin >= 2) {
            int a = bin_idx[0], b = bin_idx[1];
            if (bin_sum[0] >= bin_sum[1]) { g_inp[I_AMASK] = pk.p[a]; g_inp[I_TAG] = pk.p[b]; }
            else                          { g_inp[I_AMASK] = pk.p[b]; g_inp[I_TAG] = pk.p[a]; }
        } else if (n_bin == 1) { g_inp[I_AMASK] = pk.p[bin_idx[0]]; g_inp[I_TAG] = pk.p[bin_idx[0]]; }
    }
}

__device__ __forceinline__ float warpSum(float v) {
#pragma unroll
    for (int o = 16; o; o >>= 1) v += __shfl_xor_sync(0xffffffffu, v, o);
    return v;
}
__device__ __forceinline__ float warpMax(float v) {
#pragma unroll
    for (int o = 16; o; o >>= 1) v = fmaxf(v, __shfl_xor_sync(0xffffffffu, v, o));
    return v;
}
__device__ __forceinline__ float blockSum128(float v) {
    __shared__ float s[4];
    float w = warpSum(v);
    if ((threadIdx.x & 31) == 0) s[threadIdx.x >> 5] = w;
    __syncthreads();
    float r = s[0] + s[1] + s[2] + s[3];
    __syncthreads();
    return r;
}
__device__ __forceinline__ float blockMax128(float v) {
    __shared__ float s[4];
    float w = warpMax(v);
    if ((threadIdx.x & 31) == 0) s[threadIdx.x >> 5] = w;
    __syncthreads();
    float r = fmaxf(fmaxf(s[0], s[1]), fmaxf(s[2], s[3]));
    __syncthreads();
    return r;
}

__global__ void group_pool_kernel() {
    const float* x  = IN_F(I_X);
    const int* offs = (const int*)g_inp[I_OFFS];
    int b = blockIdx.x;
    __shared__ int seg[NN]; __shared__ int cnt[NN+1]; __shared__ int G_s;
    if (threadIdx.x == 0) {
        const int* ob = offs + b*NN*2;
        int fz = 0; bool found = false;
        for (int n = 0; n < NN; n++)
            if (ob[2*n] == 0 && ob[2*n+1] == 0) { fz = n; found = true; break; }
        if (!found) fz = 0;
        int cs = 0;
        for (int g = 0; g <= NN; g++) cnt[g] = 0;
        int ends_local[NN];
        for (int g = 0; g < NN; g++) ends_local[g] = 0;
        for (int n = 0; n < NN; n++) {
            int nxt = (n < NN-1) ? ob[2*(n+1)] : 0;
            int bi = (n < fz && ob[2*n+1] == nxt-1) ? 1 : 0;
            cs += bi; int s = cs - bi;
            seg[n] = s; cnt[s]++;
            if (bi && s < NN) ends_local[s] = n+1;
        }
        G_s = cs;
        int* igb = g_ig + b*NN*2;
        int prev_end = 0;
        for (int g = 0; g < NN; g++) {
            if (g < cs) { igb[2*g] = prev_end; igb[2*g+1] = ends_local[g]; prev_end = ends_local[g]; }
            else        { igb[2*g] = 0; igb[2*g+1] = 0; }
        }
    }
    __syncthreads();
    int G = G_s;
    float* xo = g_xoff + (long)b*NN*FIN_;
    const float* xb = x + (long)b*NN*FIN_;
    for (int f = threadIdx.x; f < FIN_; f += blockDim.x) {
        for (int g = 0; g < NN; g++) xo[g*FIN_+f] = 0.f;
        float acc = 0.f; int cur = seg[0];
        for (int n = 0; n < NN; n++) {
            int s = seg[n];
            if (s != cur) {
                if (cur < G) xo[cur*FIN_+f] = acc / (float)max(cnt[cur],1);
                acc = 0.f; cur = s;
            }
            acc += xb[n*FIN_+f];
        }
        if (cur < G) xo[cur*FIN_+f] = acc / (float)max(cnt[cur],1);
    }
}

// combined bias: cb[h][n] = sum_k Wg_b[k]*hW[h][k][n] + hW_b[h][n]
__global__ void cbias_kernel() {
    const float* wgb = IN_F(I_WGB);
    const float* hw  = IN_F(I_HWW);
    const float* hwb = IN_F(I_HWB);
    int gw = (blockIdx.x * blockDim.x + threadIdx.x) >> 5;   // 0..NHEADS*NHID-1
    if (gw >= NHEADS*NHID) return;
    int lane = threadIdx.x & 31;
    int hh = gw / NHID, n = gw % NHID;
    const float* col = hw + (long)hh*NFEAT*NHID + n;
    float a = 0.f;
    for (int k = lane; k < NFEAT; k += 32) a = fmaf(wgb[k], col[(long)k*NHID], a);
    a = warpSum(a);
    if (lane == 0) g_cb[gw] = a + hwb[gw];
}

// ---- mma.sync tf32 GEMM (round-7 verbatim) ----
__device__ __forceinline__ void cp_async16(uint32_t dst, const void* src) {
    asm volatile("cp.async.cg.shared.global [%0], [%1], 16;\n" :: "r"(dst), "l"(src));
}
__device__ __forceinline__ void cp_commit() { asm volatile("cp.async.commit_group;\n"); }
template<int N> __device__ __forceinline__ void cp_wait() {
    asm volatile("cp.async.wait_group %0;\n" :: "n"(N));
}
__device__ __forceinline__ void ldsm_x4(uint32_t* r, uint32_t saddr) {
    asm volatile("ldmatrix.sync.aligned.m8n8.x4.shared.b16 {%0,%1,%2,%3}, [%4];\n"
                 : "=r"(r[0]), "=r"(r[1]), "=r"(r[2]), "=r"(r[3]) : "r"(saddr));
}
__device__ __forceinline__ void mma_tf32(float* d, const uint32_t* a, const uint32_t* b) {
    asm volatile(
        "mma.sync.aligned.m16n8k8.row.col.f32.tf32.tf32.f32 "
        "{%0,%1,%2,%3}, {%4,%5,%6,%7}, {%8,%9}, {%0,%1,%2,%3};\n"
        : "+f"(d[0]), "+f"(d[1]), "+f"(d[2]), "+f"(d[3])
        : "r"(a[0]), "r"(a[1]), "r"(a[2]), "r"(a[3]), "r"(b[0]), "r"(b[1]));
}

#define ASTR 20
#define BSTR 132
#define STAGES 3
#define A_U32 (128 * ASTR)
#define B_U32 (16 * BSTR)
#define STAGE_U32 (A_U32 + B_U32)
#define TGEMM_SMEM (STAGES * STAGE_U32 * 4)

extern __shared__ uint32_t sm_dyn[];

__global__ void __launch_bounds__(256, 2)
tgemm_kernel(const float* Ap, int Ai, long sAz, int lda,
             const float* Bp, int Bi, long sBz, int ldb,
             float* C, long sCz1, long sCz2, int zdiv, int ldc,
             const float* biasp, int biasi, int sBiasz,
             int K, int act) {
    const float* A  = (Ai    >= 0) ? IN_F(Ai)    : Ap;
    const float* Bm = (Bi    >= 0) ? IN_F(Bi)    : Bp;
    const float* bp = (biasi >= 0) ? IN_F(biasi) : biasp;

    int z = blockIdx.z;
    A  += (long)z * sAz;
    Bm += (long)z * sBz;
    C  += (long)(z % zdiv) * sCz1 + (long)(z / zdiv) * sCz2;
    if (bp) bp += (long)z * sBiasz;

    int tid  = threadIdx.x;
    int wid  = tid >> 5;
    int lane = tid & 31;
    int gr = lane >> 2, gc = lane & 3;
    int wm = (wid & 1) << 6;
    int wn = (wid >> 1) << 5;
    int row0 = blockIdx.y << 7, col0 = blockIdx.x << 7;

    uint32_t smem_base = (uint32_t)__cvta_generic_to_shared(sm_dyn);

    int ar = tid & 127;
    int ac0 = (tid >> 7) << 2;
    int br = tid >> 4;
    int bc0 = (tid & 15) << 2;
    const char* Abase = (const char*)(A + (long)(row0 + ar) * lda);
    const char* Bbase = (const char*)(Bm + (long)br * ldb + col0);

    int lrow = lane & 15;
    int lcol = (lane >> 4) << 2;

    float acc[4][4][4];
#pragma unroll
    for (int i = 0; i < 4; i++)
#pragma unroll
        for (int j = 0; j < 4; j++)
#pragma unroll
            for (int q = 0; q < 4; q++) acc[i][j][q] = 0.f;

    int nt = K >> 4;

    auto load_tile = [&](int t, int s) {
        uint32_t abuf = smem_base + (s * STAGE_U32) * 4;
        uint32_t bbuf = abuf + A_U32 * 4;
        const char* ag = Abase + (size_t)t * 64;
        cp_async16(abuf + (ar * ASTR + ac0) * 4,        ag + ac0 * 4);
        cp_async16(abuf + (ar * ASTR + ac0 + 8) * 4,    ag + (ac0 + 8) * 4);
        const char* bg = Bbase + (size_t)t * 16 * ldb * 4;
        cp_async16(bbuf + (br * BSTR + bc0) * 4,        bg + bc0 * 4);
        cp_async16(bbuf + (br * BSTR + bc0 + 64) * 4,   bg + (bc0 + 64) * 4);
    };

    load_tile(0, 0); cp_commit();
    if (nt > 1) load_tile(1, 1);
    cp_commit();

    for (int t = 0; t < nt; t++) {
        cp_wait<1>();
        __syncthreads();
        if (t + 2 < nt) load_tile(t + 2, (t + 2) % STAGES);
        cp_commit();

        int s = t % STAGES;
        uint32_t abuf = smem_base + (s * STAGE_U32) * 4;
        const uint32_t* bs = sm_dyn + s * STAGE_U32 + A_U32;

#pragma unroll
        for (int kk = 0; kk < 16; kk += 8) {
            uint32_t afr[4][4], bfr[4][2];
#pragma unroll
            for (int ti = 0; ti < 4; ti++) {
                uint32_t addr = abuf + (((wm + (ti << 4) + lrow) * ASTR) + kk + lcol) * 4;
                ldsm_x4(afr[ti], addr);
            }
#pragma unroll
            for (int tj = 0; tj < 4; tj++) {
                int cb = (kk + gc) * BSTR + wn + (tj << 3) + gr;
                bfr[tj][0] = bs[cb];
                bfr[tj][1] = bs[cb + 4 * BSTR];
            }
#pragma unroll
            for (int ti = 0; ti < 4; ti++)
#pragma unroll
                for (int tj = 0; tj < 4; tj++)
                    mma_tf32(acc[ti][tj], afr[ti], bfr[tj]);
        }
    }

#pragma unroll
    for (int ti = 0; ti < 4; ti++) {
        int rg0 = row0 + wm + (ti << 4) + gr;
#pragma unroll
        for (int tj = 0; tj < 4; tj++) {
            int cg = col0 + wn + (tj << 3) + (gc << 1);
            float d0 = acc[ti][tj][0], d1 = acc[ti][tj][1];
            float d2 = acc[ti][tj][2], d3 = acc[ti][tj][3];
            if (bp) {
                float b0 = bp[cg], b1 = bp[cg + 1];
                d0 += b0; d1 += b1; d2 += b0; d3 += b1;
            }
            if (act == 1) {
                d0 = d0 > 0.f ? d0 : expm1f(d0);
                d1 = d1 > 0.f ? d1 : expm1f(d1);
                d2 = d2 > 0.f ? d2 : expm1f(d2);
                d3 = d3 > 0.f ? d3 : expm1f(d3);
            }
            float2 v0 = {d0, d1}, v1 = {d2, d3};
            *(float2*)(C + (long)rg0 * ldc + cg) = v0;
            *(float2*)(C + (long)(rg0 + 8) * ldc + cg) = v1;
        }
    }
}

__global__ void dots_kernel(const float* __restrict__ rows, int wIdx,
                            float* __restrict__ el, float* __restrict__ er,
                            int nrows, int rows_per_head, int width) {
    const float* w = IN_F(wIdx);
    int gw = (blockIdx.x * blockDim.x + threadIdx.x) >> 5;
    if (gw >= nrows) return;
    int lane = threadIdx.x & 31;
    int hh = gw / rows_per_head;
    const float* row = rows + (long)gw*width;
    const float* wl = w + (long)hh*2*width;
    const float* wr = wl + width;
    float a = 0.f, c = 0.f;
    for (int k = lane; k < width; k += 32) {
        float v = row[k];
        a = fmaf(v, wl[k], a); c = fmaf(v, wr[k], c);
    }
    a = warpSum(a); c = warpSum(c);
    if (lane == 0) { el[gw] = a; er[gw] = c; }
}

__global__ void att_kernel(const float* __restrict__ el, const float* __restrict__ er,
                           int biasIdx, int bias_per_head, float* __restrict__ att, int Z) {
    int gw = (blockIdx.x * blockDim.x + threadIdx.x) >> 5;
    if (gw >= Z*NN) return;
    int lane = threadIdx.x & 31;
    int z = gw >> 7, i = gw & 127;
    int b = z % BB, hh = z / BB;
    float bb = IN_F(biasIdx)[bias_per_head ? hh : 0];
    float eli = el[z*NN+i];
    const float* adjrow = IN_F(I_ADJ) + ((long)b*NN+i)*NN;
    const float* err = er + z*NN;
    float v[4]; float mx = -INFINITY;
#pragma unroll
    for (int q = 0; q < 4; q++) {
        int j = lane + (q << 5);
        float e = eli + err[j] + bb;
        e = (e >= 0.f) ? e : ALPHA_*e;
        v[q] = (adjrow[j] > 0.f) ? e : NEG_E_;
        mx = fmaxf(mx, v[q]);
    }
    mx = warpMax(mx);
    float sum = 0.f;
#pragma unroll
    for (int q = 0; q < 4; q++) { v[q] = expf(v[q]-mx); sum += v[q]; }
    sum = warpSum(sum);
    float inv = 1.f / sum;
    float* arow = att + ((long)z*NN+i)*NN;
#pragma unroll
    for (int q = 0; q < 4; q++) arow[lane+(q<<5)] = v[q]*inv;
}

__global__ void logits_kernel() {
    const float* fin_w = IN_F(I_FINW);
    const float* fin_b = IN_F(I_FINB);
    int gw = (blockIdx.x * blockDim.x + threadIdx.x) >> 5;
    if (gw >= BB*NN) return;
    int lane = threadIdx.x & 31;
    const float* row = g_x2 + (long)gw*NCLASS;
    float a = 0.f;
    for (int k = lane; k < NCLASS; k += 32) a = fmaf(row[k], fin_w[k], a);
    a = warpSum(a);
    if (lane == 0) g_logits[gw] = a + fin_b[0];
}

__global__ void score_fix_kernel() {
    const float* tag   = IN_F(I_TAG);
    const float* amask = IN_F(I_AMASK);
    int b = blockIdx.x, j = threadIdx.x;
    float m = (tag[b*NN+j] > 0.f) ? amask[b*NN+j] : 0.f;
    float lg = g_logits[b*NN+j];
    float v1 = (m > 0.f) ? lg*m : NEG_S_;
    float mx1 = blockMax128(v1);
    float e1 = expf(v1-mx1);
    float d1 = blockSum128(e1);
    float s1 = e1/d1;
    float summary = blockSum128(m);
    float v2 = (m > 0.f) ? ((float)(NN-j))/summary*m : NEG_S_;
    float mx2 = blockMax128(v2);
    float e2 = expf(v2-mx2);
    float d2 = blockSum128(e2);
    float s2 = e2/d2;
    __shared__ float sc[NN];
    sc[j] = s1+s2;
    __syncthreads();
    float me = sc[j];
    int rank = 0;
    for (int k = 0; k < NN; k++) {
        float o = sc[k];
        rank += (o > me) || (o == me && k < j);
    }
    g_fix[(b*NN+j)*2+0] = g_ig[(b*NN+rank)*2+0];
    g_fix[(b*NN+j)*2+1] = g_ig[(b*NN+rank)*2+1];
}

__global__ void expand_kernel(float* __restrict__ out) {
    int b = blockIdx.x, l = threadIdx.x;
    __shared__ int f0[NN], f1[NN], csum[NN];
    __shared__ int fzs, total;
    f0[l] = g_fix[(b*NN+l)*2+0];
    f1[l] = g_fix[(b*NN+l)*2+1];
    __syncthreads();
    if (l == 0) {
        int fz = 0; bool found = false;
        for (int n = 0; n < NN; n++)
            if (f0[n] == 0 && f1[n] == 0) { fz = n; found = true; break; }
        if (!found) fz = 0;
        int cs = 0;
        for (int n = 0; n < NN; n++) {
            int len = (n < fz) ? (f1[n]-f0[n]) : 0;
            cs += len; csum[n] = cs;
        }
        fzs = fz; total = cs;
    }
    __syncthreads();
    int k = 0;
    for (int n = 0; n < NN; n++) k += (csum[n] <= l);
    if (k > NN-1) k = NN-1;
    int lenk = (k < fzs) ? (f1[k]-f0[k]) : 0;
    int excl = csum[k]-lenk;
    int val = f0[k] + (l-excl);
    out[b*NN+l] = (float)((l < total) ? val : l);
}

extern "C" void kernel_launch(void* const* d_in, const int* in_sizes, int n_in,
                              void* d_out, int) {
    float* out = (float*)d_out;
    InPack pk;
    int nn = n_in < 17 ? n_in : 17;
    for (int i = 0; i < 17; i++) {
        pk.p[i] = (i < nn) ? d_in[i] : nullptr;
        pk.s[i] = (i < nn) ? in_sizes[i] : 0;
    }
    pk.n = nn;
    classify_kernel<<<1, 32>>>(pk);

    float *p_xoff,*p_h,*p_el,*p_er,*p_att,*p_x1,*p_h2,*p_el2,*p_er2,*p_att2,*p_x2,*p_Wc,*p_cb;
    cudaGetSymbolAddress((void**)&p_xoff, g_xoff);
    cudaGetSymbolAddress((void**)&p_h,    g_h);
    cudaGetSymbolAddress((void**)&p_el,   g_el);
    cudaGetSymbolAddress((void**)&p_er,   g_er);
    cudaGetSymbolAddress((void**)&p_att,  g_att);
    cudaGetSymbolAddress((void**)&p_x1,   g_x1);
    cudaGetSymbolAddress((void**)&p_h2,   g_h2);
    cudaGetSymbolAddress((void**)&p_el2,  g_el2);
    cudaGetSymbolAddress((void**)&p_er2,  g_er2);
    cudaGetSymbolAddress((void**)&p_att2, g_att2);
    cudaGetSymbolAddress((void**)&p_x2,   g_x2);
    cudaGetSymbolAddress((void**)&p_Wc,   g_Wc);
    cudaGetSymbolAddress((void**)&p_cb,   g_cb);

    static bool attr_set = false;
    if (!attr_set) {
        cudaFuncSetAttribute(tgemm_kernel, cudaFuncAttributeMaxDynamicSharedMemorySize, TGEMM_SMEM);
        attr_set = true;
    }

    const int M = BB*NN;

    // 1. group pooling + index_group
    group_pool_kernel<<<BB, 256>>>();

    // 1b. Wc[hh] = Wg @ hW[hh]   (8 x 768 x 512 x 1024)
    tgemm_kernel<<<dim3(NHID/128, FIN_/128, NHEADS), 256, TGEMM_SMEM>>>(
        nullptr, I_WGW, 0, NFEAT, nullptr, I_HWW, (long)NFEAT*NHID, NHID,
        p_Wc, (long)FIN_*NHID, 0, NHEADS, NHID, nullptr, -1, 0, NFEAT, 0);

    // 1c. cb[hh] = Wg_b @ hW[hh] + hW_b[hh]
    cbias_kernel<<<(NHEADS*NHID*32 + 255)/256, 256>>>();

    // 2. h[hh] = x_off @ Wc[hh] + cb[hh]   (8 x 8192 x 512 x 768)
    tgemm_kernel<<<dim3(NHID/128, M/128, NHEADS), 256, TGEMM_SMEM>>>(
        p_xoff, -1, 0, FIN_, p_Wc, -1, (long)FIN_*NHID, NHID,
        p_h, (long)M*NHID, 0, NHEADS, NHID, p_cb, -1, NHID, FIN_, 0);

    // 3. el / er dots
    {
        int nrows = NHEADS*M;
        dots_kernel<<<(nrows*32 + 255)/256, 256>>>(p_h, I_HAW, p_el, p_er, nrows, M, NHID);
    }

    // 4. att softmax
    {
        int Z = NHEADS*BB;
        att_kernel<<<(Z*NN*32 + 255)/256, 256>>>(p_el, p_er, I_HAB, 1, p_att, Z);
    }

    // 5. x1 = elu(att @ h)   (512 z: 128 x 512 x 128)
    tgemm_kernel<<<dim3(NHID/128, NN/128, NHEADS*BB), 256, TGEMM_SMEM>>>(
        p_att, -1, (long)NN*NN, NN, p_h, -1, (long)NN*NHID, NHID,
        p_x1, (long)NN*NHEADS*NHID, NHID, BB, NHEADS*NHID, nullptr, -1, 0, NN, 1);

    // 6. h2 = x1 @ oW + b   (8192 x 512 x 4096)
    tgemm_kernel<<<dim3(NCLASS/128, M/128, 1), 256, TGEMM_SMEM>>>(
        p_x1, -1, 0, NHEADS*NHID, nullptr, I_OWW, 0, NCLASS,
        p_h2, 0, 0, 1, NCLASS, nullptr, I_OWB, 0, NHEADS*NHID, 0);

    // 7. el2 / er2 dots
    dots_kernel<<<(M*32 + 255)/256, 256>>>(p_h2, I_OAW, p_el2, p_er2, M, M, NCLASS);

    // 8. att2
    att_kernel<<<(BB*NN*32 + 255)/256, 256>>>(p_el2, p_er2, I_OAB, 0, p_att2, BB);

    // 9. x2 = elu(att2 @ h2)   (64 z: 128 x 512 x 128)
    tgemm_kernel<<<dim3(NCLASS/128, NN/128, BB), 256, TGEMM_SMEM>>>(
        p_att2, -1, (long)NN*NN, NN, p_h2, -1, (long)NN*NCLASS, NCLASS,
        p_x2, (long)NN*NCLASS, 0, BB, NCLASS, nullptr, -1, 0, NN, 1);

    // 10. logits, scores, expand
    logits_kernel<<<(M*32 + 255)/256, 256>>>();
    score_fix_kernel<<<BB, 128>>>();
    expand_kernel<<<BB, 128>>>(out);
}

// round 11
// speedup vs baseline: 3.1680x; 1.0613x over previous
#include <cuda_runtime.h>
#include <math.h>
#include <stdint.h>

#define BB 64
#define NN 128
#define FIN_ 768
#define NFEAT 1024
#define NHID 512
#define NHEADS 8
#define NCLASS 512
#define ALPHA_ 0.2f
#define NEG_E_ (-9e15f)
#define NEG_S_ (-9e10f)

enum { I_X=0, I_TAG, I_OFFS, I_AMASK, I_ADJ, I_WGW, I_WGB, I_HWW, I_HWB,
       I_HAW, I_HAB, I_OWW, I_OWB, I_OAW, I_OAB, I_FINW, I_FINB };
__device__ const void* g_inp[17];
#define IN_F(i) ((const float*)g_inp[i])

__device__ float g_xoff[BB*NN*FIN_];
__device__ float g_h   [NHEADS*BB*NN*NHID];
__device__ float g_el  [NHEADS*BB*NN];
__device__ float g_er  [NHEADS*BB*NN];
__device__ float g_att [NHEADS*BB*NN*NN];
__device__ float g_x1  [BB*NN*NHEADS*NHID];
__device__ float g_h2  [BB*NN*NCLASS];
__device__ float g_el2 [BB*NN];
__device__ float g_er2 [BB*NN];
__device__ float g_att2[BB*NN*NN];
__device__ float g_x2  [BB*NN*NCLASS];
__device__ float g_logits[BB*NN];
__device__ int   g_ig  [BB*NN*2];
__device__ int   g_fix [BB*NN*2];
__device__ float g_Wc  [NHEADS*FIN_*NHID];
__device__ float g_cb  [NHEADS*NHID];

struct InPack { const void* p[17]; int s[17]; int n; };

__global__ void classify_kernel(InPack pk) {
    int lane = threadIdx.x;
    __shared__ int bin_idx[4]; __shared__ float bin_sum[4]; __shared__ int n_bin;
    if (lane == 0) n_bin = 0;
    __syncwarp();
    for (int i = 0; i < pk.n && i < 17; i++) {
        int sz = pk.s[i];
        const float* f = (const float*)pk.p[i];
        int target = -1;
        if      (sz == BB*NN*FIN_)         target = I_X;
        else if (sz == BB*NN*2)            target = I_OFFS;
        else if (sz == BB*NN*NN)           target = I_ADJ;
        else if (sz == FIN_*NFEAT)         target = I_WGW;
        else if (sz == NHEADS*NFEAT*NHID)  target = I_HWW;
        else if (sz == NHEADS*NHID*NCLASS) target = I_OWW;
        else if (sz == NHEADS*NHID)        target = I_HWB;
        else if (sz == NHEADS)             target = I_HAB;
        else if (sz == NFEAT) {
            bool nz = false;
            for (int k = lane; k < sz; k += 32) nz |= (f[k] != 0.f);
            target = __any_sync(0xffffffffu, nz) ? I_OAW : I_WGB;
        } else if (sz == NCLASS) {
            bool nz = false;
            for (int k = lane; k < sz; k += 32) nz |= (f[k] != 0.f);
            target = __any_sync(0xffffffffu, nz) ? I_FINW : I_OWB;
        } else if (sz == 1) {
            if (lane == 0) { g_inp[I_OAB] = pk.p[i]; g_inp[I_FINB] = pk.p[i]; }
        } else if (sz == BB*NN) {
            bool frac = false; float sum = 0.f;
            for (int k = lane; k < sz; k += 32) {
                float v = f[k]; frac |= (v != 0.f && v != 1.f); sum += v;
            }
            frac = __any_sync(0xffffffffu, frac);
#pragma unroll
            for (int o = 16; o; o >>= 1) sum += __shfl_xor_sync(0xffffffffu, sum, o);
            if (frac) target = I_HAW;
            else if (lane == 0) { bin_idx[n_bin] = i; bin_sum[n_bin] = sum; n_bin++; }
        }
        if (target >= 0 && lane == 0) g_inp[target] = pk.p[i];
        __syncwarp();
    }
    if (lane == 0) {
        if (n_bin >= 2) {
            int a = bin_idx[0], b = bin_idx[1];
            if (bin_sum[0] >= bin_sum[1]) { g_inp[I_AMASK] = pk.p[a]; g_inp[I_TAG] = pk.p[b]; }
            else                          { g_inp[I_AMASK] = pk.p[b]; g_inp[I_TAG] = pk.p[a]; }
        } else if (n_bin == 1) { g_inp[I_AMASK] = pk.p[bin_idx[0]]; g_inp[I_TAG] = pk.p[bin_idx[0]]; }
    }
}

__device__ __forceinline__ float warpSum(float v) {
#pragma unroll
    for (int o = 16; o; o >>= 1) v += __shfl_xor_sync(0xffffffffu, v, o);
    return v;
}
__device__ __forceinline__ float warpMax(float v) {
#pragma unroll
    for (int o = 16; o; o >>= 1) v = fmaxf(v, __shfl_xor_sync(0xffffffffu, v, o));
    return v;
}
__device__ __forceinline__ float blockSum128(float v) {
    __shared__ float s[4];
    float w = warpSum(v);
    if ((threadIdx.x & 31) == 0) s[threadIdx.x >> 5] = w;
    __syncthreads();
    float r = s[0] + s[1] + s[2] + s[3];
    __syncthreads();
    return r;
}
__device__ __forceinline__ float blockMax128(float v) {
    __shared__ float s[4];
    float w = warpMax(v);
    if ((threadIdx.x & 31) == 0) s[threadIdx.x >> 5] = w;
    __syncthreads();
    float r = fmaxf(fmaxf(s[0], s[1]), fmaxf(s[2], s[3]));
    __syncthreads();
    return r;
}

__global__ void group_pool_kernel() {
    const float* x  = IN_F(I_X);
    const int* offs = (const int*)g_inp[I_OFFS];
    int b = blockIdx.x;
    __shared__ int seg[NN]; __shared__ int cnt[NN+1]; __shared__ int G_s;
    if (threadIdx.x == 0) {
        const int* ob = offs + b*NN*2;
        int fz = 0; bool found = false;
        for (int n = 0; n < NN; n++)
            if (ob[2*n] == 0 && ob[2*n+1] == 0) { fz = n; found = true; break; }
        if (!found) fz = 0;
        int cs = 0;
        for (int g = 0; g <= NN; g++) cnt[g] = 0;
        int ends_local[NN];
        for (int g = 0; g < NN; g++) ends_local[g] = 0;
        for (int n = 0; n < NN; n++) {
            int nxt = (n < NN-1) ? ob[2*(n+1)] : 0;
            int bi = (n < fz && ob[2*n+1] == nxt-1) ? 1 : 0;
            cs += bi; int s = cs - bi;
            seg[n] = s; cnt[s]++;
            if (bi && s < NN) ends_local[s] = n+1;
        }
        G_s = cs;
        int* igb = g_ig + b*NN*2;
        int prev_end = 0;
        for (int g = 0; g < NN; g++) {
            if (g < cs) { igb[2*g] = prev_end; igb[2*g+1] = ends_local[g]; prev_end = ends_local[g]; }
            else        { igb[2*g] = 0; igb[2*g+1] = 0; }
        }
    }
    __syncthreads();
    int G = G_s;
    float* xo = g_xoff + (long)b*NN*FIN_;
    const float* xb = x + (long)b*NN*FIN_;
    for (int f = threadIdx.x; f < FIN_; f += blockDim.x) {
        for (int g = 0; g < NN; g++) xo[g*FIN_+f] = 0.f;
        float acc = 0.f; int cur = seg[0];
        for (int n = 0; n < NN; n++) {
            int s = seg[n];
            if (s != cur) {
                if (cur < G) xo[cur*FIN_+f] = acc / (float)max(cnt[cur],1);
                acc = 0.f; cur = s;
            }
            acc += xb[n*FIN_+f];
        }
        if (cur < G) xo[cur*FIN_+f] = acc / (float)max(cnt[cur],1);
    }
}

// coalesced cbias: one thread per (h,n), k-loop with coalesced rows
__global__ void cbias_kernel() {
    const float* wgb = IN_F(I_WGB);
    const float* hw  = IN_F(I_HWW);
    const float* hwb = IN_F(I_HWB);
    int g = blockIdx.x * blockDim.x + threadIdx.x;   // 0..NHEADS*NHID-1
    if (g >= NHEADS*NHID) return;
    int hh = g / NHID, n = g % NHID;
    const float* base = hw + (long)hh*NFEAT*NHID + n;
    float a = 0.f;
#pragma unroll 4
    for (int k = 0; k < NFEAT; k++) a = fmaf(wgb[k], base[(long)k*NHID], a);
    g_cb[g] = a + hwb[g];
}

// ---- mma.sync tf32 GEMM, 4-stage cp.async pipeline ----
__device__ __forceinline__ void cp_async16(uint32_t dst, const void* src) {
    asm volatile("cp.async.cg.shared.global [%0], [%1], 16;\n" :: "r"(dst), "l"(src));
}
__device__ __forceinline__ void cp_commit() { asm volatile("cp.async.commit_group;\n"); }
template<int N> __device__ __forceinline__ void cp_wait() {
    asm volatile("cp.async.wait_group %0;\n" :: "n"(N));
}
__device__ __forceinline__ void ldsm_x4(uint32_t* r, uint32_t saddr) {
    asm volatile("ldmatrix.sync.aligned.m8n8.x4.shared.b16 {%0,%1,%2,%3}, [%4];\n"
                 : "=r"(r[0]), "=r"(r[1]), "=r"(r[2]), "=r"(r[3]) : "r"(saddr));
}
__device__ __forceinline__ void mma_tf32(float* d, const uint32_t* a, const uint32_t* b) {
    asm volatile(
        "mma.sync.aligned.m16n8k8.row.col.f32.tf32.tf32.f32 "
        "{%0,%1,%2,%3}, {%4,%5,%6,%7}, {%8,%9}, {%0,%1,%2,%3};\n"
        : "+f"(d[0]), "+f"(d[1]), "+f"(d[2]), "+f"(d[3])
        : "r"(a[0]), "r"(a[1]), "r"(a[2]), "r"(a[3]), "r"(b[0]), "r"(b[1]));
}

#define ASTR 20
#define BSTR 132
#define STAGES 4
#define A_U32 (128 * ASTR)
#define B_U32 (16 * BSTR)
#define STAGE_U32 (A_U32 + B_U32)
#define TGEMM_SMEM (STAGES * STAGE_U32 * 4)

extern __shared__ uint32_t sm_dyn[];

__global__ void __launch_bounds__(256, 2)
tgemm_kernel(const float* Ap, int Ai, long sAz, int lda,
             const float* Bp, int Bi, long sBz, int ldb,
             float* C, long sCz1, long sCz2, int zdiv, int ldc,
             const float* biasp, int biasi, int sBiasz,
             int K, int act) {
    const float* A  = (Ai    >= 0) ? IN_F(Ai)    : Ap;
    const float* Bm = (Bi    >= 0) ? IN_F(Bi)    : Bp;
    const float* bp = (biasi >= 0) ? IN_F(biasi) : biasp;

    int z = blockIdx.z;
    A  += (long)z * sAz;
    Bm += (long)z * sBz;
    C  += (long)(z % zdiv) * sCz1 + (long)(z / zdiv) * sCz2;
    if (bp) bp += (long)z * sBiasz;

    int tid  = threadIdx.x;
    int wid  = tid >> 5;
    int lane = tid & 31;
    int gr = lane >> 2, gc = lane & 3;
    int wm = (wid & 1) << 6;
    int wn = (wid >> 1) << 5;
    int row0 = blockIdx.y << 7, col0 = blockIdx.x << 7;

    uint32_t smem_base = (uint32_t)__cvta_generic_to_shared(sm_dyn);

    int ar = tid & 127;
    int ac0 = (tid >> 7) << 2;
    int br = tid >> 4;
    int bc0 = (tid & 15) << 2;
    const char* Abase = (const char*)(A + (long)(row0 + ar) * lda);
    const char* Bbase = (const char*)(Bm + (long)br * ldb + col0);

    int lrow = lane & 15;
    int lcol = (lane >> 4) << 2;

    float acc[4][4][4];
#pragma unroll
    for (int i = 0; i < 4; i++)
#pragma unroll
        for (int j = 0; j < 4; j++)
#pragma unroll
            for (int q = 0; q < 4; q++) acc[i][j][q] = 0.f;

    int nt = K >> 4;

    auto load_tile = [&](int t, int s) {
        uint32_t abuf = smem_base + (s * STAGE_U32) * 4;
        uint32_t bbuf = abuf + A_U32 * 4;
        const char* ag = Abase + (size_t)t * 64;
        cp_async16(abuf + (ar * ASTR + ac0) * 4,        ag + ac0 * 4);
        cp_async16(abuf + (ar * ASTR + ac0 + 8) * 4,    ag + (ac0 + 8) * 4);
        const char* bg = Bbase + (size_t)t * 16 * ldb * 4;
        cp_async16(bbuf + (br * BSTR + bc0) * 4,        bg + bc0 * 4);
        cp_async16(bbuf + (br * BSTR + bc0 + 64) * 4,   bg + (bc0 + 64) * 4);
    };

    // prologue: 3 tiles in flight
    load_tile(0, 0); cp_commit();
    if (nt > 1) load_tile(1, 1);
    cp_commit();
    if (nt > 2) load_tile(2, 2);
    cp_commit();

    for (int t = 0; t < nt; t++) {
        cp_wait<2>();
        __syncthreads();
        if (t + 3 < nt) load_tile(t + 3, (t + 3) % STAGES);
        cp_commit();

        int s = t % STAGES;
        uint32_t abuf = smem_base + (s * STAGE_U32) * 4;
        const uint32_t* bs = sm_dyn + s * STAGE_U32 + A_U32;

#pragma unroll
        for (int kk = 0; kk < 16; kk += 8) {
            uint32_t afr[4][4], bfr[4][2];
#pragma unroll
            for (int ti = 0; ti < 4; ti++) {
                uint32_t addr = abuf + (((wm + (ti << 4) + lrow) * ASTR) + kk + lcol) * 4;
                ldsm_x4(afr[ti], addr);
            }
#pragma unroll
            for (int tj = 0; tj < 4; tj++) {
                int cb = (kk + gc) * BSTR + wn + (tj << 3) + gr;
                bfr[tj][0] = bs[cb];
                bfr[tj][1] = bs[cb + 4 * BSTR];
            }
#pragma unroll
            for (int ti = 0; ti < 4; ti++)
#pragma unroll
                for (int tj = 0; tj < 4; tj++)
                    mma_tf32(acc[ti][tj], afr[ti], bfr[tj]);
        }
    }

#pragma unroll
    for (int ti = 0; ti < 4; ti++) {
        int rg0 = row0 + wm + (ti << 4) + gr;
#pragma unroll
        for (int tj = 0; tj < 4; tj++) {
            int cg = col0 + wn + (tj << 3) + (gc << 1);
            float d0 = acc[ti][tj][0], d1 = acc[ti][tj][1];
            float d2 = acc[ti][tj][2], d3 = acc[ti][tj][3];
            if (bp) {
                float b0 = bp[cg], b1 = bp[cg + 1];
                d0 += b0; d1 += b1; d2 += b0; d3 += b1;
            }
            if (act == 1) {
                d0 = d0 > 0.f ? d0 : expm1f(d0);
                d1 = d1 > 0.f ? d1 : expm1f(d1);
                d2 = d2 > 0.f ? d2 : expm1f(d2);
                d3 = d3 > 0.f ? d3 : expm1f(d3);
            }
            float2 v0 = {d0, d1}, v1 = {d2, d3};
            *(float2*)(C + (long)rg0 * ldc + cg) = v0;
            *(float2*)(C + (long)(rg0 + 8) * ldc + cg) = v1;
        }
    }
}

__global__ void dots_kernel(const float* __restrict__ rows, int wIdx,
                            float* __restrict__ el, float* __restrict__ er,
                            int nrows, int rows_per_head, int width) {
    const float* w = IN_F(wIdx);
    int gw = (blockIdx.x * blockDim.x + threadIdx.x) >> 5;
    if (gw >= nrows) return;
    int lane = threadIdx.x & 31;
    int hh = gw / rows_per_head;
    const float* row = rows + (long)gw*width;
    const float* wl = w + (long)hh*2*width;
    const float* wr = wl + width;
    float a = 0.f, c = 0.f;
    for (int k = lane; k < width; k += 32) {
        float v = row[k];
        a = fmaf(v, wl[k], a); c = fmaf(v, wr[k], c);
    }
    a = warpSum(a); c = warpSum(c);
    if (lane == 0) { el[gw] = a; er[gw] = c; }
}

__global__ void att_kernel(const float* __restrict__ el, const float* __restrict__ er,
                           int biasIdx, int bias_per_head, float* __restrict__ att, int Z) {
    int gw = (blockIdx.x * blockDim.x + threadIdx.x) >> 5;
    if (gw >= Z*NN) return;
    int lane = threadIdx.x & 31;
    int z = gw >> 7, i = gw & 127;
    int b = z % BB, hh = z / BB;
    float bb = IN_F(biasIdx)[bias_per_head ? hh : 0];
    float eli = el[z*NN+i];
    const float* adjrow = IN_F(I_ADJ) + ((long)b*NN+i)*NN;
    const float* err = er + z*NN;
    float v[4]; float mx = -INFINITY;
#pragma unroll
    for (int q = 0; q < 4; q++) {
        int j = lane + (q << 5);
        float e = eli + err[j] + bb;
        e = (e >= 0.f) ? e : ALPHA_*e;
        v[q] = (adjrow[j] > 0.f) ? e : NEG_E_;
        mx = fmaxf(mx, v[q]);
    }
    mx = warpMax(mx);
    float sum = 0.f;
#pragma unroll
    for (int q = 0; q < 4; q++) { v[q] = expf(v[q]-mx); sum += v[q]; }
    sum = warpSum(sum);
    float inv = 1.f / sum;
    float* arow = att + ((long)z*NN+i)*NN;
#pragma unroll
    for (int q = 0; q < 4; q++) arow[lane+(q<<5)] = v[q]*inv;
}

__global__ void logits_kernel() {
    const float* fin_w = IN_F(I_FINW);
    const float* fin_b = IN_F(I_FINB);
    int gw = (blockIdx.x * blockDim.x + threadIdx.x) >> 5;
    if (gw >= BB*NN) return;
    int lane = threadIdx.x & 31;
    const float* row = g_x2 + (long)gw*NCLASS;
    float a = 0.f;
    for (int k = lane; k < NCLASS; k += 32) a = fmaf(row[k], fin_w[k], a);
    a = warpSum(a);
    if (lane == 0) g_logits[gw] = a + fin_b[0];
}

__global__ void score_fix_kernel() {
    const float* tag   = IN_F(I_TAG);
    const float* amask = IN_F(I_AMASK);
    int b = blockIdx.x, j = threadIdx.x;
    float m = (tag[b*NN+j] > 0.f) ? amask[b*NN+j] : 0.f;
    float lg = g_logits[b*NN+j];
    float v1 = (m > 0.f) ? lg*m : NEG_S_;
    float mx1 = blockMax128(v1);
    float e1 = expf(v1-mx1);
    float d1 = blockSum128(e1);
    float s1 = e1/d1;
    float summary = blockSum128(m);
    float v2 = (m > 0.f) ? ((float)(NN-j))/summary*m : NEG_S_;
    float mx2 = blockMax128(v2);
    float e2 = expf(v2-mx2);
    float d2 = blockSum128(e2);
    float s2 = e2/d2;
    __shared__ float sc[NN];
    sc[j] = s1+s2;
    __syncthreads();
    float me = sc[j];
    int rank = 0;
    for (int k = 0; k < NN; k++) {
        float o = sc[k];
        rank += (o > me) || (o == me && k < j);
    }
    g_fix[(b*NN+j)*2+0] = g_ig[(b*NN+rank)*2+0];
    g_fix[(b*NN+j)*2+1] = g_ig[(b*NN+rank)*2+1];
}

__global__ void expand_kernel(float* __restrict__ out) {
    int b = blockIdx.x, l = threadIdx.x;
    __shared__ int f0[NN], f1[NN], csum[NN];
    __shared__ int fzs, total;
    f0[l] = g_fix[(b*NN+l)*2+0];
    f1[l] = g_fix[(b*NN+l)*2+1];
    __syncthreads();
    if (l == 0) {
        int fz = 0; bool found = false;
        for (int n = 0; n < NN; n++)
            if (f0[n] == 0 && f1[n] == 0) { fz = n; found = true; break; }
        if (!found) fz = 0;
        int cs = 0;
        for (int n = 0; n < NN; n++) {
            int len = (n < fz) ? (f1[n]-f0[n]) : 0;
            cs += len; csum[n] = cs;
        }
        fzs = fz; total = cs;
    }
    __syncthreads();
    int k = 0;
    for (int n = 0; n < NN; n++) k += (csum[n] <= l);
    if (k > NN-1) k = NN-1;
    int lenk = (k < fzs) ? (f1[k]-f0[k]) : 0;
    int excl = csum[k]-lenk;
    int val = f0[k] + (l-excl);
    out[b*NN+l] = (float)((l < total) ? val : l);
}

extern "C" void kernel_launch(void* const* d_in, const int* in_sizes, int n_in,
                              void* d_out, int) {
    float* out = (float*)d_out;
    InPack pk;
    int nn = n_in < 17 ? n_in : 17;
    for (int i = 0; i < 17; i++) {
        pk.p[i] = (i < nn) ? d_in[i] : nullptr;
        pk.s[i] = (i < nn) ? in_sizes[i] : 0;
    }
    pk.n = nn;

    float *p_xoff,*p_h,*p_el,*p_er,*p_att,*p_x1,*p_h2,*p_el2,*p_er2,*p_att2,*p_x2,*p_Wc,*p_cb;
    cudaGetSymbolAddress((void**)&p_xoff, g_xoff);
    cudaGetSymbolAddress((void**)&p_h,    g_h);
    cudaGetSymbolAddress((void**)&p_el,   g_el);
    cudaGetSymbolAddress((void**)&p_er,   g_er);
    cudaGetSymbolAddress((void**)&p_att,  g_att);
    cudaGetSymbolAddress((void**)&p_x1,   g_x1);
    cudaGetSymbolAddress((void**)&p_h2,   g_h2);
    cudaGetSymbolAddress((void**)&p_el2,  g_el2);
    cudaGetSymbolAddress((void**)&p_er2,  g_er2);
    cudaGetSymbolAddress((void**)&p_att2, g_att2);
    cudaGetSymbolAddress((void**)&p_x2,   g_x2);
    cudaGetSymbolAddress((void**)&p_Wc,   g_Wc);
    cudaGetSymbolAddress((void**)&p_cb,   g_cb);

    static bool init_done = false;
    static cudaStream_t s2;
    static cudaEvent_t evFork, evJoin;
    if (!init_done) {
        cudaFuncSetAttribute(tgemm_kernel, cudaFuncAttributeMaxDynamicSharedMemorySize, TGEMM_SMEM);
        cudaStreamCreateWithFlags(&s2, cudaStreamNonBlocking);
        cudaEventCreateWithFlags(&evFork, cudaEventDisableTiming);
        cudaEventCreateWithFlags(&evJoin, cudaEventDisableTiming);
        init_done = true;
    }

    const int M = BB*NN;

    classify_kernel<<<1, 32>>>(pk);

    // fork: Wc + cbias on s2, group_pool on main — both depend only on classify
    cudaEventRecord(evFork, 0);
    cudaStreamWaitEvent(s2, evFork, 0);

    // s2 branch: Wc[hh] = Wg @ hW[hh]  (8 x 768 x 512 x 1024), then cbias
    tgemm_kernel<<<dim3(NHID/128, FIN_/128, NHEADS), 256, TGEMM_SMEM, s2>>>(
        nullptr, I_WGW, 0, NFEAT, nullptr, I_HWW, (long)NFEAT*NHID, NHID,
        p_Wc, (long)FIN_*NHID, 0, NHEADS, NHID, nullptr, -1, 0, NFEAT, 0);
    cbias_kernel<<<(NHEADS*NHID + 255)/256, 256, 0, s2>>>();
    cudaEventRecord(evJoin, s2);

    // main branch
    group_pool_kernel<<<BB, 256>>>();

    // join before h-GEMM
    cudaStreamWaitEvent(0, evJoin, 0);

    // h[hh] = x_off @ Wc[hh] + cb[hh]   (8 x 8192 x 512 x 768)
    tgemm_kernel<<<dim3(NHID/128, M/128, NHEADS), 256, TGEMM_SMEM>>>(
        p_xoff, -1, 0, FIN_, p_Wc, -1, (long)FIN_*NHID, NHID,
        p_h, (long)M*NHID, 0, NHEADS, NHID, p_cb, -1, NHID, FIN_, 0);

    {
        int nrows = NHEADS*M;
        dots_kernel<<<(nrows*32 + 255)/256, 256>>>(p_h, I_HAW, p_el, p_er, nrows, M, NHID);
    }
    {
        int Z = NHEADS*BB;
        att_kernel<<<(Z*NN*32 + 255)/256, 256>>>(p_el, p_er, I_HAB, 1, p_att, Z);
    }

    // x1 = elu(att @ h)   (512 z: 128 x 512 x 128)
    tgemm_kernel<<<dim3(NHID/128, NN/128, NHEADS*BB), 256, TGEMM_SMEM>>>(
        p_att, -1, (long)NN*NN, NN, p_h, -1, (long)NN*NHID, NHID,
        p_x1, (long)NN*NHEADS*NHID, NHID, BB, NHEADS*NHID, nullptr, -1, 0, NN, 1);

    // h2 = x1 @ oW + b   (8192 x 512 x 4096)
    tgemm_kernel<<<dim3(NCLASS/128, M/128, 1), 256, TGEMM_SMEM>>>(
        p_x1, -1, 0, NHEADS*NHID, nullptr, I_OWW, 0, NCLASS,
        p_h2, 0, 0, 1, NCLASS, nullptr, I_OWB, 0, NHEADS*NHID, 0);

    dots_kernel<<<(M*32 + 255)/256, 256>>>(p_h2, I_OAW, p_el2, p_er2, M, M, NCLASS);
    att_kernel<<<(BB*NN*32 + 255)/256, 256>>>(p_el2, p_er2, I_OAB, 0, p_att2, BB);

    // x2 = elu(att2 @ h2)   (64 z: 128 x 512 x 128)
    tgemm_kernel<<<dim3(NCLASS/128, NN/128, BB), 256, TGEMM_SMEM>>>(
        p_att2, -1, (long)NN*NN, NN, p_h2, -1, (long)NN*NCLASS, NCLASS,
        p_x2, (long)NN*NCLASS, 0, BB, NCLASS, nullptr, -1, 0, NN, 1);

    logits_kernel<<<(M*32 + 255)/256, 256>>>();
    score_fix_kernel<<<BB, 128>>>();
    expand_kernel<<<BB, 128>>>(out);
}

// round 12
// speedup vs baseline: 3.2514x; 1.0263x over previous
#include <cuda_runtime.h>
#include <math.h>
#include <stdint.h>

#define BB 64
#define NN 128
#define FIN_ 768
#define NFEAT 1024
#define NHID 512
#define NHEADS 8
#define NCLASS 512
#define ALPHA_ 0.2f
#define NEG_E_ (-9e15f)
#define NEG_S_ (-9e10f)

enum { I_X=0, I_TAG, I_OFFS, I_AMASK, I_ADJ, I_WGW, I_WGB, I_HWW, I_HWB,
       I_HAW, I_HAB, I_OWW, I_OWB, I_OAW, I_OAB, I_FINW, I_FINB };
__device__ const void* g_inp[17];
#define IN_F(i) ((const float*)g_inp[i])

__device__ float g_xoff[BB*NN*FIN_];
__device__ float g_h   [NHEADS*BB*NN*NHID];
__device__ float g_el  [NHEADS*BB*NN];
__device__ float g_er  [NHEADS*BB*NN];
__device__ float g_att [NHEADS*BB*NN*NN];
__device__ float g_x1  [BB*NN*NHEADS*NHID];
__device__ float g_h2  [BB*NN*NCLASS];
__device__ float g_el2 [BB*NN];
__device__ float g_er2 [BB*NN];
__device__ float g_att2[BB*NN*NN];
__device__ float g_x2  [BB*NN*NCLASS];
__device__ float g_logits[BB*NN];
__device__ int   g_ig  [BB*NN*2];
__device__ int   g_fix [BB*NN*2];
__device__ float g_Wc  [NHEADS*FIN_*NHID];
__device__ float g_cb  [NHEADS*NHID];

struct InPack { const void* p[17]; int s[17]; int n; };

__global__ void classify_kernel(InPack pk) {
    int lane = threadIdx.x;
    __shared__ int bin_idx[4]; __shared__ float bin_sum[4]; __shared__ int n_bin;
    if (lane == 0) n_bin = 0;
    __syncwarp();
    for (int i = 0; i < pk.n && i < 17; i++) {
        int sz = pk.s[i];
        const float* f = (const float*)pk.p[i];
        int target = -1;
        if      (sz == BB*NN*FIN_)         target = I_X;
        else if (sz == BB*NN*2)            target = I_OFFS;
        else if (sz == BB*NN*NN)           target = I_ADJ;
        else if (sz == FIN_*NFEAT)         target = I_WGW;
        else if (sz == NHEADS*NFEAT*NHID)  target = I_HWW;
        else if (sz == NHEADS*NHID*NCLASS) target = I_OWW;
        else if (sz == NHEADS*NHID)        target = I_HWB;
        else if (sz == NHEADS)             target = I_HAB;
        else if (sz == NFEAT) {
            bool nz = false;
            for (int k = lane; k < sz; k += 32) nz |= (f[k] != 0.f);
            target = __any_sync(0xffffffffu, nz) ? I_OAW : I_WGB;
        } else if (sz == NCLASS) {
            bool nz = false;
            for (int k = lane; k < sz; k += 32) nz |= (f[k] != 0.f);
            target = __any_sync(0xffffffffu, nz) ? I_FINW : I_OWB;
        } else if (sz == 1) {
            if (lane == 0) { g_inp[I_OAB] = pk.p[i]; g_inp[I_FINB] = pk.p[i]; }
        } else if (sz == BB*NN) {
            bool frac = false; float sum = 0.f;
            for (int k = lane; k < sz; k += 32) {
                float v = f[k]; frac |= (v != 0.f && v != 1.f); sum += v;
            }
            frac = __any_sync(0xffffffffu, frac);
#pragma unroll
            for (int o = 16; o; o >>= 1) sum += __shfl_xor_sync(0xffffffffu, sum, o);
            if (frac) target = I_HAW;
            else if (lane == 0) { bin_idx[n_bin] = i; bin_sum[n_bin] = sum; n_bin++; }
        }
        if (target >= 0 && lane == 0) g_inp[target] = pk.p[i];
        __syncwarp();
    }
    if (lane == 0) {
        if (n_bin >= 2) {
            int a = bin_idx[0], b = bin_idx[1];
            if (bin_sum[0] >= bin_sum[1]) { g_inp[I_AMASK] = pk.p[a]; g_inp[I_TAG] = pk.p[b]; }
            else                          { g_inp[I_AMASK] = pk.p[b]; g_inp[I_TAG] = pk.p[a]; }
        } else if (n_bin == 1) { g_inp[I_AMASK] = pk.p[bin_idx[0]]; g_inp[I_TAG] = pk.p[bin_idx[0]]; }
    }
}

__device__ __forceinline__ float warpSum(float v) {
#pragma unroll
    for (int o = 16; o; o >>= 1) v += __shfl_xor_sync(0xffffffffu, v, o);
    return v;
}
__device__ __forceinline__ float warpMax(float v) {
#pragma unroll
    for (int o = 16; o; o >>= 1) v = fmaxf(v, __shfl_xor_sync(0xffffffffu, v, o));
    return v;
}
__device__ __forceinline__ float blockSum128(float v) {
    __shared__ float s[4];
    float w = warpSum(v);
    if ((threadIdx.x & 31) == 0) s[threadIdx.x >> 5] = w;
    __syncthreads();
    float r = s[0] + s[1] + s[2] + s[3];
    __syncthreads();
    return r;
}
__device__ __forceinline__ float blockMax128(float v) {
    __shared__ float s[4];
    float w = warpMax(v);
    if ((threadIdx.x & 31) == 0) s[threadIdx.x >> 5] = w;
    __syncthreads();
    float r = fmaxf(fmaxf(s[0], s[1]), fmaxf(s[2], s[3]));
    __syncthreads();
    return r;
}

// ---- segment metadata -> g_ig (row ranges per group) ----
__global__ void meta_kernel() {
    const int* offs = (const int*)g_inp[I_OFFS];
    int b = blockIdx.x;
    if (threadIdx.x != 0) return;
    const int* ob = offs + b*NN*2;
    int fz = 0; bool found = false;
    for (int n = 0; n < NN; n++)
        if (ob[2*n] == 0 && ob[2*n+1] == 0) { fz = n; found = true; break; }
    if (!found) fz = 0;
    int cs = 0;
    int ends_local[NN];
    for (int n = 0; n < NN; n++) {
        int nxt = (n < NN-1) ? ob[2*(n+1)] : 0;
        int bi = (n < fz && ob[2*n+1] == nxt-1) ? 1 : 0;
        if (bi) { ends_local[cs] = n+1; cs++; }
    }
    int* igb = g_ig + b*NN*2;
    int prev_end = 0;
    for (int g = 0; g < NN; g++) {
        if (g < cs) { igb[2*g] = prev_end; igb[2*g+1] = ends_local[g]; prev_end = ends_local[g]; }
        else        { igb[2*g] = 0; igb[2*g+1] = 0; }
    }
}

// ---- pooling: grid (BB, FIN/128), 128 threads; thread owns one f-column ----
__global__ void pool_kernel() {
    const float* x = IN_F(I_X);
    int b = blockIdx.x;
    int f = blockIdx.y * 128 + threadIdx.x;
    __shared__ int s_ig[NN*2];
    for (int i = threadIdx.x; i < NN*2; i += 128) s_ig[i] = g_ig[b*NN*2 + i];
    __syncthreads();
    const float* xb = x + (long)b*NN*FIN_ + f;
    float* xo = g_xoff + (long)b*NN*FIN_ + f;
    for (int g = 0; g < NN; g++) {
        int s = s_ig[2*g], e = s_ig[2*g+1];
        float acc = 0.f;
        for (int n = s; n < e; n++) acc += xb[(long)n*FIN_];
        xo[(long)g*FIN_] = (e > s) ? acc / (float)(e - s) : 0.f;
    }
}

// coalesced cbias
__global__ void cbias_kernel() {
    const float* wgb = IN_F(I_WGB);
    const float* hw  = IN_F(I_HWW);
    const float* hwb = IN_F(I_HWB);
    int g = blockIdx.x * blockDim.x + threadIdx.x;
    if (g >= NHEADS*NHID) return;
    int hh = g / NHID, n = g % NHID;
    const float* base = hw + (long)hh*NFEAT*NHID + n;
    float a = 0.f;
#pragma unroll 4
    for (int k = 0; k < NFEAT; k++) a = fmaf(wgb[k], base[(long)k*NHID], a);
    g_cb[g] = a + hwb[g];
}

// ---- mma.sync tf32 GEMM, 4-stage cp.async pipeline ----
__device__ __forceinline__ void cp_async16(uint32_t dst, const void* src) {
    asm volatile("cp.async.cg.shared.global [%0], [%1], 16;\n" :: "r"(dst), "l"(src));
}
__device__ __forceinline__ void cp_commit() { asm volatile("cp.async.commit_group;\n"); }
template<int N> __device__ __forceinline__ void cp_wait() {
    asm volatile("cp.async.wait_group %0;\n" :: "n"(N));
}
__device__ __forceinline__ void ldsm_x4(uint32_t* r, uint32_t saddr) {
    asm volatile("ldmatrix.sync.aligned.m8n8.x4.shared.b16 {%0,%1,%2,%3}, [%4];\n"
                 : "=r"(r[0]), "=r"(r[1]), "=r"(r[2]), "=r"(r[3]) : "r"(saddr));
}
__device__ __forceinline__ void mma_tf32(float* d, const uint32_t* a, const uint32_t* b) {
    asm volatile(
        "mma.sync.aligned.m16n8k8.row.col.f32.tf32.tf32.f32 "
        "{%0,%1,%2,%3}, {%4,%5,%6,%7}, {%8,%9}, {%0,%1,%2,%3};\n"
        : "+f"(d[0]), "+f"(d[1]), "+f"(d[2]), "+f"(d[3])
        : "r"(a[0]), "r"(a[1]), "r"(a[2]), "r"(a[3]), "r"(b[0]), "r"(b[1]));
}

#define ASTR 20
#define BSTR 132
#define STAGES 4
#define A_U32 (128 * ASTR)
#define B_U32 (16 * BSTR)
#define STAGE_U32 (A_U32 + B_U32)
#define TGEMM_SMEM (STAGES * STAGE_U32 * 4)

extern __shared__ uint32_t sm_dyn[];

__global__ void __launch_bounds__(256, 2)
tgemm_kernel(const float* Ap, int Ai, long sAz, int lda,
             const float* Bp, int Bi, long sBz, int ldb,
             float* C, long sCz1, long sCz2, int zdiv, int ldc,
             const float* biasp, int biasi, int sBiasz,
             int K, int act) {
    const float* A  = (Ai    >= 0) ? IN_F(Ai)    : Ap;
    const float* Bm = (Bi    >= 0) ? IN_F(Bi)    : Bp;
    const float* bp = (biasi >= 0) ? IN_F(biasi) : biasp;

    int z = blockIdx.z;
    A  += (long)z * sAz;
    Bm += (long)z * sBz;
    C  += (long)(z % zdiv) * sCz1 + (long)(z / zdiv) * sCz2;
    if (bp) bp += (long)z * sBiasz;

    int tid  = threadIdx.x;
    int wid  = tid >> 5;
    int lane = tid & 31;
    int gr = lane >> 2, gc = lane & 3;
    int wm = (wid & 1) << 6;
    int wn = (wid >> 1) << 5;
    int row0 = blockIdx.y << 7, col0 = blockIdx.x << 7;

    uint32_t smem_base = (uint32_t)__cvta_generic_to_shared(sm_dyn);

    int ar = tid & 127;
    int ac0 = (tid >> 7) << 2;
    int br = tid >> 4;
    int bc0 = (tid & 15) << 2;
    const char* Abase = (const char*)(A + (long)(row0 + ar) * lda);
    const char* Bbase = (const char*)(Bm + (long)br * ldb + col0);

    int lrow = lane & 15;
    int lcol = (lane >> 4) << 2;

    float acc[4][4][4];
#pragma unroll
    for (int i = 0; i < 4; i++)
#pragma unroll
        for (int j = 0; j < 4; j++)
#pragma unroll
            for (int q = 0; q < 4; q++) acc[i][j][q] = 0.f;

    int nt = K >> 4;

    auto load_tile = [&](int t, int s) {
        uint32_t abuf = smem_base + (s * STAGE_U32) * 4;
        uint32_t bbuf = abuf + A_U32 * 4;
        const char* ag = Abase + (size_t)t * 64;
        cp_async16(abuf + (ar * ASTR + ac0) * 4,        ag + ac0 * 4);
        cp_async16(abuf + (ar * ASTR + ac0 + 8) * 4,    ag + (ac0 + 8) * 4);
        const char* bg = Bbase + (size_t)t * 16 * ldb * 4;
        cp_async16(bbuf + (br * BSTR + bc0) * 4,        bg + bc0 * 4);
        cp_async16(bbuf + (br * BSTR + bc0 + 64) * 4,   bg + (bc0 + 64) * 4);
    };

    load_tile(0, 0); cp_commit();
    if (nt > 1) load_tile(1, 1);
    cp_commit();
    if (nt > 2) load_tile(2, 2);
    cp_commit();

    for (int t = 0; t < nt; t++) {
        cp_wait<2>();
        __syncthreads();
        if (t + 3 < nt) load_tile(t + 3, (t + 3) % STAGES);
        cp_commit();

        int s = t % STAGES;
        uint32_t abuf = smem_base + (s * STAGE_U32) * 4;
        const uint32_t* bs = sm_dyn + s * STAGE_U32 + A_U32;

#pragma unroll
        for (int kk = 0; kk < 16; kk += 8) {
            uint32_t afr[4][4], bfr[4][2];
#pragma unroll
            for (int ti = 0; ti < 4; ti++) {
                uint32_t addr = abuf + (((wm + (ti << 4) + lrow) * ASTR) + kk + lcol) * 4;
                ldsm_x4(afr[ti], addr);
            }
#pragma unroll
            for (int tj = 0; tj < 4; tj++) {
                int cb = (kk + gc) * BSTR + wn + (tj << 3) + gr;
                bfr[tj][0] = bs[cb];
                bfr[tj][1] = bs[cb + 4 * BSTR];
            }
#pragma unroll
            for (int ti = 0; ti < 4; ti++)
#pragma unroll
                for (int tj = 0; tj < 4; tj++)
                    mma_tf32(acc[ti][tj], afr[ti], bfr[tj]);
        }
    }

#pragma unroll
    for (int ti = 0; ti < 4; ti++) {
        int rg0 = row0 + wm + (ti << 4) + gr;
#pragma unroll
        for (int tj = 0; tj < 4; tj++) {
            int cg = col0 + wn + (tj << 3) + (gc << 1);
            float d0 = acc[ti][tj][0], d1 = acc[ti][tj][1];
            float d2 = acc[ti][tj][2], d3 = acc[ti][tj][3];
            if (bp) {
                float b0 = bp[cg], b1 = bp[cg + 1];
                d0 += b0; d1 += b1; d2 += b0; d3 += b1;
            }
            if (act == 1) {
                d0 = d0 > 0.f ? d0 : expm1f(d0);
                d1 = d1 > 0.f ? d1 : expm1f(d1);
                d2 = d2 > 0.f ? d2 : expm1f(d2);
                d3 = d3 > 0.f ? d3 : expm1f(d3);
            }
            float2 v0 = {d0, d1}, v1 = {d2, d3};
            *(float2*)(C + (long)rg0 * ldc + cg) = v0;
            *(float2*)(C + (long)(rg0 + 8) * ldc + cg) = v1;
        }
    }
}

__global__ void dots_kernel(const float* __restrict__ rows, int wIdx,
                            float* __restrict__ el, float* __restrict__ er,
                            int nrows, int rows_per_head, int width) {
    const float* w = IN_F(wIdx);
    int gw = (blockIdx.x * blockDim.x + threadIdx.x) >> 5;
    if (gw >= nrows) return;
    int lane = threadIdx.x & 31;
    int hh = gw / rows_per_head;
    const float* row = rows + (long)gw*width;
    const float* wl = w + (long)hh*2*width;
    const float* wr = wl + width;
    float a = 0.f, c = 0.f;
    for (int k = lane; k < width; k += 32) {
        float v = row[k];
        a = fmaf(v, wl[k], a); c = fmaf(v, wr[k], c);
    }
    a = warpSum(a); c = warpSum(c);
    if (lane == 0) { el[gw] = a; er[gw] = c; }
}

__global__ void att_kernel(const float* __restrict__ el, const float* __restrict__ er,
                           int biasIdx, int bias_per_head, float* __restrict__ att, int Z) {
    int gw = (blockIdx.x * blockDim.x + threadIdx.x) >> 5;
    if (gw >= Z*NN) return;
    int lane = threadIdx.x & 31;
    int z = gw >> 7, i = gw & 127;
    int b = z % BB, hh = z / BB;
    float bb = IN_F(biasIdx)[bias_per_head ? hh : 0];
    float eli = el[z*NN+i];
    const float* adjrow = IN_F(I_ADJ) + ((long)b*NN+i)*NN;
    const float* err = er + z*NN;
    float v[4]; float mx = -INFINITY;
#pragma unroll
    for (int q = 0; q < 4; q++) {
        int j = lane + (q << 5);
        float e = eli + err[j] + bb;
        e = (e >= 0.f) ? e : ALPHA_*e;
        v[q] = (adjrow[j] > 0.f) ? e : NEG_E_;
        mx = fmaxf(mx, v[q]);
    }
    mx = warpMax(mx);
    float sum = 0.f;
#pragma unroll
    for (int q = 0; q < 4; q++) { v[q] = expf(v[q]-mx); sum += v[q]; }
    sum = warpSum(sum);
    float inv = 1.f / sum;
    float* arow = att + ((long)z*NN+i)*NN;
#pragma unroll
    for (int q = 0; q < 4; q++) arow[lane+(q<<5)] = v[q]*inv;
}

__global__ void logits_kernel() {
    const float* fin_w = IN_F(I_FINW);
    const float* fin_b = IN_F(I_FINB);
    int gw = (blockIdx.x * blockDim.x + threadIdx.x) >> 5;
    if (gw >= BB*NN) return;
    int lane = threadIdx.x & 31;
    const float* row = g_x2 + (long)gw*NCLASS;
    float a = 0.f;
    for (int k = lane; k < NCLASS; k += 32) a = fmaf(row[k], fin_w[k], a);
    a = warpSum(a);
    if (lane == 0) g_logits[gw] = a + fin_b[0];
}

__global__ void score_fix_kernel() {
    const float* tag   = IN_F(I_TAG);
    const float* amask = IN_F(I_AMASK);
    int b = blockIdx.x, j = threadIdx.x;
    float m = (tag[b*NN+j] > 0.f) ? amask[b*NN+j] : 0.f;
    float lg = g_logits[b*NN+j];
    float v1 = (m > 0.f) ? lg*m : NEG_S_;
    float mx1 = blockMax128(v1);
    float e1 = expf(v1-mx1);
    float d1 = blockSum128(e1);
    float s1 = e1/d1;
    float summary = blockSum128(m);
    float v2 = (m > 0.f) ? ((float)(NN-j))/summary*m : NEG_S_;
    float mx2 = blockMax128(v2);
    float e2 = expf(v2-mx2);
    float d2 = blockSum128(e2);
    float s2 = e2/d2;
    __shared__ float sc[NN];
    sc[j] = s1+s2;
    __syncthreads();
    float me = sc[j];
    int rank = 0;
    for (int k = 0; k < NN; k++) {
        float o = sc[k];
        rank += (o > me) || (o == me && k < j);
    }
    g_fix[(b*NN+j)*2+0] = g_ig[(b*NN+rank)*2+0];
    g_fix[(b*NN+j)*2+1] = g_ig[(b*NN+rank)*2+1];
}

__global__ void expand_kernel(float* __restrict__ out) {
    int b = blockIdx.x, l = threadIdx.x;
    __shared__ int f0[NN], f1[NN], csum[NN];
    __shared__ int fzs, total;
    f0[l] = g_fix[(b*NN+l)*2+0];
    f1[l] = g_fix[(b*NN+l)*2+1];
    __syncthreads();
    if (l == 0) {
        int fz = 0; bool found = false;
        for (int n = 0; n < NN; n++)
            if (f0[n] == 0 && f1[n] == 0) { fz = n; found = true; break; }
        if (!found) fz = 0;
        int cs = 0;
        for (int n = 0; n < NN; n++) {
            int len = (n < fz) ? (f1[n]-f0[n]) : 0;
            cs += len; csum[n] = cs;
        }
        fzs = fz; total = cs;
    }
    __syncthreads();
    int k = 0;
    for (int n = 0; n < NN; n++) k += (csum[n] <= l);
    if (k > NN-1) k = NN-1;
    int lenk = (k < fzs) ? (f1[k]-f0[k]) : 0;
    int excl = csum[k]-lenk;
    int val = f0[k] + (l-excl);
    out[b*NN+l] = (float)((l < total) ? val : l);
}

extern "C" void kernel_launch(void* const* d_in, const int* in_sizes, int n_in,
                              void* d_out, int) {
    float* out = (float*)d_out;
    InPack pk;
    int nn = n_in < 17 ? n_in : 17;
    for (int i = 0; i < 17; i++) {
        pk.p[i] = (i < nn) ? d_in[i] : nullptr;
        pk.s[i] = (i < nn) ? in_sizes[i] : 0;
    }
    pk.n = nn;

    float *p_xoff,*p_h,*p_el,*p_er,*p_att,*p_x1,*p_h2,*p_el2,*p_er2,*p_att2,*p_x2,*p_Wc,*p_cb;
    cudaGetSymbolAddress((void**)&p_xoff, g_xoff);
    cudaGetSymbolAddress((void**)&p_h,    g_h);
    cudaGetSymbolAddress((void**)&p_el,   g_el);
    cudaGetSymbolAddress((void**)&p_er,   g_er);
    cudaGetSymbolAddress((void**)&p_att,  g_att);
    cudaGetSymbolAddress((void**)&p_x1,   g_x1);
    cudaGetSymbolAddress((void**)&p_h2,   g_h2);
    cudaGetSymbolAddress((void**)&p_el2,  g_el2);
    cudaGetSymbolAddress((void**)&p_er2,  g_er2);
    cudaGetSymbolAddress((void**)&p_att2, g_att2);
    cudaGetSymbolAddress((void**)&p_x2,   g_x2);
    cudaGetSymbolAddress((void**)&p_Wc,   g_Wc);
    cudaGetSymbolAddress((void**)&p_cb,   g_cb);

    static bool init_done = false;
    static cudaStream_t s2;
    static cudaEvent_t evFork, evJoin;
    if (!init_done) {
        cudaFuncSetAttribute(tgemm_kernel, cudaFuncAttributeMaxDynamicSharedMemorySize, TGEMM_SMEM);
        cudaStreamCreateWithFlags(&s2, cudaStreamNonBlocking);
        cudaEventCreateWithFlags(&evFork, cudaEventDisableTiming);
        cudaEventCreateWithFlags(&evJoin, cudaEventDisableTiming);
        init_done = true;
    }

    const int M = BB*NN;

    classify_kernel<<<1, 32>>>(pk);

    // fork: Wc + cbias on s2 || meta + pool on main
    cudaEventRecord(evFork, 0);
    cudaStreamWaitEvent(s2, evFork, 0);

    tgemm_kernel<<<dim3(NHID/128, FIN_/128, NHEADS), 256, TGEMM_SMEM, s2>>>(
        nullptr, I_WGW, 0, NFEAT, nullptr, I_HWW, (long)NFEAT*NHID, NHID,
        p_Wc, (long)FIN_*NHID, 0, NHEADS, NHID, nullptr, -1, 0, NFEAT, 0);
    cbias_kernel<<<(NHEADS*NHID + 255)/256, 256, 0, s2>>>();
    cudaEventRecord(evJoin, s2);

    meta_kernel<<<BB, 32>>>();
    pool_kernel<<<dim3(BB, FIN_/128), 128>>>();

    cudaStreamWaitEvent(0, evJoin, 0);

    // h[hh] = x_off @ Wc[hh] + cb[hh]   (8 x 8192 x 512 x 768)
    tgemm_kernel<<<dim3(NHID/128, M/128, NHEADS), 256, TGEMM_SMEM>>>(
        p_xoff, -1, 0, FIN_, p_Wc, -1, (long)FIN_*NHID, NHID,
        p_h, (long)M*NHID, 0, NHEADS, NHID, p_cb, -1, NHID, FIN_, 0);

    {
        int nrows = NHEADS*M;
        dots_kernel<<<(nrows*32 + 255)/256, 256>>>(p_h, I_HAW, p_el, p_er, nrows, M, NHID);
    }
    {
        int Z = NHEADS*BB;
        att_kernel<<<(Z*NN*32 + 255)/256, 256>>>(p_el, p_er, I_HAB, 1, p_att, Z);
    }

    // x1 = elu(att @ h)
    tgemm_kernel<<<dim3(NHID/128, NN/128, NHEADS*BB), 256, TGEMM_SMEM>>>(
        p_att, -1, (long)NN*NN, NN, p_h, -1, (long)NN*NHID, NHID,
        p_x1, (long)NN*NHEADS*NHID, NHID, BB, NHEADS*NHID, nullptr, -1, 0, NN, 1);

    // h2 = x1 @ oW + b
    tgemm_kernel<<<dim3(NCLASS/128, M/128, 1), 256, TGEMM_SMEM>>>(
        p_x1, -1, 0, NHEADS*NHID, nullptr, I_OWW, 0, NCLASS,
        p_h2, 0, 0, 1, NCLASS, nullptr, I_OWB, 0, NHEADS*NHID, 0);

    dots_kernel<<<(M*32 + 255)/256, 256>>>(p_h2, I_OAW, p_el2, p_er2, M, M, NCLASS);
    att_kernel<<<(BB*NN*32 + 255)/256, 256>>>(p_el2, p_er2, I_OAB, 0, p_att2, BB);

    // x2 = elu(att2 @ h2)
    tgemm_kernel<<<dim3(NCLASS/128, NN/128, BB), 256, TGEMM_SMEM>>>(
        p_att2, -1, (long)NN*NN, NN, p_h2, -1, (long)NN*NCLASS, NCLASS,
        p_x2, (long)NN*NCLASS, 0, BB, NCLASS, nullptr, -1, 0, NN, 1);

    logits_kernel<<<(M*32 + 255)/256, 256>>>();
    score_fix_kernel<<<BB, 128>>>();
    expand_kernel<<<BB, 128>>>(out);
}

// round 13
// speedup vs baseline: 5.2525x; 1.6154x over previous
#include <cuda_runtime.h>
#include <cuda_bf16.h>
#include <math.h>
#include <stdint.h>

#define BB 64
#define NN 128
#define FIN_ 768
#define NFEAT 1024
#define NHID 512
#define NHEADS 8
#define NCLASS 512
#define ALPHA_ 0.2f
#define NEG_E_ (-9e15f)
#define NEG_S_ (-9e10f)

enum { I_X=0, I_TAG, I_OFFS, I_AMASK, I_ADJ, I_WGW, I_WGB, I_HWW, I_HWB,
       I_HAW, I_HAB, I_OWW, I_OWB, I_OAW, I_OAB, I_FINW, I_FINB };
__device__ const void* g_inp[17];
#define IN_F(i) ((const float*)g_inp[i])

typedef __nv_bfloat16 bf16;

__device__ bf16  g_xoffH[BB*NN*FIN_];
__device__ bf16  g_hH  [NHEADS*BB*NN*NHID];
__device__ float g_el  [NHEADS*BB*NN];
__device__ float g_er  [NHEADS*BB*NN];
__device__ bf16  g_attH[NHEADS*BB*NN*NN];
__device__ bf16  g_x1H [BB*NN*NHEADS*NHID];
__device__ bf16  g_h2H [BB*NN*NCLASS];
__device__ float g_el2 [BB*NN];
__device__ float g_er2 [BB*NN];
__device__ bf16  g_att2H[BB*NN*NN];
__device__ float g_x2  [BB*NN*NCLASS];
__device__ float g_logits[BB*NN];
__device__ int   g_ig  [BB*NN*2];
__device__ int   g_fix [BB*NN*2];
__device__ bf16  g_WcH [NHEADS*FIN_*NHID];
__device__ float g_cb  [NHEADS*NHID];
__device__ bf16  g_WgH [FIN_*NFEAT];
__device__ bf16  g_hWH [NHEADS*NFEAT*NHID];
__device__ bf16  g_oWH [NHEADS*NHID*NCLASS];

struct InPack { const void* p[17]; int s[17]; int n; };

__global__ void classify_kernel(InPack pk) {
    int lane = threadIdx.x;
    __shared__ int bin_idx[4]; __shared__ float bin_sum[4]; __shared__ int n_bin;
    if (lane == 0) n_bin = 0;
    __syncwarp();
    for (int i = 0; i < pk.n && i < 17; i++) {
        int sz = pk.s[i];
        const float* f = (const float*)pk.p[i];
        int target = -1;
        if      (sz == BB*NN*FIN_)         target = I_X;
        else if (sz == BB*NN*2)            target = I_OFFS;
        else if (sz == BB*NN*NN)           target = I_ADJ;
        else if (sz == FIN_*NFEAT)         target = I_WGW;
        else if (sz == NHEADS*NFEAT*NHID)  target = I_HWW;
        else if (sz == NHEADS*NHID*NCLASS) target = I_OWW;
        else if (sz == NHEADS*NHID)        target = I_HWB;
        else if (sz == NHEADS)             target = I_HAB;
        else if (sz == NFEAT) {
            bool nz = false;
            for (int k = lane; k < sz; k += 32) nz |= (f[k] != 0.f);
            target = __any_sync(0xffffffffu, nz) ? I_OAW : I_WGB;
        } else if (sz == NCLASS) {
            bool nz = false;
            for (int k = lane; k < sz; k += 32) nz |= (f[k] != 0.f);
            target = __any_sync(0xffffffffu, nz) ? I_FINW : I_OWB;
        } else if (sz == 1) {
            if (lane == 0) { g_inp[I_OAB] = pk.p[i]; g_inp[I_FINB] = pk.p[i]; }
        } else if (sz == BB*NN) {
            bool frac = false; float sum = 0.f;
            for (int k = lane; k < sz; k += 32) {
                float v = f[k]; frac |= (v != 0.f && v != 1.f); sum += v;
            }
            frac = __any_sync(0xffffffffu, frac);
#pragma unroll
            for (int o = 16; o; o >>= 1) sum += __shfl_xor_sync(0xffffffffu, sum, o);
            if (frac) target = I_HAW;
            else if (lane == 0) { bin_idx[n_bin] = i; bin_sum[n_bin] = sum; n_bin++; }
        }
        if (target >= 0 && lane == 0) g_inp[target] = pk.p[i];
        __syncwarp();
    }
    if (lane == 0) {
        if (n_bin >= 2) {
            int a = bin_idx[0], b = bin_idx[1];
            if (bin_sum[0] >= bin_sum[1]) { g_inp[I_AMASK] = pk.p[a]; g_inp[I_TAG] = pk.p[b]; }
            else                          { g_inp[I_AMASK] = pk.p[b]; g_inp[I_TAG] = pk.p[a]; }
        } else if (n_bin == 1) { g_inp[I_AMASK] = pk.p[bin_idx[0]]; g_inp[I_TAG] = pk.p[bin_idx[0]]; }
    }
}

__device__ __forceinline__ float warpSum(float v) {
#pragma unroll
    for (int o = 16; o; o >>= 1) v += __shfl_xor_sync(0xffffffffu, v, o);
    return v;
}
__device__ __forceinline__ float warpMax(float v) {
#pragma unroll
    for (int o = 16; o; o >>= 1) v = fmaxf(v, __shfl_xor_sync(0xffffffffu, v, o));
    return v;
}
__device__ __forceinline__ float blockSum128(float v) {
    __shared__ float s[4];
    float w = warpSum(v);
    if ((threadIdx.x & 31) == 0) s[threadIdx.x >> 5] = w;
    __syncthreads();
    float r = s[0] + s[1] + s[2] + s[3];
    __syncthreads();
    return r;
}
__device__ __forceinline__ float blockMax128(float v) {
    __shared__ float s[4];
    float w = warpMax(v);
    if ((threadIdx.x & 31) == 0) s[threadIdx.x >> 5] = w;
    __syncthreads();
    float r = fmaxf(fmaxf(s[0], s[1]), fmaxf(s[2], s[3]));
    __syncthreads();
    return r;
}

__global__ void meta_kernel() {
    const int* offs = (const int*)g_inp[I_OFFS];
    int b = blockIdx.x;
    if (threadIdx.x != 0) return;
    const int* ob = offs + b*NN*2;
    int fz = 0; bool found = false;
    for (int n = 0; n < NN; n++)
        if (ob[2*n] == 0 && ob[2*n+1] == 0) { fz = n; found = true; break; }
    if (!found) fz = 0;
    int cs = 0;
    int ends_local[NN];
    for (int n = 0; n < NN; n++) {
        int nxt = (n < NN-1) ? ob[2*(n+1)] : 0;
        int bi = (n < fz && ob[2*n+1] == nxt-1) ? 1 : 0;
        if (bi) { ends_local[cs] = n+1; cs++; }
    }
    int* igb = g_ig + b*NN*2;
    int prev_end = 0;
    for (int g = 0; g < NN; g++) {
        if (g < cs) { igb[2*g] = prev_end; igb[2*g+1] = ends_local[g]; prev_end = ends_local[g]; }
        else        { igb[2*g] = 0; igb[2*g+1] = 0; }
    }
}

__global__ void pool_kernel() {
    const float* x = IN_F(I_X);
    int b = blockIdx.x;
    int f = blockIdx.y * 128 + threadIdx.x;
    __shared__ int s_ig[NN*2];
    for (int i = threadIdx.x; i < NN*2; i += 128) s_ig[i] = g_ig[b*NN*2 + i];
    __syncthreads();
    const float* xb = x + (long)b*NN*FIN_ + f;
    bf16* xo = g_xoffH + (long)b*NN*FIN_ + f;
    for (int g = 0; g < NN; g++) {
        int s = s_ig[2*g], e = s_ig[2*g+1];
        float acc = 0.f;
        for (int n = s; n < e; n++) acc += xb[(long)n*FIN_];
        xo[(long)g*FIN_] = __float2bfloat16((e > s) ? acc / (float)(e - s) : 0.f);
    }
}

__global__ void f2h_kernel(int srcIdx, bf16* dst, int n) {
    const float* src = IN_F(srcIdx);
    for (int i = blockIdx.x * blockDim.x + threadIdx.x; i < n; i += gridDim.x * blockDim.x)
        dst[i] = __float2bfloat16(src[i]);
}

__global__ void cbias_kernel() {
    const float* wgb = IN_F(I_WGB);
    const float* hw  = IN_F(I_HWW);
    const float* hwb = IN_F(I_HWB);
    int g = blockIdx.x * blockDim.x + threadIdx.x;
    if (g >= NHEADS*NHID) return;
    int hh = g / NHID, n = g % NHID;
    const float* base = hw + (long)hh*NFEAT*NHID + n;
    float a = 0.f;
#pragma unroll 4
    for (int k = 0; k < NFEAT; k++) a = fmaf(wgb[k], base[(long)k*NHID], a);
    g_cb[g] = a + hwb[g];
}

// ---- bf16 mma GEMM: 128x128 tile, BK=16, 4-stage cp.async ----
__device__ __forceinline__ void cp_async16(uint32_t dst, const void* src) {
    asm volatile("cp.async.cg.shared.global [%0], [%1], 16;\n" :: "r"(dst), "l"(src));
}
__device__ __forceinline__ void cp_commit() { asm volatile("cp.async.commit_group;\n"); }
template<int N> __device__ __forceinline__ void cp_wait() {
    asm volatile("cp.async.wait_group %0;\n" :: "n"(N));
}
__device__ __forceinline__ void ldsm_x4(uint32_t* r, uint32_t a) {
    asm volatile("ldmatrix.sync.aligned.m8n8.x4.shared.b16 {%0,%1,%2,%3}, [%4];\n"
                 : "=r"(r[0]), "=r"(r[1]), "=r"(r[2]), "=r"(r[3]) : "r"(a));
}
__device__ __forceinline__ void ldsm_x2t(uint32_t* r, uint32_t a) {
    asm volatile("ldmatrix.sync.aligned.m8n8.x2.trans.shared.b16 {%0,%1}, [%2];\n"
                 : "=r"(r[0]), "=r"(r[1]) : "r"(a));
}
__device__ __forceinline__ void mma_bf16(float* d, const uint32_t* a, const uint32_t* b) {
    asm volatile(
        "mma.sync.aligned.m16n8k16.row.col.f32.bf16.bf16.f32 "
        "{%0,%1,%2,%3}, {%4,%5,%6,%7}, {%8,%9}, {%0,%1,%2,%3};\n"
        : "+f"(d[0]), "+f"(d[1]), "+f"(d[2]), "+f"(d[3])
        : "r"(a[0]), "r"(a[1]), "r"(a[2]), "r"(a[3]), "r"(b[0]), "r"(b[1]));
}

#define ASTRH 24      // bf16 elems per A row (16 data + 8 pad) = 48B
#define BSTRH 136     // bf16 elems per B k-row (128 data + 8 pad) = 272B
#define STAGES 4
#define A_BYTES (128 * ASTRH * 2)
#define B_BYTES (16 * BSTRH * 2)
#define STAGE_BYTES (A_BYTES + B_BYTES)
#define HGEMM_SMEM (STAGES * STAGE_BYTES)

extern __shared__ uint8_t sm_raw[];

__global__ void __launch_bounds__(256, 2)
hgemm_kernel(const bf16* A, long sAz, int lda,
             const bf16* Bm, long sBz, int ldb,
             void* Cv, long sCz1, long sCz2, int zdiv, int ldc,
             const float* biasp, int biasi, int sBiasz,
             int K, int act, int outBF) {
    const float* bp = (biasi >= 0) ? IN_F(biasi) : biasp;
    int z = blockIdx.z;
    A  += (long)z * sAz;
    Bm += (long)z * sBz;
    long coff = (long)(z % zdiv) * sCz1 + (long)(z / zdiv) * sCz2;
    if (bp) bp += (long)z * sBiasz;

    int tid = threadIdx.x, wid = tid >> 5, lane = tid & 31;
    int gr = lane >> 2, gc = lane & 3;
    int wm = (wid & 1) << 6;
    int wn = (wid >> 1) << 5;
    int row0 = blockIdx.y << 7, col0 = blockIdx.x << 7;

    uint32_t smem_base = (uint32_t)__cvta_generic_to_shared(sm_raw);

    int ar = tid & 127, ah = (tid >> 7);          // A: row, 16B-half
    int br = tid >> 4,  bc = (tid & 15);          // B: k-row, 16B-chunk
    const char* Abase = (const char*)(A + (long)(row0 + ar) * lda);
    const char* Bbase = (const char*)(Bm + (long)br * ldb + col0);

    float acc[4][4][4];
#pragma unroll
    for (int i = 0; i < 4; i++)
#pragma unroll
        for (int j = 0; j < 4; j++)
#pragma unroll
            for (int q = 0; q < 4; q++) acc[i][j][q] = 0.f;

    int nt = K >> 4;

    auto load_tile = [&](int t, int s) {
        uint32_t abuf = smem_base + s * STAGE_BYTES;
        uint32_t bbuf = abuf + A_BYTES;
        cp_async16(abuf + ar * 48 + ah * 16, Abase + (size_t)t * 32 + ah * 16);
        cp_async16(bbuf + br * 272 + bc * 16,
                   Bbase + ((size_t)t * 16) * (size_t)ldb * 2 + bc * 16);
    };

    load_tile(0, 0); cp_commit();
    if (nt > 1) load_tile(1, 1);
    cp_commit();
    if (nt > 2) load_tile(2, 2);
    cp_commit();

    int lrow = lane & 15;
    int lhalf = (lane >> 4) << 4;   // byte offset 0/16 for A k-half

    for (int t = 0; t < nt; t++) {
        cp_wait<2>();
        __syncthreads();
        if (t + 3 < nt) load_tile(t + 3, (t + 3) % STAGES);
        cp_commit();

        int s = t % STAGES;
        uint32_t abuf = smem_base + s * STAGE_BYTES;
        uint32_t bbuf = abuf + A_BYTES;

        uint32_t afr[4][4], bfr[4][2];
#pragma unroll
        for (int ti = 0; ti < 4; ti++)
            ldsm_x4(afr[ti], abuf + (wm + (ti << 4) + lrow) * 48 + lhalf);
#pragma unroll
        for (int tj = 0; tj < 4; tj++)
            ldsm_x2t(bfr[tj], bbuf + (lane & 15) * 272 + (wn + (tj << 3)) * 2);
#pragma unroll
        for (int ti = 0; ti < 4; ti++)
#pragma unroll
            for (int tj = 0; tj < 4; tj++)
                mma_bf16(acc[ti][tj], afr[ti], bfr[tj]);
    }

#pragma unroll
    for (int ti = 0; ti < 4; ti++) {
        int rg0 = row0 + wm + (ti << 4) + gr;
#pragma unroll
        for (int tj = 0; tj < 4; tj++) {
            int cg = col0 + wn + (tj << 3) + (gc << 1);
            float d0 = acc[ti][tj][0], d1 = acc[ti][tj][1];
            float d2 = acc[ti][tj][2], d3 = acc[ti][tj][3];
            if (bp) {
                float b0 = bp[cg], b1 = bp[cg + 1];
                d0 += b0; d1 += b1; d2 += b0; d3 += b1;
            }
            if (act == 1) {
                d0 = d0 > 0.f ? d0 : expm1f(d0);
                d1 = d1 > 0.f ? d1 : expm1f(d1);
                d2 = d2 > 0.f ? d2 : expm1f(d2);
                d3 = d3 > 0.f ? d3 : expm1f(d3);
            }
            if (outBF) {
                bf16* C = (bf16*)Cv + coff;
                __nv_bfloat162 p0 = {__float2bfloat16(d0), __float2bfloat16(d1)};
                __nv_bfloat162 p1 = {__float2bfloat16(d2), __float2bfloat16(d3)};
                *(__nv_bfloat162*)(C + (long)rg0 * ldc + cg) = p0;
                *(__nv_bfloat162*)(C + (long)(rg0 + 8) * ldc + cg) = p1;
            } else {
                float* C = (float*)Cv + coff;
                float2 v0 = {d0, d1}, v1 = {d2, d3};
                *(float2*)(C + (long)rg0 * ldc + cg) = v0;
                *(float2*)(C + (long)(rg0 + 8) * ldc + cg) = v1;
            }
        }
    }
}

__global__ void dots_kernel(const bf16* __restrict__ rows, int wIdx,
                            float* __restrict__ el, float* __restrict__ er,
                            int nrows, int rows_per_head, int width) {
    const float* w = IN_F(wIdx);
    int gw = (blockIdx.x * blockDim.x + threadIdx.x) >> 5;
    if (gw >= nrows) return;
    int lane = threadIdx.x & 31;
    int hh = gw / rows_per_head;
    const bf16* row = rows + (long)gw*width;
    const float* wl = w + (long)hh*2*width;
    const float* wr = wl + width;
    float a = 0.f, c = 0.f;
    for (int k = lane; k < width; k += 32) {
        float v = __bfloat162float(row[k]);
        a = fmaf(v, wl[k], a); c = fmaf(v, wr[k], c);
    }
    a = warpSum(a); c = warpSum(c);
    if (lane == 0) { el[gw] = a; er[gw] = c; }
}

__global__ void att_kernel(const float* __restrict__ el, const float* __restrict__ er,
                           int biasIdx, int bias_per_head, bf16* __restrict__ att, int Z) {
    int gw = (blockIdx.x * blockDim.x + threadIdx.x) >> 5;
    if (gw >= Z*NN) return;
    int lane = threadIdx.x & 31;
    int z = gw >> 7, i = gw & 127;
    int b = z % BB, hh = z / BB;
    float bb = IN_F(biasIdx)[bias_per_head ? hh : 0];
    float eli = el[z*NN+i];
    const float* adjrow = IN_F(I_ADJ) + ((long)b*NN+i)*NN;
    const float* err = er + z*NN;
    float v[4]; float mx = -INFINITY;
#pragma unroll
    for (int q = 0; q < 4; q++) {
        int j = lane + (q << 5);
        float e = eli + err[j] + bb;
        e = (e >= 0.f) ? e : ALPHA_*e;
        v[q] = (adjrow[j] > 0.f) ? e : NEG_E_;
        mx = fmaxf(mx, v[q]);
    }
    mx = warpMax(mx);
    float sum = 0.f;
#pragma unroll
    for (int q = 0; q < 4; q++) { v[q] = expf(v[q]-mx); sum += v[q]; }
    sum = warpSum(sum);
    float inv = 1.f / sum;
    bf16* arow = att + ((long)z*NN+i)*NN;
#pragma unroll
    for (int q = 0; q < 4; q++) arow[lane+(q<<5)] = __float2bfloat16(v[q]*inv);
}

__global__ void logits_kernel() {
    const float* fin_w = IN_F(I_FINW);
    const float* fin_b = IN_F(I_FINB);
    int gw = (blockIdx.x * blockDim.x + threadIdx.x) >> 5;
    if (gw >= BB*NN) return;
    int lane = threadIdx.x & 31;
    const float* row = g_x2 + (long)gw*NCLASS;
    float a = 0.f;
    for (int k = lane; k < NCLASS; k += 32) a = fmaf(row[k], fin_w[k], a);
    a = warpSum(a);
    if (lane == 0) g_logits[gw] = a + fin_b[0];
}

__global__ void score_fix_kernel() {
    const float* tag   = IN_F(I_TAG);
    const float* amask = IN_F(I_AMASK);
    int b = blockIdx.x, j = threadIdx.x;
    float m = (tag[b*NN+j] > 0.f) ? amask[b*NN+j] : 0.f;
    float lg = g_logits[b*NN+j];
    float v1 = (m > 0.f) ? lg*m : NEG_S_;
    float mx1 = blockMax128(v1);
    float e1 = expf(v1-mx1);
    float d1 = blockSum128(e1);
    float s1 = e1/d1;
    float summary = blockSum128(m);
    float v2 = (m > 0.f) ? ((float)(NN-j))/summary*m : NEG_S_;
    float mx2 = blockMax128(v2);
    float e2 = expf(v2-mx2);
    float d2 = blockSum128(e2);
    float s2 = e2/d2;
    __shared__ float sc[NN];
    sc[j] = s1+s2;
    __syncthreads();
    float me = sc[j];
    int rank = 0;
    for (int k = 0; k < NN; k++) {
        float o = sc[k];
        rank += (o > me) || (o == me && k < j);
    }
    g_fix[(b*NN+j)*2+0] = g_ig[(b*NN+rank)*2+0];
    g_fix[(b*NN+j)*2+1] = g_ig[(b*NN+rank)*2+1];
}

__global__ void expand_kernel(float* __restrict__ out) {
    int b = blockIdx.x, l = threadIdx.x;
    __shared__ int f0[NN], f1[NN], csum[NN];
    __shared__ int fzs, total;
    f0[l] = g_fix[(b*NN+l)*2+0];
    f1[l] = g_fix[(b*NN+l)*2+1];
    __syncthreads();
    if (l == 0) {
        int fz = 0; bool found = false;
        for (int n = 0; n < NN; n++)
            if (f0[n] == 0 && f1[n] == 0) { fz = n; found = true; break; }
        if (!found) fz = 0;
        int cs = 0;
        for (int n = 0; n < NN; n++) {
            int len = (n < fz) ? (f1[n]-f0[n]) : 0;
            cs += len; csum[n] = cs;
        }
        fzs = fz; total = cs;
    }
    __syncthreads();
    int k = 0;
    for (int n = 0; n < NN; n++) k += (csum[n] <= l);
    if (k > NN-1) k = NN-1;
    int lenk = (k < fzs) ? (f1[k]-f0[k]) : 0;
    int excl = csum[k]-lenk;
    int val = f0[k] + (l-excl);
    out[b*NN+l] = (float)((l < total) ? val : l);
}

extern "C" void kernel_launch(void* const* d_in, const int* in_sizes, int n_in,
                              void* d_out, int) {
    float* out = (float*)d_out;
    InPack pk;
    int nn = n_in < 17 ? n_in : 17;
    for (int i = 0; i < 17; i++) {
        pk.p[i] = (i < nn) ? d_in[i] : nullptr;
        pk.s[i] = (i < nn) ? in_sizes[i] : 0;
    }
    pk.n = nn;

    bf16 *p_xoffH,*p_hH,*p_attH,*p_x1H,*p_h2H,*p_att2H,*p_WcH,*p_WgH,*p_hWH,*p_oWH;
    float *p_el,*p_er,*p_el2,*p_er2,*p_x2,*p_cb;
    cudaGetSymbolAddress((void**)&p_xoffH, g_xoffH);
    cudaGetSymbolAddress((void**)&p_hH,    g_hH);
    cudaGetSymbolAddress((void**)&p_el,    g_el);
    cudaGetSymbolAddress((void**)&p_er,    g_er);
    cudaGetSymbolAddress((void**)&p_attH,  g_attH);
    cudaGetSymbolAddress((void**)&p_x1H,   g_x1H);
    cudaGetSymbolAddress((void**)&p_h2H,   g_h2H);
    cudaGetSymbolAddress((void**)&p_el2,   g_el2);
    cudaGetSymbolAddress((void**)&p_er2,   g_er2);
    cudaGetSymbolAddress((void**)&p_att2H, g_att2H);
    cudaGetSymbolAddress((void**)&p_x2,    g_x2);
    cudaGetSymbolAddress((void**)&p_WcH,   g_WcH);
    cudaGetSymbolAddress((void**)&p_cb,    g_cb);
    cudaGetSymbolAddress((void**)&p_WgH,   g_WgH);
    cudaGetSymbolAddress((void**)&p_hWH,   g_hWH);
    cudaGetSymbolAddress((void**)&p_oWH,   g_oWH);

    static bool init_done = false;
    static cudaStream_t s2;
    static cudaEvent_t evFork, evJoin;
    if (!init_done) {
        cudaFuncSetAttribute(hgemm_kernel, cudaFuncAttributeMaxDynamicSharedMemorySize, HGEMM_SMEM);
        cudaStreamCreateWithFlags(&s2, cudaStreamNonBlocking);
        cudaEventCreateWithFlags(&evFork, cudaEventDisableTiming);
        cudaEventCreateWithFlags(&evJoin, cudaEventDisableTiming);
        init_done = true;
    }

    const int M = BB*NN;

    classify_kernel<<<1, 32>>>(pk);

    cudaEventRecord(evFork, 0);
    cudaStreamWaitEvent(s2, evFork, 0);

    // s2: weight conversions, Wc GEMM (bf16), cbias
    f2h_kernel<<<296, 256, 0, s2>>>(I_WGW, p_WgH, FIN_*NFEAT);
    f2h_kernel<<<296, 256, 0, s2>>>(I_HWW, p_hWH, NHEADS*NFEAT*NHID);
    f2h_kernel<<<296, 256, 0, s2>>>(I_OWW, p_oWH, NHEADS*NHID*NCLASS);
    hgemm_kernel<<<dim3(NHID/128, FIN_/128, NHEADS), 256, HGEMM_SMEM, s2>>>(
        p_WgH, 0, NFEAT, p_hWH, (long)NFEAT*NHID, NHID,
        p_WcH, (long)FIN_*NHID, 0, NHEADS, NHID, nullptr, -1, 0, NFEAT, 0, 1);
    cbias_kernel<<<(NHEADS*NHID + 255)/256, 256, 0, s2>>>();
    cudaEventRecord(evJoin, s2);

    meta_kernel<<<BB, 32>>>();
    pool_kernel<<<dim3(BB, FIN_/128), 128>>>();

    cudaStreamWaitEvent(0, evJoin, 0);

    // h = xoff @ Wc + cb  (8 x 8192 x 512 x 768), bf16 out
    hgemm_kernel<<<dim3(NHID/128, M/128, NHEADS), 256, HGEMM_SMEM>>>(
        p_xoffH, 0, FIN_, p_WcH, (long)FIN_*NHID, NHID,
        p_hH, (long)M*NHID, 0, NHEADS, NHID, p_cb, -1, NHID, FIN_, 0, 1);

    {
        int nrows = NHEADS*M;
        dots_kernel<<<(nrows*32 + 255)/256, 256>>>(p_hH, I_HAW, p_el, p_er, nrows, M, NHID);
    }
    {
        int Z = NHEADS*BB;
        att_kernel<<<(Z*NN*32 + 255)/256, 256>>>(p_el, p_er, I_HAB, 1, p_attH, Z);
    }

    // x1 = elu(att @ h)  (512 z), bf16 out scattered (B,N,H*O)
    hgemm_kernel<<<dim3(NHID/128, NN/128, NHEADS*BB), 256, HGEMM_SMEM>>>(
        p_attH, (long)NN*NN, NN, p_hH, (long)NN*NHID, NHID,
        p_x1H, (long)NN*NHEADS*NHID, NHID, BB, NHEADS*NHID, nullptr, -1, 0, NN, 1, 1);

    // h2 = x1 @ oW + b  (8192 x 512 x 4096), bf16 out
    hgemm_kernel<<<dim3(NCLASS/128, M/128, 1), 256, HGEMM_SMEM>>>(
        p_x1H, 0, NHEADS*NHID, p_oWH, 0, NCLASS,
        p_h2H, 0, 0, 1, NCLASS, nullptr, I_OWB, 0, NHEADS*NHID, 0, 1);

    dots_kernel<<<(M*32 + 255)/256, 256>>>(p_h2H, I_OAW, p_el2, p_er2, M, M, NCLASS);
    att_kernel<<<(BB*NN*32 + 255)/256, 256>>>(p_el2, p_er2, I_OAB, 0, p_att2H, BB);

    // x2 = elu(att2 @ h2)  (64 z), f32 out
    hgemm_kernel<<<dim3(NCLASS/128, NN/128, BB), 256, HGEMM_SMEM>>>(
        p_att2H, (long)NN*NN, NN, p_h2H, (long)NN*NCLASS, NCLASS,
        p_x2, (long)NN*NCLASS, 0, BB, NCLASS, nullptr, -1, 0, NN, 1, 0);

    logits_kernel<<<(M*32 + 255)/256, 256>>>();
    score_fix_kernel<<<BB, 128>>>();
    expand_kernel<<<BB, 128>>>(out);
}